// round 1
// baseline (speedup 1.0000x reference)
#include <cuda_runtime.h>

// Problem constants
#define B_  2
#define T_  2048
#define C_  1024
#define H_  16
#define HS_ 64
#define M_  (B_*T_)      // 4096
#define NQKV_ (3*C_)     // 3072

// Scratch (allocation-free rule: __device__ globals)
__device__ float g_q[B_*H_*T_*HS_];      // [b,h,t,d]
__device__ float g_k[B_*H_*T_*HS_];
__device__ float g_v[B_*H_*T_*HS_];
__device__ float g_attn[M_*C_];          // [b*T+t, h*64+d]

// ---------------------------------------------------------------------------
// SGEMM 128x128x8, 256 threads, 8x8 per-thread register tile.
// A: [M,K] row-major, Bm: [K,N] row-major.
// ---------------------------------------------------------------------------
__global__ __launch_bounds__(256) void qkv_gemm(const float* __restrict__ A,
                                                const float* __restrict__ Bm) {
    const int K = C_;
    const int N = NQKV_;
    __shared__ float As[8][128];
    __shared__ float Bs[8][128];

    int tid = threadIdx.x;
    int bm = blockIdx.y * 128, bn = blockIdx.x * 128;
    int a_row = tid >> 1, a_col = (tid & 1) << 2;
    int b_row = tid >> 5, b_col = (tid & 31) << 2;
    int tx = tid & 15, ty = tid >> 4;

    float acc[8][8];
#pragma unroll
    for (int i = 0; i < 8; i++)
#pragma unroll
        for (int j = 0; j < 8; j++) acc[i][j] = 0.0f;

    const float* Aptr = A + (size_t)(bm + a_row) * K + a_col;
    const float* Bptr = Bm + (size_t)b_row * N + bn + b_col;

    for (int k0 = 0; k0 < K; k0 += 8) {
        float4 av = *(const float4*)(Aptr + k0);
        As[a_col + 0][a_row] = av.x;
        As[a_col + 1][a_row] = av.y;
        As[a_col + 2][a_row] = av.z;
        As[a_col + 3][a_row] = av.w;
        float4 bv = *(const float4*)(Bptr + (size_t)k0 * N);
        *(float4*)&Bs[b_row][b_col] = bv;
        __syncthreads();
#pragma unroll
        for (int kk = 0; kk < 8; kk++) {
            float a[8], b[8];
            *(float4*)&a[0] = *(const float4*)&As[kk][ty * 8];
            *(float4*)&a[4] = *(const float4*)&As[kk][ty * 8 + 4];
            *(float4*)&b[0] = *(const float4*)&Bs[kk][tx * 8];
            *(float4*)&b[4] = *(const float4*)&Bs[kk][tx * 8 + 4];
#pragma unroll
            for (int i = 0; i < 8; i++)
#pragma unroll
                for (int j = 0; j < 8; j++)
                    acc[i][j] = fmaf(a[i], b[j], acc[i][j]);
        }
        __syncthreads();
    }

    // Scatter into q/k/v with [b,h,t,d] layout
#pragma unroll
    for (int i = 0; i < 8; i++) {
        int m = bm + ty * 8 + i;
        int bb = m >> 11;           // / T_
        int t  = m & (T_ - 1);
#pragma unroll
        for (int j = 0; j < 8; j++) {
            int n = bn + tx * 8 + j;
            int which = n >> 10;    // 0=q,1=k,2=v (block tile never straddles: 1024%128==0)
            int c = n & (C_ - 1);
            int h = c >> 6, d = c & 63;
            float* dst = (which == 0) ? g_q : (which == 1 ? g_k : g_v);
            dst[(((bb << 4) + h) * T_ + t) * HS_ + d] = acc[i][j];
        }
    }
}

__global__ __launch_bounds__(256) void proj_gemm(const float* __restrict__ Bm,
                                                 const float* __restrict__ bias,
                                                 float* __restrict__ out) {
    const int K = C_;
    const int N = C_;
    __shared__ float As[8][128];
    __shared__ float Bs[8][128];

    int tid = threadIdx.x;
    int bm = blockIdx.y * 128, bn = blockIdx.x * 128;
    int a_row = tid >> 1, a_col = (tid & 1) << 2;
    int b_row = tid >> 5, b_col = (tid & 31) << 2;
    int tx = tid & 15, ty = tid >> 4;

    float acc[8][8];
#pragma unroll
    for (int i = 0; i < 8; i++)
#pragma unroll
        for (int j = 0; j < 8; j++) acc[i][j] = 0.0f;

    const float* Aptr = g_attn + (size_t)(bm + a_row) * K + a_col;
    const float* Bptr = Bm + (size_t)b_row * N + bn + b_col;

    for (int k0 = 0; k0 < K; k0 += 8) {
        float4 av = *(const float4*)(Aptr + k0);
        As[a_col + 0][a_row] = av.x;
        As[a_col + 1][a_row] = av.y;
        As[a_col + 2][a_row] = av.z;
        As[a_col + 3][a_row] = av.w;
        float4 bv = *(const float4*)(Bptr + (size_t)k0 * N);
        *(float4*)&Bs[b_row][b_col] = bv;
        __syncthreads();
#pragma unroll
        for (int kk = 0; kk < 8; kk++) {
            float a[8], b[8];
            *(float4*)&a[0] = *(const float4*)&As[kk][ty * 8];
            *(float4*)&a[4] = *(const float4*)&As[kk][ty * 8 + 4];
            *(float4*)&b[0] = *(const float4*)&Bs[kk][tx * 8];
            *(float4*)&b[4] = *(const float4*)&Bs[kk][tx * 8 + 4];
#pragma unroll
            for (int i = 0; i < 8; i++)
#pragma unroll
                for (int j = 0; j < 8; j++)
                    acc[i][j] = fmaf(a[i], b[j], acc[i][j]);
        }
        __syncthreads();
    }

#pragma unroll
    for (int i = 0; i < 8; i++) {
        int m = bm + ty * 8 + i;
#pragma unroll
        for (int j = 0; j < 8; j++) {
            int n = bn + tx * 8 + j;
            out[(size_t)m * N + n] = acc[i][j] + bias[n];
        }
    }
}

// ---------------------------------------------------------------------------
// Flash attention: 64x64 tiles, causal, 256 threads (16x16), online softmax.
// Each thread: 4 query rows (ty*4..) x 4 key cols / output dims (tx*4..).
// ---------------------------------------------------------------------------
#define FA_SMEM (4 * 64 * 65 * 4)

__global__ __launch_bounds__(256) void flash_attn_kernel() {
    extern __shared__ float sm[];
    float (*Qs)[65] = (float(*)[65])sm;
    float (*Ks)[65] = (float(*)[65])(sm + 64 * 65);
    float (*Vs)[65] = (float(*)[65])(sm + 2 * 64 * 65);
    float (*Ps)[65] = (float(*)[65])(sm + 3 * 64 * 65);

    int tid = threadIdx.x;
    int tx = tid & 15, ty = tid >> 4;
    int qt = blockIdx.x;    // query tile 0..31
    int bh = blockIdx.y;    // b*16+h, 0..31
    int row0 = ty * 4, col0 = tx * 4;

    const float* Qp = g_q + (size_t)bh * T_ * HS_ + qt * 64 * HS_;
    const float* Kp = g_k + (size_t)bh * T_ * HS_;
    const float* Vp = g_v + (size_t)bh * T_ * HS_;

    // Load Q tile (64x64)
    for (int i = tid; i < 64 * 16; i += 256) {
        int r = i >> 4, c4 = (i & 15) << 2;
        float4 v4 = *(const float4*)&Qp[(r << 6) + c4];
        Qs[r][c4 + 0] = v4.x; Qs[r][c4 + 1] = v4.y;
        Qs[r][c4 + 2] = v4.z; Qs[r][c4 + 3] = v4.w;
    }

    float m_i[4], l_i[4], acc[4][4];
#pragma unroll
    for (int i = 0; i < 4; i++) {
        m_i[i] = -1e30f;
        l_i[i] = 0.0f;
#pragma unroll
        for (int j = 0; j < 4; j++) acc[i][j] = 0.0f;
    }

    const float scale = 0.125f;  // hs^-0.5 = 1/8

    for (int kt = 0; kt <= qt; kt++) {
        __syncthreads();  // prev iter's P@V done; Q tile visible on 1st iter
        const float* Kt = Kp + kt * 64 * HS_;
        const float* Vt = Vp + kt * 64 * HS_;
        for (int i = tid; i < 64 * 16; i += 256) {
            int r = i >> 4, c4 = (i & 15) << 2;
            float4 k4 = *(const float4*)&Kt[(r << 6) + c4];
            Ks[r][c4 + 0] = k4.x; Ks[r][c4 + 1] = k4.y;
            Ks[r][c4 + 2] = k4.z; Ks[r][c4 + 3] = k4.w;
            float4 v4 = *(const float4*)&Vt[(r << 6) + c4];
            Vs[r][c4 + 0] = v4.x; Vs[r][c4 + 1] = v4.y;
            Vs[r][c4 + 2] = v4.z; Vs[r][c4 + 3] = v4.w;
        }
        __syncthreads();

        // S = Q K^T
        float s[4][4];
#pragma unroll
        for (int i = 0; i < 4; i++)
#pragma unroll
            for (int j = 0; j < 4; j++) s[i][j] = 0.0f;

#pragma unroll 8
        for (int d = 0; d < 64; d++) {
            float qv[4], kv[4];
#pragma unroll
            for (int i = 0; i < 4; i++) qv[i] = Qs[row0 + i][d];
#pragma unroll
            for (int j = 0; j < 4; j++) kv[j] = Ks[col0 + j][d];
#pragma unroll
            for (int i = 0; i < 4; i++)
#pragma unroll
                for (int j = 0; j < 4; j++)
                    s[i][j] = fmaf(qv[i], kv[j], s[i][j]);
        }

        // scale + causal mask (only diagonal tile partially masked)
#pragma unroll
        for (int i = 0; i < 4; i++)
#pragma unroll
            for (int j = 0; j < 4; j++) s[i][j] *= scale;
        if (kt == qt) {
#pragma unroll
            for (int i = 0; i < 4; i++)
#pragma unroll
                for (int j = 0; j < 4; j++)
                    if (col0 + j > row0 + i) s[i][j] = -1e30f;
        }

        // online softmax per row (reduce over 16 tx lanes)
#pragma unroll
        for (int i = 0; i < 4; i++) {
            float mx = fmaxf(fmaxf(s[i][0], s[i][1]), fmaxf(s[i][2], s[i][3]));
#pragma unroll
            for (int off = 8; off >= 1; off >>= 1)
                mx = fmaxf(mx, __shfl_xor_sync(0xffffffffu, mx, off));
            float newm = fmaxf(m_i[i], mx);
            float alpha = __expf(m_i[i] - newm);   // first iter: exp(-huge)=0
            float rs = 0.0f;
#pragma unroll
            for (int j = 0; j < 4; j++) {
                float p = __expf(s[i][j] - newm);
                Ps[row0 + i][col0 + j] = p;
                rs += p;
            }
#pragma unroll
            for (int off = 8; off >= 1; off >>= 1)
                rs += __shfl_xor_sync(0xffffffffu, rs, off);
            l_i[i] = l_i[i] * alpha + rs;
            m_i[i] = newm;
#pragma unroll
            for (int j = 0; j < 4; j++) acc[i][j] *= alpha;
        }
        __syncthreads();

        // acc += P @ V
#pragma unroll 8
        for (int kk = 0; kk < 64; kk++) {
            float pv[4], vv[4];
#pragma unroll
            for (int i = 0; i < 4; i++) pv[i] = Ps[row0 + i][kk];
#pragma unroll
            for (int j = 0; j < 4; j++) vv[j] = Vs[kk][col0 + j];
#pragma unroll
            for (int i = 0; i < 4; i++)
#pragma unroll
                for (int j = 0; j < 4; j++)
                    acc[i][j] = fmaf(pv[i], vv[j], acc[i][j]);
        }
    }

    // write attn output in [b*T+t, h*64+d] layout for the projection GEMM
    int b = bh >> 4, h = bh & 15;
#pragma unroll
    for (int i = 0; i < 4; i++) {
        int t = qt * 64 + row0 + i;
        float inv_l = 1.0f / l_i[i];
        size_t base = (size_t)(b * T_ + t) * C_ + h * 64 + col0;
#pragma unroll
        for (int j = 0; j < 4; j++)
            g_attn[base + j] = acc[i][j] * inv_l;
    }
}

// ---------------------------------------------------------------------------
extern "C" void kernel_launch(void* const* d_in, const int* in_sizes, int n_in,
                              void* d_out, int out_size) {
    const float* x    = (const float*)d_in[0];   // [B,T,C]
    const float* Wqkv = (const float*)d_in[1];   // [C,3C]
    const float* Wout = (const float*)d_in[2];   // [C,C]
    const float* bout = (const float*)d_in[3];   // [C]
    float* out = (float*)d_out;                  // [B,T,C]

    qkv_gemm<<<dim3(NQKV_ / 128, M_ / 128), 256>>>(x, Wqkv);

    cudaFuncSetAttribute(flash_attn_kernel,
                         cudaFuncAttributeMaxDynamicSharedMemorySize, FA_SMEM);
    flash_attn_kernel<<<dim3(T_ / 64, B_ * H_), 256, FA_SMEM>>>();

    proj_gemm<<<dim3(C_ / 128, M_ / 128), 256>>>(Wout, bout, out);
}

// round 3
// speedup vs baseline: 1.7016x; 1.7016x over previous
#include <cuda_runtime.h>
#include <cuda_bf16.h>
#include <cstdint>

#define B_  2
#define T_  2048
#define C_  1024
#define H_  16
#define M_  (B_*T_)      // 4096
#define NQKV_ (3*C_)     // 3072

// ---------------- device scratch (no allocation allowed) -------------------
__device__ __nv_bfloat16 g_xhi[M_*C_],     g_xlo[M_*C_];
__device__ __nv_bfloat16 g_wqkvThi[NQKV_*C_], g_wqkvTlo[NQKV_*C_];
__device__ __nv_bfloat16 g_woutThi[C_*C_], g_woutTlo[C_*C_];
__device__ __nv_bfloat16 g_attnhi[M_*C_],  g_attnlo[M_*C_];
__device__ float g_qkv[M_*NQKV_];          // [b*T+t][3C] fp32

// ---------------- helpers ----------------------------------------------------
__device__ __forceinline__ uint32_t smem_u32_of(const void* p) {
    uint32_t a;
    asm("{ .reg .u64 t; cvta.to.shared.u64 t, %1; cvt.u32.u64 %0, t; }" : "=r"(a) : "l"(p));
    return a;
}

__device__ __forceinline__ void ldsm4(uint32_t* r, uint32_t addr) {
    asm volatile("ldmatrix.sync.aligned.m8n8.x4.shared.b16 {%0,%1,%2,%3}, [%4];"
                 : "=r"(r[0]), "=r"(r[1]), "=r"(r[2]), "=r"(r[3]) : "r"(addr));
}

__device__ __forceinline__ void mma16816(float* c, const uint32_t* a,
                                         uint32_t b0, uint32_t b1) {
    asm volatile(
        "mma.sync.aligned.m16n8k16.row.col.f32.bf16.bf16.f32 "
        "{%0,%1,%2,%3}, {%4,%5,%6,%7}, {%8,%9}, {%0,%1,%2,%3};"
        : "+f"(c[0]), "+f"(c[1]), "+f"(c[2]), "+f"(c[3])
        : "r"(a[0]), "r"(a[1]), "r"(a[2]), "r"(a[3]), "r"(b0), "r"(b1));
}

// ---------------------------------------------------------------------------
// bf16 hi/lo compensated HMMA GEMM.
// CTA tile 128(M) x 128(N), K-chunk 64 bf16, 8 warps (4x2), warp tile 32x64.
// A: [M][1024] bf16 hi/lo (K-major). B: [N][1024] bf16 hi/lo (K-major).
// mode 0: A=x, B=WqkvT -> g_qkv (no bias).  mode 1: A=attn, B=WoutT -> out (+bias)
// ---------------------------------------------------------------------------
#define SA_HI 0
#define SA_LO 16384
#define SB_HI 32768
#define SB_LO 49152
#define GEMM_SMEM 65536

__global__ __launch_bounds__(256) void hmma_gemm(int mode, float* __restrict__ out_arg,
                                                 const float* __restrict__ bias, int N) {
    extern __shared__ char smem[];
    const uint32_t sbase = smem_u32_of(smem);
    const int tid = threadIdx.x, wid = tid >> 5, lane = tid & 31;
    const int bm = blockIdx.y * 128, bn = blockIdx.x * 128;
    const int wm = wid & 3, wn = wid >> 2;

    const __nv_bfloat16* Ahi = (mode == 0) ? g_xhi : g_attnhi;
    const __nv_bfloat16* Alo = (mode == 0) ? g_xlo : g_attnlo;
    const __nv_bfloat16* Bhi = (mode == 0) ? g_wqkvThi : g_woutThi;
    const __nv_bfloat16* Blo = (mode == 0) ? g_wqkvTlo : g_woutTlo;
    float* out = (mode == 0) ? g_qkv : out_arg;

    float acc[2][8][4];
#pragma unroll
    for (int i = 0; i < 2; i++)
#pragma unroll
        for (int j = 0; j < 8; j++)
#pragma unroll
            for (int k = 0; k < 4; k++) acc[i][j][k] = 0.0f;

    const int lrow = lane & 15;
    const int lkb  = (lane >> 4) << 4;

    for (int ch = 0; ch < 16; ch++) {
        const int k0 = ch * 64;
        // stage A(128x64) and B(128x64), hi+lo, SW128 swizzled (128B rows)
        for (int i = tid; i < 1024; i += 256) {
            int r = i >> 3, g = i & 7;
            uint32_t off = (uint32_t)(r * 128 + g * 16);
            uint32_t sw = off ^ ((off >> 3) & 0x70);
            size_t ga = (size_t)(bm + r) * C_ + k0 + g * 8;
            *(uint4*)(smem + SA_HI + sw) = *(const uint4*)(Ahi + ga);
            *(uint4*)(smem + SA_LO + sw) = *(const uint4*)(Alo + ga);
            size_t gb = (size_t)(bn + r) * C_ + k0 + g * 8;
            *(uint4*)(smem + SB_HI + sw) = *(const uint4*)(Bhi + gb);
            *(uint4*)(smem + SB_LO + sw) = *(const uint4*)(Blo + gb);
        }
        __syncthreads();

#pragma unroll
        for (int ks = 0; ks < 4; ks++) {
            uint32_t ah[2][4], al[2][4];
#pragma unroll
            for (int mf = 0; mf < 2; mf++) {
                uint32_t off = (uint32_t)((wm * 32 + mf * 16 + lrow) * 128 + ks * 32 + lkb);
                uint32_t sw = off ^ ((off >> 3) & 0x70);
                ldsm4(ah[mf], sbase + SA_HI + sw);
                ldsm4(al[mf], sbase + SA_LO + sw);
            }
#pragma unroll
            for (int np = 0; np < 4; np++) {
                uint32_t off = (uint32_t)((wn * 64 + np * 16 + lrow) * 128 + ks * 32 + lkb);
                uint32_t sw = off ^ ((off >> 3) & 0x70);
                uint32_t bh[4], bl[4];
                ldsm4(bh, sbase + SB_HI + sw);
                ldsm4(bl, sbase + SB_LO + sw);
#pragma unroll
                for (int mf = 0; mf < 2; mf++) {
                    mma16816(acc[mf][np * 2],     ah[mf], bh[0], bh[2]);
                    mma16816(acc[mf][np * 2 + 1], ah[mf], bh[1], bh[3]);
                    mma16816(acc[mf][np * 2],     ah[mf], bl[0], bl[2]);
                    mma16816(acc[mf][np * 2 + 1], ah[mf], bl[1], bl[3]);
                    mma16816(acc[mf][np * 2],     al[mf], bh[0], bh[2]);
                    mma16816(acc[mf][np * 2 + 1], al[mf], bh[1], bh[3]);
                }
            }
        }
        __syncthreads();
    }

    // epilogue: c0/c1 at (row, col..col+1), c2/c3 at (row+8, ...)
    const int r0 = bm + wm * 32 + (lane >> 2);
    const int c0 = bn + wn * 64 + (lane & 3) * 2;
#pragma unroll
    for (int mf = 0; mf < 2; mf++) {
#pragma unroll
        for (int nf = 0; nf < 8; nf++) {
            int row = r0 + mf * 16;
            int col = c0 + nf * 8;
            float b0 = bias ? bias[col] : 0.0f;
            float b1 = bias ? bias[col + 1] : 0.0f;
            float2 v0 = make_float2(acc[mf][nf][0] + b0, acc[mf][nf][1] + b1);
            float2 v1 = make_float2(acc[mf][nf][2] + b0, acc[mf][nf][3] + b1);
            *(float2*)&out[(size_t)row * N + col] = v0;
            *(float2*)&out[(size_t)(row + 8) * N + col] = v1;
        }
    }
}

// ---------------------------------------------------------------------------
__global__ void conv_split_x(const float* __restrict__ src) {
    int i = blockIdx.x * 256 + threadIdx.x;
    if (i < M_ * C_) {
        float v = src[i];
        __nv_bfloat16 h = __float2bfloat16(v);
        g_xhi[i] = h;
        g_xlo[i] = __float2bfloat16(v - __bfloat162float(h));
    }
}

__global__ void conv_split_t(const float* __restrict__ src, int mode, int K, int N) {
    __shared__ float s[32][33];
    __nv_bfloat16* hi = (mode == 0) ? g_wqkvThi : g_woutThi;
    __nv_bfloat16* lo = (mode == 0) ? g_wqkvTlo : g_woutTlo;
    int n0 = blockIdx.x * 32, k0 = blockIdx.y * 32;
    int tx = threadIdx.x, ty = threadIdx.y;
#pragma unroll
    for (int yy = 0; yy < 32; yy += 8)
        s[ty + yy][tx] = src[(size_t)(k0 + ty + yy) * N + n0 + tx];
    __syncthreads();
#pragma unroll
    for (int yy = 0; yy < 32; yy += 8) {
        float v = s[tx][ty + yy];
        __nv_bfloat16 h = __float2bfloat16(v);
        size_t o = (size_t)(n0 + ty + yy) * K + k0 + tx;
        hi[o] = h;
        lo[o] = __float2bfloat16(v - __bfloat162float(h));
    }
}

// ---------------------------------------------------------------------------
// Flash attention (fp32 CUDA cores) — reads g_qkv [m][3C], writes attn hi/lo
// ---------------------------------------------------------------------------
#define FA_SMEM (4 * 64 * 65 * 4)

__global__ __launch_bounds__(256) void flash_attn_kernel() {
    extern __shared__ float sm[];
    float (*Qs)[65] = (float(*)[65])sm;
    float (*Ks)[65] = (float(*)[65])(sm + 64 * 65);
    float (*Vs)[65] = (float(*)[65])(sm + 2 * 64 * 65);
    float (*Ps)[65] = (float(*)[65])(sm + 3 * 64 * 65);

    int tid = threadIdx.x;
    int tx = tid & 15, ty = tid >> 4;
    int qt = blockIdx.x;
    int bh = blockIdx.y;
    int b = bh >> 4, h = bh & 15;
    int row0 = ty * 4, col0 = tx * 4;

    const float* Qp = g_qkv + (size_t)(b * T_ + qt * 64) * NQKV_ + h * 64;
    const float* Kbase = g_qkv + (size_t)b * T_ * NQKV_ + C_ + h * 64;
    const float* Vbase = g_qkv + (size_t)b * T_ * NQKV_ + 2 * C_ + h * 64;

    for (int i = tid; i < 64 * 16; i += 256) {
        int r = i >> 4, c4 = (i & 15) << 2;
        float4 v4 = *(const float4*)&Qp[(size_t)r * NQKV_ + c4];
        Qs[r][c4 + 0] = v4.x; Qs[r][c4 + 1] = v4.y;
        Qs[r][c4 + 2] = v4.z; Qs[r][c4 + 3] = v4.w;
    }

    float m_i[4], l_i[4], acc[4][4];
#pragma unroll
    for (int i = 0; i < 4; i++) {
        m_i[i] = -1e30f; l_i[i] = 0.0f;
#pragma unroll
        for (int j = 0; j < 4; j++) acc[i][j] = 0.0f;
    }
    const float scale = 0.125f;

    for (int kt = 0; kt <= qt; kt++) {
        __syncthreads();
        const float* Kt = Kbase + (size_t)(kt * 64) * NQKV_;
        const float* Vt = Vbase + (size_t)(kt * 64) * NQKV_;
        for (int i = tid; i < 64 * 16; i += 256) {
            int r = i >> 4, c4 = (i & 15) << 2;
            float4 k4 = *(const float4*)&Kt[(size_t)r * NQKV_ + c4];
            Ks[r][c4 + 0] = k4.x; Ks[r][c4 + 1] = k4.y;
            Ks[r][c4 + 2] = k4.z; Ks[r][c4 + 3] = k4.w;
            float4 v4 = *(const float4*)&Vt[(size_t)r * NQKV_ + c4];
            Vs[r][c4 + 0] = v4.x; Vs[r][c4 + 1] = v4.y;
            Vs[r][c4 + 2] = v4.z; Vs[r][c4 + 3] = v4.w;
        }
        __syncthreads();

        float s[4][4];
#pragma unroll
        for (int i = 0; i < 4; i++)
#pragma unroll
            for (int j = 0; j < 4; j++) s[i][j] = 0.0f;
#pragma unroll 8
        for (int d = 0; d < 64; d++) {
            float qv[4], kv[4];
#pragma unroll
            for (int i = 0; i < 4; i++) qv[i] = Qs[row0 + i][d];
#pragma unroll
            for (int j = 0; j < 4; j++) kv[j] = Ks[col0 + j][d];
#pragma unroll
            for (int i = 0; i < 4; i++)
#pragma unroll
                for (int j = 0; j < 4; j++)
                    s[i][j] = fmaf(qv[i], kv[j], s[i][j]);
        }
#pragma unroll
        for (int i = 0; i < 4; i++)
#pragma unroll
            for (int j = 0; j < 4; j++) s[i][j] *= scale;
        if (kt == qt) {
#pragma unroll
            for (int i = 0; i < 4; i++)
#pragma unroll
                for (int j = 0; j < 4; j++)
                    if (col0 + j > row0 + i) s[i][j] = -1e30f;
        }
#pragma unroll
        for (int i = 0; i < 4; i++) {
            float mx = fmaxf(fmaxf(s[i][0], s[i][1]), fmaxf(s[i][2], s[i][3]));
#pragma unroll
            for (int off = 8; off >= 1; off >>= 1)
                mx = fmaxf(mx, __shfl_xor_sync(0xffffffffu, mx, off));
            float newm = fmaxf(m_i[i], mx);
            float alpha = __expf(m_i[i] - newm);
            float rs = 0.0f;
#pragma unroll
            for (int j = 0; j < 4; j++) {
                float p = __expf(s[i][j] - newm);
                Ps[row0 + i][col0 + j] = p;
                rs += p;
            }
#pragma unroll
            for (int off = 8; off >= 1; off >>= 1)
                rs += __shfl_xor_sync(0xffffffffu, rs, off);
            l_i[i] = l_i[i] * alpha + rs;
            m_i[i] = newm;
#pragma unroll
            for (int j = 0; j < 4; j++) acc[i][j] *= alpha;
        }
        __syncthreads();
#pragma unroll 8
        for (int kk = 0; kk < 64; kk++) {
            float pv[4], vv[4];
#pragma unroll
            for (int i = 0; i < 4; i++) pv[i] = Ps[row0 + i][kk];
#pragma unroll
            for (int j = 0; j < 4; j++) vv[j] = Vs[kk][col0 + j];
#pragma unroll
            for (int i = 0; i < 4; i++)
#pragma unroll
                for (int j = 0; j < 4; j++)
                    acc[i][j] = fmaf(pv[i], vv[j], acc[i][j]);
        }
    }

#pragma unroll
    for (int i = 0; i < 4; i++) {
        int t = qt * 64 + row0 + i;
        float inv_l = 1.0f / l_i[i];
        size_t base = (size_t)(b * T_ + t) * C_ + h * 64 + col0;
#pragma unroll
        for (int j = 0; j < 4; j++) {
            float v = acc[i][j] * inv_l;
            __nv_bfloat16 hh = __float2bfloat16(v);
            g_attnhi[base + j] = hh;
            g_attnlo[base + j] = __float2bfloat16(v - __bfloat162float(hh));
        }
    }
}

// ---------------------------------------------------------------------------
extern "C" void kernel_launch(void* const* d_in, const int* in_sizes, int n_in,
                              void* d_out, int out_size) {
    const float* x    = (const float*)d_in[0];
    const float* Wqkv = (const float*)d_in[1];
    const float* Wout = (const float*)d_in[2];
    const float* bout = (const float*)d_in[3];
    float* out = (float*)d_out;

    conv_split_x<<<(M_ * C_ + 255) / 256, 256>>>(x);
    conv_split_t<<<dim3(NQKV_ / 32, C_ / 32), dim3(32, 8)>>>(Wqkv, 0, C_, NQKV_);
    conv_split_t<<<dim3(C_ / 32, C_ / 32), dim3(32, 8)>>>(Wout, 1, C_, C_);

    cudaFuncSetAttribute(hmma_gemm, cudaFuncAttributeMaxDynamicSharedMemorySize, GEMM_SMEM);
    hmma_gemm<<<dim3(NQKV_ / 128, M_ / 128), 256, GEMM_SMEM>>>(0, nullptr, nullptr, NQKV_);

    cudaFuncSetAttribute(flash_attn_kernel, cudaFuncAttributeMaxDynamicSharedMemorySize, FA_SMEM);
    flash_attn_kernel<<<dim3(T_ / 64, B_ * H_), 256, FA_SMEM>>>();

    hmma_gemm<<<dim3(C_ / 128, M_ / 128), 256, GEMM_SMEM>>>(1, out, bout, C_);
}

// round 4
// speedup vs baseline: 2.3686x; 1.3919x over previous
#include <cuda_runtime.h>
#include <cuda_bf16.h>
#include <cstdint>

#define B_  2
#define T_  2048
#define C_  1024
#define H_  16
#define M_  (B_*T_)      // 4096
#define NQKV_ (3*C_)     // 3072

// ---------------- device scratch (no allocation allowed) -------------------
__device__ __nv_bfloat16 g_xhi[M_*C_],     g_xlo[M_*C_];
__device__ __nv_bfloat16 g_wqkvThi[NQKV_*C_], g_wqkvTlo[NQKV_*C_];
__device__ __nv_bfloat16 g_woutThi[C_*C_], g_woutTlo[C_*C_];
__device__ __nv_bfloat16 g_attnhi[M_*C_],  g_attnlo[M_*C_];
// q/k/v in [b,h,t,d] bf16 hi/lo (q pre-scaled by 1/8)
__device__ __nv_bfloat16 g_qhi[M_*C_], g_qlo[M_*C_];
__device__ __nv_bfloat16 g_khi[M_*C_], g_klo[M_*C_];
__device__ __nv_bfloat16 g_vhi[M_*C_], g_vlo[M_*C_];

// ---------------- helpers ----------------------------------------------------
__device__ __forceinline__ uint32_t smem_u32_of(const void* p) {
    uint32_t a;
    asm("{ .reg .u64 t; cvta.to.shared.u64 t, %1; cvt.u32.u64 %0, t; }" : "=r"(a) : "l"(p));
    return a;
}
__device__ __forceinline__ void ldsm4(uint32_t* r, uint32_t addr) {
    asm volatile("ldmatrix.sync.aligned.m8n8.x4.shared.b16 {%0,%1,%2,%3}, [%4];"
                 : "=r"(r[0]), "=r"(r[1]), "=r"(r[2]), "=r"(r[3]) : "r"(addr));
}
__device__ __forceinline__ void ldsm4t(uint32_t* r, uint32_t addr) {
    asm volatile("ldmatrix.sync.aligned.m8n8.x4.trans.shared.b16 {%0,%1,%2,%3}, [%4];"
                 : "=r"(r[0]), "=r"(r[1]), "=r"(r[2]), "=r"(r[3]) : "r"(addr));
}
__device__ __forceinline__ void mma16816(float* c, const uint32_t* a,
                                         uint32_t b0, uint32_t b1) {
    asm volatile(
        "mma.sync.aligned.m16n8k16.row.col.f32.bf16.bf16.f32 "
        "{%0,%1,%2,%3}, {%4,%5,%6,%7}, {%8,%9}, {%0,%1,%2,%3};"
        : "+f"(c[0]), "+f"(c[1]), "+f"(c[2]), "+f"(c[3])
        : "r"(a[0]), "r"(a[1]), "r"(a[2]), "r"(a[3]), "r"(b0), "r"(b1));
}
#define CP16(dst, src) \
    asm volatile("cp.async.cg.shared.global [%0], [%1], 16;" :: "r"(dst), "l"(src) : "memory")
#define CP_COMMIT() asm volatile("cp.async.commit_group;" ::: "memory")
#define CP_WAIT1()  asm volatile("cp.async.wait_group 1;" ::: "memory")
#define CP_WAIT0()  asm volatile("cp.async.wait_group 0;" ::: "memory")

__device__ __forceinline__ uint32_t sw128(uint32_t off) {
    return off ^ ((off >> 3) & 0x70);
}
// pack two f32 -> bf16x2 (v0 low, v1 high)
__device__ __forceinline__ uint32_t pack_bf2(float v0, float v1) {
    uint32_t r;
    asm("cvt.rn.bf16x2.f32 %0, %1, %2;" : "=r"(r) : "f"(v1), "f"(v0));
    return r;
}
// hi/lo split of a pair
__device__ __forceinline__ void split2(float v0, float v1, uint32_t& hi, uint32_t& lo) {
    hi = pack_bf2(v0, v1);
    float h0 = __int_as_float(hi << 16);
    float h1 = __int_as_float(hi & 0xffff0000u);
    lo = pack_bf2(v0 - h0, v1 - h1);
}
// fast exp on fma/alu pipes (x <= ~0, handles -1e30 mask via clamp)
__device__ __forceinline__ float fexp(float x) {
    x = fmaxf(x, -87.0f);
    float y = fmaf(x, 1.4426950408889634f, 12582912.0f);
    int   n = __float_as_int(y) - 0x4B400000;
    float nf = y - 12582912.0f;
    float f = fmaf(x, 1.4426950408889634f, -nf);
    float p = fmaf(1.54035304e-4f, f, 1.33335581e-3f);
    p = fmaf(p, f, 9.61812911e-3f);
    p = fmaf(p, f, 5.55041087e-2f);
    p = fmaf(p, f, 2.40226507e-1f);
    p = fmaf(p, f, 6.93147181e-1f);
    p = fmaf(p, f, 1.0f);
    return __int_as_float((n + 127) << 23) * p;
}

// ---------------------------------------------------------------------------
// bf16 hi/lo compensated HMMA GEMM.  CTA 128x128, 8 warps (4x2), wtile 32x64.
// mode 0: A=x, B=WqkvT -> q/k/v bf16 hi/lo [b,h,t,d] (q scaled by 0.125)
// mode 1: A=attn, B=WoutT -> out fp32 (+bias)
// ---------------------------------------------------------------------------
#define SA_HI 0
#define SA_LO 16384
#define SB_HI 32768
#define SB_LO 49152
#define GEMM_SMEM 65536

__global__ __launch_bounds__(256) void hmma_gemm(int mode, float* __restrict__ out,
                                                 const float* __restrict__ bias, int N) {
    extern __shared__ char smem[];
    const uint32_t sbase = smem_u32_of(smem);
    const int tid = threadIdx.x, wid = tid >> 5, lane = tid & 31;
    const int bm = blockIdx.y * 128, bn = blockIdx.x * 128;
    const int wm = wid & 3, wn = wid >> 2;

    const __nv_bfloat16* Ahi = (mode == 0) ? g_xhi : g_attnhi;
    const __nv_bfloat16* Alo = (mode == 0) ? g_xlo : g_attnlo;
    const __nv_bfloat16* Bhi = (mode == 0) ? g_wqkvThi : g_woutThi;
    const __nv_bfloat16* Blo = (mode == 0) ? g_wqkvTlo : g_woutTlo;

    float acc[2][8][4];
#pragma unroll
    for (int i = 0; i < 2; i++)
#pragma unroll
        for (int j = 0; j < 8; j++)
#pragma unroll
            for (int k = 0; k < 4; k++) acc[i][j][k] = 0.0f;

    const int lrow = lane & 15;
    const int lkb  = (lane >> 4) << 4;

    for (int ch = 0; ch < 16; ch++) {
        const int k0 = ch * 64;
        for (int i = tid; i < 1024; i += 256) {
            int r = i >> 3, g = i & 7;
            uint32_t sw = sw128((uint32_t)(r * 128 + g * 16));
            size_t ga = (size_t)(bm + r) * C_ + k0 + g * 8;
            *(uint4*)(smem + SA_HI + sw) = *(const uint4*)(Ahi + ga);
            *(uint4*)(smem + SA_LO + sw) = *(const uint4*)(Alo + ga);
            size_t gb = (size_t)(bn + r) * C_ + k0 + g * 8;
            *(uint4*)(smem + SB_HI + sw) = *(const uint4*)(Bhi + gb);
            *(uint4*)(smem + SB_LO + sw) = *(const uint4*)(Blo + gb);
        }
        __syncthreads();

#pragma unroll
        for (int ks = 0; ks < 4; ks++) {
            uint32_t ah[2][4], al[2][4];
#pragma unroll
            for (int mf = 0; mf < 2; mf++) {
                uint32_t sw = sw128((uint32_t)((wm * 32 + mf * 16 + lrow) * 128 + ks * 32 + lkb));
                ldsm4(ah[mf], sbase + SA_HI + sw);
                ldsm4(al[mf], sbase + SA_LO + sw);
            }
#pragma unroll
            for (int np = 0; np < 4; np++) {
                uint32_t sw = sw128((uint32_t)((wn * 64 + np * 16 + lrow) * 128 + ks * 32 + lkb));
                uint32_t bh[4], bl[4];
                ldsm4(bh, sbase + SB_HI + sw);
                ldsm4(bl, sbase + SB_LO + sw);
#pragma unroll
                for (int mf = 0; mf < 2; mf++) {
                    mma16816(acc[mf][np * 2],     ah[mf], bh[0], bh[2]);
                    mma16816(acc[mf][np * 2 + 1], ah[mf], bh[1], bh[3]);
                    mma16816(acc[mf][np * 2],     ah[mf], bl[0], bl[2]);
                    mma16816(acc[mf][np * 2 + 1], ah[mf], bl[1], bl[3]);
                    mma16816(acc[mf][np * 2],     al[mf], bh[0], bh[2]);
                    mma16816(acc[mf][np * 2 + 1], al[mf], bh[1], bh[3]);
                }
            }
        }
        __syncthreads();
    }

    const int r0 = bm + wm * 32 + (lane >> 2);
    const int c0 = bn + wn * 64 + (lane & 3) * 2;
    if (mode == 0) {
#pragma unroll
        for (int nf = 0; nf < 8; nf++) {
            int col = c0 + nf * 8;
            int which = col >> 10;
            int hh = (col >> 6) & 15;
            int d = col & 63;
            float sc = (which == 0) ? 0.125f : 1.0f;
            __nv_bfloat16* dhi = (which == 0) ? g_qhi : (which == 1) ? g_khi : g_vhi;
            __nv_bfloat16* dlo = (which == 0) ? g_qlo : (which == 1) ? g_klo : g_vlo;
#pragma unroll
            for (int mf = 0; mf < 2; mf++) {
                int row = r0 + mf * 16;
                int t = row & (T_ - 1), b = row >> 11;
                size_t i1 = ((size_t)((b << 4) + hh) * T_ + t) * 64 + d;
                uint32_t h0, l0, h1, l1;
                split2(acc[mf][nf][0] * sc, acc[mf][nf][1] * sc, h0, l0);
                split2(acc[mf][nf][2] * sc, acc[mf][nf][3] * sc, h1, l1);
                *(uint32_t*)&dhi[i1] = h0;
                *(uint32_t*)&dlo[i1] = l0;
                *(uint32_t*)&dhi[i1 + 8 * 64] = h1;
                *(uint32_t*)&dlo[i1 + 8 * 64] = l1;
            }
        }
    } else {
#pragma unroll
        for (int mf = 0; mf < 2; mf++) {
#pragma unroll
            for (int nf = 0; nf < 8; nf++) {
                int row = r0 + mf * 16;
                int col = c0 + nf * 8;
                float b0 = bias[col], b1 = bias[col + 1];
                *(float2*)&out[(size_t)row * N + col] =
                    make_float2(acc[mf][nf][0] + b0, acc[mf][nf][1] + b1);
                *(float2*)&out[(size_t)(row + 8) * N + col] =
                    make_float2(acc[mf][nf][2] + b0, acc[mf][nf][3] + b1);
            }
        }
    }
}

// ---------------------------------------------------------------------------
__global__ void conv_split_x(const float* __restrict__ src) {
    int i = blockIdx.x * 256 + threadIdx.x;
    if (i < M_ * C_) {
        float v = src[i];
        __nv_bfloat16 h = __float2bfloat16(v);
        g_xhi[i] = h;
        g_xlo[i] = __float2bfloat16(v - __bfloat162float(h));
    }
}
__global__ void conv_split_t(const float* __restrict__ src, int mode, int K, int N) {
    __shared__ float s[32][33];
    __nv_bfloat16* hi = (mode == 0) ? g_wqkvThi : g_woutThi;
    __nv_bfloat16* lo = (mode == 0) ? g_wqkvTlo : g_woutTlo;
    int n0 = blockIdx.x * 32, k0 = blockIdx.y * 32;
    int tx = threadIdx.x, ty = threadIdx.y;
#pragma unroll
    for (int yy = 0; yy < 32; yy += 8)
        s[ty + yy][tx] = src[(size_t)(k0 + ty + yy) * N + n0 + tx];
    __syncthreads();
#pragma unroll
    for (int yy = 0; yy < 32; yy += 8) {
        float v = s[tx][ty + yy];
        __nv_bfloat16 h = __float2bfloat16(v);
        size_t o = (size_t)(n0 + ty + yy) * K + k0 + tx;
        hi[o] = h;
        lo[o] = __float2bfloat16(v - __bfloat162float(h));
    }
}

// ---------------------------------------------------------------------------
// Tensor-core flash attention.
// Block = 256 thr (8 warps), q-tile 128 rows (16 rows/warp), k-tiles of 64.
// smem: 2 x 32KB double-buffered K/V (hi/lo); Q staged once in buf1.
// ---------------------------------------------------------------------------
#define FL_SMEM 65536

__device__ __forceinline__ void fl_load_tile(uint32_t dst, size_t gbase, int kt, int tid) {
    const __nv_bfloat16* kh = g_khi + gbase + (size_t)kt * 64 * 64;
    const __nv_bfloat16* kl = g_klo + gbase + (size_t)kt * 64 * 64;
    const __nv_bfloat16* vh = g_vhi + gbase + (size_t)kt * 64 * 64;
    const __nv_bfloat16* vl = g_vlo + gbase + (size_t)kt * 64 * 64;
#pragma unroll
    for (int i = tid; i < 512; i += 256) {
        int r = i >> 3, g = i & 7;
        uint32_t sw = sw128((uint32_t)(r * 128 + g * 16));
        size_t go = (size_t)r * 64 + g * 8;
        CP16(dst + 0     + sw, kh + go);
        CP16(dst + 8192  + sw, kl + go);
        CP16(dst + 16384 + sw, vh + go);
        CP16(dst + 24576 + sw, vl + go);
    }
}

__global__ __launch_bounds__(256) void hmma_flash() {
    extern __shared__ char smem[];
    const uint32_t sbase = smem_u32_of(smem);
    const int tid = threadIdx.x, w = tid >> 5, lane = tid & 31;
    const int qt = blockIdx.x, bh = blockIdx.y;
    const int nkt = 2 * (qt + 1);
    const size_t gbase = (size_t)bh * T_ * 64;
    const int lrow = lane & 15, lkb = (lane >> 4) << 4;

    // stage Q (hi->buf1+0, lo->buf1+16K) and prefetch tile 0 into buf0
    {
        const __nv_bfloat16* qh = g_qhi + gbase + (size_t)qt * 128 * 64;
        const __nv_bfloat16* ql = g_qlo + gbase + (size_t)qt * 128 * 64;
#pragma unroll
        for (int i = tid; i < 1024; i += 256) {
            int r = i >> 3, g = i & 7;
            uint32_t sw = sw128((uint32_t)(r * 128 + g * 16));
            size_t go = (size_t)r * 64 + g * 8;
            CP16(sbase + 32768 + sw, qh + go);
            CP16(sbase + 49152 + sw, ql + go);
        }
        CP_COMMIT();
    }
    fl_load_tile(sbase, gbase, 0, tid);
    CP_COMMIT();
    CP_WAIT1();          // Q group done
    __syncthreads();

    uint32_t qfh[4][4], qfl[4][4];
#pragma unroll
    for (int ks = 0; ks < 4; ks++) {
        uint32_t sw = sw128((uint32_t)((w * 16 + lrow) * 128 + ks * 32 + lkb));
        ldsm4(qfh[ks], sbase + 32768 + sw);
        ldsm4(qfl[ks], sbase + 49152 + sw);
    }
    __syncthreads();     // Q staging (buf1) free for reuse

    float o[8][4];
#pragma unroll
    for (int j = 0; j < 8; j++)
#pragma unroll
        for (int k = 0; k < 4; k++) o[j][k] = 0.0f;
    float m1 = -1e30f, m2 = -1e30f, l1 = 0.0f, l2 = 0.0f;

    for (int kt = 0; kt < nkt; kt++) {
        const uint32_t buf = sbase + (uint32_t)(kt & 1) * 32768;
        if (kt + 1 < nkt) {
            fl_load_tile(sbase + (uint32_t)((kt + 1) & 1) * 32768, gbase, kt + 1, tid);
            CP_COMMIT();
            CP_WAIT1();
        } else {
            CP_WAIT0();
        }
        __syncthreads();

        // ---- S = (Q/8) K^T  (compensated)
        float s[8][4];
#pragma unroll
        for (int j = 0; j < 8; j++)
#pragma unroll
            for (int k = 0; k < 4; k++) s[j][k] = 0.0f;
#pragma unroll
        for (int kn = 0; kn < 4; kn++) {
#pragma unroll
            for (int ks = 0; ks < 4; ks++) {
                uint32_t sw = sw128((uint32_t)((kn * 16 + lrow) * 128 + ks * 32 + lkb));
                uint32_t kh4[4], kl4[4];
                ldsm4(kh4, buf + 0 + sw);
                ldsm4(kl4, buf + 8192 + sw);
                mma16816(s[kn * 2],     qfh[ks], kh4[0], kh4[2]);
                mma16816(s[kn * 2 + 1], qfh[ks], kh4[1], kh4[3]);
                mma16816(s[kn * 2],     qfh[ks], kl4[0], kl4[2]);
                mma16816(s[kn * 2 + 1], qfh[ks], kl4[1], kl4[3]);
                mma16816(s[kn * 2],     qfl[ks], kh4[0], kh4[2]);
                mma16816(s[kn * 2 + 1], qfl[ks], kh4[1], kh4[3]);
            }
        }

        // ---- causal mask
        const int gr1 = qt * 128 + w * 16 + (lane >> 2);
        if (kt * 64 + 63 > qt * 128 + w * 16) {
#pragma unroll
            for (int j = 0; j < 8; j++) {
                int c = kt * 64 + j * 8 + (lane & 3) * 2;
                if (c     > gr1)     s[j][0] = -1e30f;
                if (c + 1 > gr1)     s[j][1] = -1e30f;
                if (c     > gr1 + 8) s[j][2] = -1e30f;
                if (c + 1 > gr1 + 8) s[j][3] = -1e30f;
            }
        }

        // ---- online softmax
        float mx1 = -1e30f, mx2 = -1e30f;
#pragma unroll
        for (int j = 0; j < 8; j++) {
            mx1 = fmaxf(mx1, fmaxf(s[j][0], s[j][1]));
            mx2 = fmaxf(mx2, fmaxf(s[j][2], s[j][3]));
        }
        mx1 = fmaxf(mx1, __shfl_xor_sync(0xffffffffu, mx1, 1));
        mx1 = fmaxf(mx1, __shfl_xor_sync(0xffffffffu, mx1, 2));
        mx2 = fmaxf(mx2, __shfl_xor_sync(0xffffffffu, mx2, 1));
        mx2 = fmaxf(mx2, __shfl_xor_sync(0xffffffffu, mx2, 2));
        float nm1 = fmaxf(m1, mx1), nm2 = fmaxf(m2, mx2);
        float a1 = fexp(m1 - nm1), a2 = fexp(m2 - nm2);
        m1 = nm1; m2 = nm2;
        float rs1 = 0.0f, rs2 = 0.0f;
#pragma unroll
        for (int j = 0; j < 8; j++) {
            s[j][0] = fexp(s[j][0] - nm1);
            s[j][1] = fexp(s[j][1] - nm1);
            s[j][2] = fexp(s[j][2] - nm2);
            s[j][3] = fexp(s[j][3] - nm2);
            rs1 += s[j][0] + s[j][1];
            rs2 += s[j][2] + s[j][3];
        }
        rs1 += __shfl_xor_sync(0xffffffffu, rs1, 1);
        rs1 += __shfl_xor_sync(0xffffffffu, rs1, 2);
        rs2 += __shfl_xor_sync(0xffffffffu, rs2, 1);
        rs2 += __shfl_xor_sync(0xffffffffu, rs2, 2);
        l1 = l1 * a1 + rs1;
        l2 = l2 * a2 + rs2;
#pragma unroll
        for (int j = 0; j < 8; j++) {
            o[j][0] *= a1; o[j][1] *= a1;
            o[j][2] *= a2; o[j][3] *= a2;
        }

        // ---- O += P V  (compensated)
        const int lg = lane >> 3, lr8 = lane & 7;
#pragma unroll
        for (int kn = 0; kn < 4; kn++) {
            uint32_t ph[4], pl[4];
            split2(s[2 * kn][0],     s[2 * kn][1],     ph[0], pl[0]);
            split2(s[2 * kn][2],     s[2 * kn][3],     ph[1], pl[1]);
            split2(s[2 * kn + 1][0], s[2 * kn + 1][1], ph[2], pl[2]);
            split2(s[2 * kn + 1][2], s[2 * kn + 1][3], ph[3], pl[3]);
#pragma unroll
            for (int nd = 0; nd < 4; nd++) {
                int key = kn * 16 + lr8 + (lg >> 1) * 8;
                int dim = nd * 16 + (lg & 1) * 8;
                uint32_t sw = sw128((uint32_t)(key * 128 + dim * 2));
                uint32_t vh4[4], vl4[4];
                ldsm4t(vh4, buf + 16384 + sw);
                ldsm4t(vl4, buf + 24576 + sw);
                mma16816(o[nd * 2],     ph, vh4[0], vh4[2]);
                mma16816(o[nd * 2 + 1], ph, vh4[1], vh4[3]);
                mma16816(o[nd * 2],     pl, vh4[0], vh4[2]);
                mma16816(o[nd * 2 + 1], pl, vh4[1], vh4[3]);
                mma16816(o[nd * 2],     ph, vl4[0], vl4[2]);
                mma16816(o[nd * 2 + 1], ph, vl4[1], vl4[3]);
            }
        }
        __syncthreads();
    }

    // ---- epilogue: write attn hi/lo bf16 [m][C]
    const int b = bh >> 4, hh = bh & 15;
    const int t1 = qt * 128 + w * 16 + (lane >> 2);
    const float inv1 = 1.0f / l1, inv2 = 1.0f / l2;
#pragma unroll
    for (int j = 0; j < 8; j++) {
        int d = j * 8 + (lane & 3) * 2;
        size_t i1 = ((size_t)(b * T_ + t1)) * C_ + hh * 64 + d;
        size_t i2 = i1 + (size_t)8 * C_;
        uint32_t h0, l0;
        split2(o[j][0] * inv1, o[j][1] * inv1, h0, l0);
        *(uint32_t*)&g_attnhi[i1] = h0;
        *(uint32_t*)&g_attnlo[i1] = l0;
        split2(o[j][2] * inv2, o[j][3] * inv2, h0, l0);
        *(uint32_t*)&g_attnhi[i2] = h0;
        *(uint32_t*)&g_attnlo[i2] = l0;
    }
}

// ---------------------------------------------------------------------------
extern "C" void kernel_launch(void* const* d_in, const int* in_sizes, int n_in,
                              void* d_out, int out_size) {
    const float* x    = (const float*)d_in[0];
    const float* Wqkv = (const float*)d_in[1];
    const float* Wout = (const float*)d_in[2];
    const float* bout = (const float*)d_in[3];
    float* out = (float*)d_out;

    conv_split_x<<<(M_ * C_ + 255) / 256, 256>>>(x);
    conv_split_t<<<dim3(NQKV_ / 32, C_ / 32), dim3(32, 8)>>>(Wqkv, 0, C_, NQKV_);
    conv_split_t<<<dim3(C_ / 32, C_ / 32), dim3(32, 8)>>>(Wout, 1, C_, C_);

    cudaFuncSetAttribute(hmma_gemm, cudaFuncAttributeMaxDynamicSharedMemorySize, GEMM_SMEM);
    hmma_gemm<<<dim3(NQKV_ / 128, M_ / 128), 256, GEMM_SMEM>>>(0, nullptr, nullptr, NQKV_);

    cudaFuncSetAttribute(hmma_flash, cudaFuncAttributeMaxDynamicSharedMemorySize, FL_SMEM);
    hmma_flash<<<dim3(T_ / 128, B_ * H_), 256, FL_SMEM>>>();

    hmma_gemm<<<dim3(C_ / 128, M_ / 128), 256, GEMM_SMEM>>>(1, out, bout, C_);
}

// round 5
// speedup vs baseline: 2.9988x; 1.2661x over previous
#include <cuda_runtime.h>
#include <cuda_bf16.h>
#include <cstdint>

#define B_  2
#define T_  2048
#define C_  1024
#define H_  16
#define M_  (B_*T_)      // 4096
#define NQKV_ (3*C_)     // 3072

// ---------------- device scratch (no allocation allowed) -------------------
__device__ __nv_bfloat16 g_xhi[M_*C_],     g_xlo[M_*C_];
__device__ __nv_bfloat16 g_wqkvThi[NQKV_*C_], g_wqkvTlo[NQKV_*C_];
__device__ __nv_bfloat16 g_woutThi[C_*C_], g_woutTlo[C_*C_];
__device__ __nv_bfloat16 g_attnhi[M_*C_],  g_attnlo[M_*C_];
// q/k/v in [b,h,t,d] bf16 hi/lo (q pre-scaled by 1/8)
__device__ __nv_bfloat16 g_qhi[M_*C_], g_qlo[M_*C_];
__device__ __nv_bfloat16 g_khi[M_*C_], g_klo[M_*C_];
__device__ __nv_bfloat16 g_vhi[M_*C_], g_vlo[M_*C_];

// ---------------- helpers ----------------------------------------------------
__device__ __forceinline__ uint32_t smem_u32_of(const void* p) {
    uint32_t a;
    asm("{ .reg .u64 t; cvta.to.shared.u64 t, %1; cvt.u32.u64 %0, t; }" : "=r"(a) : "l"(p));
    return a;
}
__device__ __forceinline__ void ldsm4(uint32_t* r, uint32_t addr) {
    asm volatile("ldmatrix.sync.aligned.m8n8.x4.shared.b16 {%0,%1,%2,%3}, [%4];"
                 : "=r"(r[0]), "=r"(r[1]), "=r"(r[2]), "=r"(r[3]) : "r"(addr));
}
__device__ __forceinline__ void ldsm4t(uint32_t* r, uint32_t addr) {
    asm volatile("ldmatrix.sync.aligned.m8n8.x4.trans.shared.b16 {%0,%1,%2,%3}, [%4];"
                 : "=r"(r[0]), "=r"(r[1]), "=r"(r[2]), "=r"(r[3]) : "r"(addr));
}
__device__ __forceinline__ void mma16816(float* c, const uint32_t* a,
                                         uint32_t b0, uint32_t b1) {
    asm volatile(
        "mma.sync.aligned.m16n8k16.row.col.f32.bf16.bf16.f32 "
        "{%0,%1,%2,%3}, {%4,%5,%6,%7}, {%8,%9}, {%0,%1,%2,%3};"
        : "+f"(c[0]), "+f"(c[1]), "+f"(c[2]), "+f"(c[3])
        : "r"(a[0]), "r"(a[1]), "r"(a[2]), "r"(a[3]), "r"(b0), "r"(b1));
}
#define CP16(dst, src) \
    asm volatile("cp.async.cg.shared.global [%0], [%1], 16;" :: "r"(dst), "l"(src) : "memory")
#define CP_COMMIT() asm volatile("cp.async.commit_group;" ::: "memory")
#define CP_WAIT1()  asm volatile("cp.async.wait_group 1;" ::: "memory")
#define CP_WAIT0()  asm volatile("cp.async.wait_group 0;" ::: "memory")

__device__ __forceinline__ uint32_t sw128(uint32_t off) {
    return off ^ ((off >> 3) & 0x70);
}
__device__ __forceinline__ uint32_t sw64(uint32_t off) {
    return off ^ ((off >> 3) & 0x30);
}
__device__ __forceinline__ uint32_t pack_bf2(float v0, float v1) {
    uint32_t r;
    asm("cvt.rn.bf16x2.f32 %0, %1, %2;" : "=r"(r) : "f"(v1), "f"(v0));
    return r;
}
__device__ __forceinline__ void split2(float v0, float v1, uint32_t& hi, uint32_t& lo) {
    hi = pack_bf2(v0, v1);
    float h0 = __int_as_float(hi << 16);
    float h1 = __int_as_float(hi & 0xffff0000u);
    lo = pack_bf2(v0 - h0, v1 - h1);
}
__device__ __forceinline__ float fexp(float x) {
    x = fmaxf(x, -87.0f);
    float y = fmaf(x, 1.4426950408889634f, 12582912.0f);
    int   n = __float_as_int(y) - 0x4B400000;
    float nf = y - 12582912.0f;
    float f = fmaf(x, 1.4426950408889634f, -nf);
    float p = fmaf(1.54035304e-4f, f, 1.33335581e-3f);
    p = fmaf(p, f, 9.61812911e-3f);
    p = fmaf(p, f, 5.55041087e-2f);
    p = fmaf(p, f, 2.40226507e-1f);
    p = fmaf(p, f, 6.93147181e-1f);
    p = fmaf(p, f, 1.0f);
    return __int_as_float((n + 127) << 23) * p;
}

// ---------------------------------------------------------------------------
// bf16 hi/lo compensated HMMA GEMM, cp.async double-buffered.
// CTA 128x128, 8 warps (4x2), warp tile 32x64, K-chunk 32 (SW64, 64B rows).
// smem/stage: A_hi 8K | A_lo 8K | B_hi 8K | B_lo 8K = 32K;  2 stages = 64K.
// mode 0: A=x, B=WqkvT -> q/k/v bf16 hi/lo [b,h,t,d] (q scaled by 0.125)
// mode 1: A=attn, B=WoutT -> out fp32 (+bias)
// ---------------------------------------------------------------------------
#define GS_A_HI 0
#define GS_A_LO 8192
#define GS_B_HI 16384
#define GS_B_LO 24576
#define GS_STAGE 32768
#define GEMM_SMEM 65536
#define NCHUNK 32

__device__ __forceinline__ void gemm_load_stage(
    char* smem, uint32_t dst, int ch, int bm, int bn, int tid,
    const __nv_bfloat16* Ahi, const __nv_bfloat16* Alo,
    const __nv_bfloat16* Bhi, const __nv_bfloat16* Blo) {
    const int k0 = ch * 32;
#pragma unroll
    for (int i = tid; i < 512; i += 256) {
        int r = i >> 2, g = i & 3;
        uint32_t sw = sw64((uint32_t)(r * 64 + g * 16));
        size_t ga = (size_t)(bm + r) * C_ + k0 + g * 8;
        CP16(dst + GS_A_HI + sw, Ahi + ga);
        CP16(dst + GS_A_LO + sw, Alo + ga);
        size_t gb = (size_t)(bn + r) * C_ + k0 + g * 8;
        CP16(dst + GS_B_HI + sw, Bhi + gb);
        CP16(dst + GS_B_LO + sw, Blo + gb);
    }
}

__global__ __launch_bounds__(256, 2) void hmma_gemm(int mode, float* __restrict__ out,
                                                    const float* __restrict__ bias, int N) {
    extern __shared__ char smem[];
    const uint32_t sbase = smem_u32_of(smem);
    const int tid = threadIdx.x, wid = tid >> 5, lane = tid & 31;
    const int bm = blockIdx.y * 128, bn = blockIdx.x * 128;
    const int wm = wid & 3, wn = wid >> 2;

    const __nv_bfloat16* Ahi = (mode == 0) ? g_xhi : g_attnhi;
    const __nv_bfloat16* Alo = (mode == 0) ? g_xlo : g_attnlo;
    const __nv_bfloat16* Bhi = (mode == 0) ? g_wqkvThi : g_woutThi;
    const __nv_bfloat16* Blo = (mode == 0) ? g_wqkvTlo : g_woutTlo;

    float acc[2][8][4];
#pragma unroll
    for (int i = 0; i < 2; i++)
#pragma unroll
        for (int j = 0; j < 8; j++)
#pragma unroll
            for (int k = 0; k < 4; k++) acc[i][j][k] = 0.0f;

    const int lrow = lane & 15;
    const int lkb  = (lane >> 4) << 4;

    gemm_load_stage(smem, sbase, 0, bm, bn, tid, Ahi, Alo, Bhi, Blo);
    CP_COMMIT();
    gemm_load_stage(smem, sbase + GS_STAGE, 1, bm, bn, tid, Ahi, Alo, Bhi, Blo);
    CP_COMMIT();

    for (int ch = 0; ch < NCHUNK; ch++) {
        if (ch < NCHUNK - 1) { CP_WAIT1(); } else { CP_WAIT0(); }
        __syncthreads();
        const uint32_t buf = sbase + (uint32_t)(ch & 1) * GS_STAGE;

#pragma unroll
        for (int ks = 0; ks < 2; ks++) {
            uint32_t ah[2][4], al[2][4];
#pragma unroll
            for (int mf = 0; mf < 2; mf++) {
                uint32_t sw = sw64((uint32_t)((wm * 32 + mf * 16 + lrow) * 64 + ks * 32 + lkb));
                ldsm4(ah[mf], buf + GS_A_HI + sw);
                ldsm4(al[mf], buf + GS_A_LO + sw);
            }
#pragma unroll
            for (int np = 0; np < 4; np++) {
                uint32_t sw = sw64((uint32_t)((wn * 64 + np * 16 + lrow) * 64 + ks * 32 + lkb));
                uint32_t bh[4], bl[4];
                ldsm4(bh, buf + GS_B_HI + sw);
                ldsm4(bl, buf + GS_B_LO + sw);
#pragma unroll
                for (int mf = 0; mf < 2; mf++) {
                    mma16816(acc[mf][np * 2],     ah[mf], bh[0], bh[2]);
                    mma16816(acc[mf][np * 2 + 1], ah[mf], bh[1], bh[3]);
                    mma16816(acc[mf][np * 2],     ah[mf], bl[0], bl[2]);
                    mma16816(acc[mf][np * 2 + 1], ah[mf], bl[1], bl[3]);
                    mma16816(acc[mf][np * 2],     al[mf], bh[0], bh[2]);
                    mma16816(acc[mf][np * 2 + 1], al[mf], bh[1], bh[3]);
                }
            }
        }
        __syncthreads();
        if (ch + 2 < NCHUNK) {
            gemm_load_stage(smem, sbase + (uint32_t)(ch & 1) * GS_STAGE, ch + 2,
                            bm, bn, tid, Ahi, Alo, Bhi, Blo);
            CP_COMMIT();
        }
    }

    const int r0 = bm + wm * 32 + (lane >> 2);
    const int c0 = bn + wn * 64 + (lane & 3) * 2;
    if (mode == 0) {
#pragma unroll
        for (int nf = 0; nf < 8; nf++) {
            int col = c0 + nf * 8;
            int which = col >> 10;
            int hh = (col >> 6) & 15;
            int d = col & 63;
            float sc = (which == 0) ? 0.125f : 1.0f;
            __nv_bfloat16* dhi = (which == 0) ? g_qhi : (which == 1) ? g_khi : g_vhi;
            __nv_bfloat16* dlo = (which == 0) ? g_qlo : (which == 1) ? g_klo : g_vlo;
#pragma unroll
            for (int mf = 0; mf < 2; mf++) {
                int row = r0 + mf * 16;
                int t = row & (T_ - 1), b = row >> 11;
                size_t i1 = ((size_t)((b << 4) + hh) * T_ + t) * 64 + d;
                uint32_t h0, l0, h1, l1;
                split2(acc[mf][nf][0] * sc, acc[mf][nf][1] * sc, h0, l0);
                split2(acc[mf][nf][2] * sc, acc[mf][nf][3] * sc, h1, l1);
                *(uint32_t*)&dhi[i1] = h0;
                *(uint32_t*)&dlo[i1] = l0;
                *(uint32_t*)&dhi[i1 + 8 * 64] = h1;
                *(uint32_t*)&dlo[i1 + 8 * 64] = l1;
            }
        }
    } else {
#pragma unroll
        for (int mf = 0; mf < 2; mf++) {
#pragma unroll
            for (int nf = 0; nf < 8; nf++) {
                int row = r0 + mf * 16;
                int col = c0 + nf * 8;
                float b0 = bias[col], b1 = bias[col + 1];
                *(float2*)&out[(size_t)row * N + col] =
                    make_float2(acc[mf][nf][0] + b0, acc[mf][nf][1] + b1);
                *(float2*)&out[(size_t)(row + 8) * N + col] =
                    make_float2(acc[mf][nf][2] + b0, acc[mf][nf][3] + b1);
            }
        }
    }
}

// ---------------------------------------------------------------------------
__global__ void conv_split_x(const float* __restrict__ src) {
    int i = blockIdx.x * 256 + threadIdx.x;
    if (i < M_ * C_) {
        float v = src[i];
        __nv_bfloat16 h = __float2bfloat16(v);
        g_xhi[i] = h;
        g_xlo[i] = __float2bfloat16(v - __bfloat162float(h));
    }
}
__global__ void conv_split_t(const float* __restrict__ src, int mode, int K, int N) {
    __shared__ float s[32][33];
    __nv_bfloat16* hi = (mode == 0) ? g_wqkvThi : g_woutThi;
    __nv_bfloat16* lo = (mode == 0) ? g_wqkvTlo : g_woutTlo;
    int n0 = blockIdx.x * 32, k0 = blockIdx.y * 32;
    int tx = threadIdx.x, ty = threadIdx.y;
#pragma unroll
    for (int yy = 0; yy < 32; yy += 8)
        s[ty + yy][tx] = src[(size_t)(k0 + ty + yy) * N + n0 + tx];
    __syncthreads();
#pragma unroll
    for (int yy = 0; yy < 32; yy += 8) {
        float v = s[tx][ty + yy];
        __nv_bfloat16 h = __float2bfloat16(v);
        size_t o = (size_t)(n0 + ty + yy) * K + k0 + tx;
        hi[o] = h;
        lo[o] = __float2bfloat16(v - __bfloat162float(h));
    }
}

// ---------------------------------------------------------------------------
// Tensor-core flash attention (unchanged from round 4).
// ---------------------------------------------------------------------------
#define FL_SMEM 65536

__device__ __forceinline__ void fl_load_tile(uint32_t dst, size_t gbase, int kt, int tid) {
    const __nv_bfloat16* kh = g_khi + gbase + (size_t)kt * 64 * 64;
    const __nv_bfloat16* kl = g_klo + gbase + (size_t)kt * 64 * 64;
    const __nv_bfloat16* vh = g_vhi + gbase + (size_t)kt * 64 * 64;
    const __nv_bfloat16* vl = g_vlo + gbase + (size_t)kt * 64 * 64;
#pragma unroll
    for (int i = tid; i < 512; i += 256) {
        int r = i >> 3, g = i & 7;
        uint32_t sw = sw128((uint32_t)(r * 128 + g * 16));
        size_t go = (size_t)r * 64 + g * 8;
        CP16(dst + 0     + sw, kh + go);
        CP16(dst + 8192  + sw, kl + go);
        CP16(dst + 16384 + sw, vh + go);
        CP16(dst + 24576 + sw, vl + go);
    }
}

__global__ __launch_bounds__(256) void hmma_flash() {
    extern __shared__ char smem[];
    const uint32_t sbase = smem_u32_of(smem);
    const int tid = threadIdx.x, w = tid >> 5, lane = tid & 31;
    const int qt = blockIdx.x, bh = blockIdx.y;
    const int nkt = 2 * (qt + 1);
    const size_t gbase = (size_t)bh * T_ * 64;
    const int lrow = lane & 15, lkb = (lane >> 4) << 4;

    {
        const __nv_bfloat16* qh = g_qhi + gbase + (size_t)qt * 128 * 64;
        const __nv_bfloat16* ql = g_qlo + gbase + (size_t)qt * 128 * 64;
#pragma unroll
        for (int i = tid; i < 1024; i += 256) {
            int r = i >> 3, g = i & 7;
            uint32_t sw = sw128((uint32_t)(r * 128 + g * 16));
            size_t go = (size_t)r * 64 + g * 8;
            CP16(sbase + 32768 + sw, qh + go);
            CP16(sbase + 49152 + sw, ql + go);
        }
        CP_COMMIT();
    }
    fl_load_tile(sbase, gbase, 0, tid);
    CP_COMMIT();
    CP_WAIT1();
    __syncthreads();

    uint32_t qfh[4][4], qfl[4][4];
#pragma unroll
    for (int ks = 0; ks < 4; ks++) {
        uint32_t sw = sw128((uint32_t)((w * 16 + lrow) * 128 + ks * 32 + lkb));
        ldsm4(qfh[ks], sbase + 32768 + sw);
        ldsm4(qfl[ks], sbase + 49152 + sw);
    }
    __syncthreads();

    float o[8][4];
#pragma unroll
    for (int j = 0; j < 8; j++)
#pragma unroll
        for (int k = 0; k < 4; k++) o[j][k] = 0.0f;
    float m1 = -1e30f, m2 = -1e30f, l1 = 0.0f, l2 = 0.0f;

    for (int kt = 0; kt < nkt; kt++) {
        const uint32_t buf = sbase + (uint32_t)(kt & 1) * 32768;
        if (kt + 1 < nkt) {
            fl_load_tile(sbase + (uint32_t)((kt + 1) & 1) * 32768, gbase, kt + 1, tid);
            CP_COMMIT();
            CP_WAIT1();
        } else {
            CP_WAIT0();
        }
        __syncthreads();

        float s[8][4];
#pragma unroll
        for (int j = 0; j < 8; j++)
#pragma unroll
            for (int k = 0; k < 4; k++) s[j][k] = 0.0f;
#pragma unroll
        for (int kn = 0; kn < 4; kn++) {
#pragma unroll
            for (int ks = 0; ks < 4; ks++) {
                uint32_t sw = sw128((uint32_t)((kn * 16 + lrow) * 128 + ks * 32 + lkb));
                uint32_t kh4[4], kl4[4];
                ldsm4(kh4, buf + 0 + sw);
                ldsm4(kl4, buf + 8192 + sw);
                mma16816(s[kn * 2],     qfh[ks], kh4[0], kh4[2]);
                mma16816(s[kn * 2 + 1], qfh[ks], kh4[1], kh4[3]);
                mma16816(s[kn * 2],     qfh[ks], kl4[0], kl4[2]);
                mma16816(s[kn * 2 + 1], qfh[ks], kl4[1], kl4[3]);
                mma16816(s[kn * 2],     qfl[ks], kh4[0], kh4[2]);
                mma16816(s[kn * 2 + 1], qfl[ks], kh4[1], kh4[3]);
            }
        }

        const int gr1 = qt * 128 + w * 16 + (lane >> 2);
        if (kt * 64 + 63 > qt * 128 + w * 16) {
#pragma unroll
            for (int j = 0; j < 8; j++) {
                int c = kt * 64 + j * 8 + (lane & 3) * 2;
                if (c     > gr1)     s[j][0] = -1e30f;
                if (c + 1 > gr1)     s[j][1] = -1e30f;
                if (c     > gr1 + 8) s[j][2] = -1e30f;
                if (c + 1 > gr1 + 8) s[j][3] = -1e30f;
            }
        }

        float mx1 = -1e30f, mx2 = -1e30f;
#pragma unroll
        for (int j = 0; j < 8; j++) {
            mx1 = fmaxf(mx1, fmaxf(s[j][0], s[j][1]));
            mx2 = fmaxf(mx2, fmaxf(s[j][2], s[j][3]));
        }
        mx1 = fmaxf(mx1, __shfl_xor_sync(0xffffffffu, mx1, 1));
        mx1 = fmaxf(mx1, __shfl_xor_sync(0xffffffffu, mx1, 2));
        mx2 = fmaxf(mx2, __shfl_xor_sync(0xffffffffu, mx2, 1));
        mx2 = fmaxf(mx2, __shfl_xor_sync(0xffffffffu, mx2, 2));
        float nm1 = fmaxf(m1, mx1), nm2 = fmaxf(m2, mx2);
        float a1 = fexp(m1 - nm1), a2 = fexp(m2 - nm2);
        m1 = nm1; m2 = nm2;
        float rs1 = 0.0f, rs2 = 0.0f;
#pragma unroll
        for (int j = 0; j < 8; j++) {
            s[j][0] = fexp(s[j][0] - nm1);
            s[j][1] = fexp(s[j][1] - nm1);
            s[j][2] = fexp(s[j][2] - nm2);
            s[j][3] = fexp(s[j][3] - nm2);
            rs1 += s[j][0] + s[j][1];
            rs2 += s[j][2] + s[j][3];
        }
        rs1 += __shfl_xor_sync(0xffffffffu, rs1, 1);
        rs1 += __shfl_xor_sync(0xffffffffu, rs1, 2);
        rs2 += __shfl_xor_sync(0xffffffffu, rs2, 1);
        rs2 += __shfl_xor_sync(0xffffffffu, rs2, 2);
        l1 = l1 * a1 + rs1;
        l2 = l2 * a2 + rs2;
#pragma unroll
        for (int j = 0; j < 8; j++) {
            o[j][0] *= a1; o[j][1] *= a1;
            o[j][2] *= a2; o[j][3] *= a2;
        }

        const int lg = lane >> 3, lr8 = lane & 7;
#pragma unroll
        for (int kn = 0; kn < 4; kn++) {
            uint32_t ph[4], pl[4];
            split2(s[2 * kn][0],     s[2 * kn][1],     ph[0], pl[0]);
            split2(s[2 * kn][2],     s[2 * kn][3],     ph[1], pl[1]);
            split2(s[2 * kn + 1][0], s[2 * kn + 1][1], ph[2], pl[2]);
            split2(s[2 * kn + 1][2], s[2 * kn + 1][3], ph[3], pl[3]);
#pragma unroll
            for (int nd = 0; nd < 4; nd++) {
                int key = kn * 16 + lr8 + (lg >> 1) * 8;
                int dim = nd * 16 + (lg & 1) * 8;
                uint32_t sw = sw128((uint32_t)(key * 128 + dim * 2));
                uint32_t vh4[4], vl4[4];
                ldsm4t(vh4, buf + 16384 + sw);
                ldsm4t(vl4, buf + 24576 + sw);
                mma16816(o[nd * 2],     ph, vh4[0], vh4[2]);
                mma16816(o[nd * 2 + 1], ph, vh4[1], vh4[3]);
                mma16816(o[nd * 2],     pl, vh4[0], vh4[2]);
                mma16816(o[nd * 2 + 1], pl, vh4[1], vh4[3]);
                mma16816(o[nd * 2],     ph, vl4[0], vl4[2]);
                mma16816(o[nd * 2 + 1], ph, vl4[1], vl4[3]);
            }
        }
        __syncthreads();
    }

    const int b = bh >> 4, hh = bh & 15;
    const int t1 = qt * 128 + w * 16 + (lane >> 2);
    const float inv1 = 1.0f / l1, inv2 = 1.0f / l2;
#pragma unroll
    for (int j = 0; j < 8; j++) {
        int d = j * 8 + (lane & 3) * 2;
        size_t i1 = ((size_t)(b * T_ + t1)) * C_ + hh * 64 + d;
        size_t i2 = i1 + (size_t)8 * C_;
        uint32_t h0, l0;
        split2(o[j][0] * inv1, o[j][1] * inv1, h0, l0);
        *(uint32_t*)&g_attnhi[i1] = h0;
        *(uint32_t*)&g_attnlo[i1] = l0;
        split2(o[j][2] * inv2, o[j][3] * inv2, h0, l0);
        *(uint32_t*)&g_attnhi[i2] = h0;
        *(uint32_t*)&g_attnlo[i2] = l0;
    }
}

// ---------------------------------------------------------------------------
extern "C" void kernel_launch(void* const* d_in, const int* in_sizes, int n_in,
                              void* d_out, int out_size) {
    const float* x    = (const float*)d_in[0];
    const float* Wqkv = (const float*)d_in[1];
    const float* Wout = (const float*)d_in[2];
    const float* bout = (const float*)d_in[3];
    float* out = (float*)d_out;

    conv_split_x<<<(M_ * C_ + 255) / 256, 256>>>(x);
    conv_split_t<<<dim3(NQKV_ / 32, C_ / 32), dim3(32, 8)>>>(Wqkv, 0, C_, NQKV_);
    conv_split_t<<<dim3(C_ / 32, C_ / 32), dim3(32, 8)>>>(Wout, 1, C_, C_);

    cudaFuncSetAttribute(hmma_gemm, cudaFuncAttributeMaxDynamicSharedMemorySize, GEMM_SMEM);
    hmma_gemm<<<dim3(NQKV_ / 128, M_ / 128), 256, GEMM_SMEM>>>(0, nullptr, nullptr, NQKV_);

    cudaFuncSetAttribute(hmma_flash, cudaFuncAttributeMaxDynamicSharedMemorySize, FL_SMEM);
    hmma_flash<<<dim3(T_ / 128, B_ * H_), 256, FL_SMEM>>>();

    hmma_gemm<<<dim3(C_ / 128, M_ / 128), 256, GEMM_SMEM>>>(1, out, bout, C_);
}

// round 6
// speedup vs baseline: 3.8418x; 1.2811x over previous
#include <cuda_runtime.h>
#include <cuda_fp16.h>
#include <cstdint>

#define B_  2
#define T_  2048
#define C_  1024
#define H_  16
#define M_  (B_*T_)      // 4096
#define NQKV_ (3*C_)     // 3072

// ---------------- device scratch (no allocation allowed) -------------------
__device__ __half g_xh[M_*C_];                       // x as single fp16
__device__ __half g_wqkvThi[NQKV_*C_], g_wqkvTlo[NQKV_*C_];
__device__ __half g_woutThi[C_*C_],    g_woutTlo[C_*C_];
__device__ __half g_attnh[M_*C_];                    // attn out single fp16
// q/k/v in [b,h,t,d] fp16 hi/lo (q pre-scaled by 1/8)
__device__ __half g_qhi[M_*C_], g_qlo[M_*C_];
__device__ __half g_khi[M_*C_], g_klo[M_*C_];
__device__ __half g_vhi[M_*C_], g_vlo[M_*C_];

// ---------------- helpers ----------------------------------------------------
__device__ __forceinline__ uint32_t smem_u32_of(const void* p) {
    uint32_t a;
    asm("{ .reg .u64 t; cvta.to.shared.u64 t, %1; cvt.u32.u64 %0, t; }" : "=r"(a) : "l"(p));
    return a;
}
__device__ __forceinline__ void ldsm4(uint32_t* r, uint32_t addr) {
    asm volatile("ldmatrix.sync.aligned.m8n8.x4.shared.b16 {%0,%1,%2,%3}, [%4];"
                 : "=r"(r[0]), "=r"(r[1]), "=r"(r[2]), "=r"(r[3]) : "r"(addr));
}
__device__ __forceinline__ void ldsm4t(uint32_t* r, uint32_t addr) {
    asm volatile("ldmatrix.sync.aligned.m8n8.x4.trans.shared.b16 {%0,%1,%2,%3}, [%4];"
                 : "=r"(r[0]), "=r"(r[1]), "=r"(r[2]), "=r"(r[3]) : "r"(addr));
}
__device__ __forceinline__ void mma16816(float* c, const uint32_t* a,
                                         uint32_t b0, uint32_t b1) {
    asm volatile(
        "mma.sync.aligned.m16n8k16.row.col.f32.f16.f16.f32 "
        "{%0,%1,%2,%3}, {%4,%5,%6,%7}, {%8,%9}, {%0,%1,%2,%3};"
        : "+f"(c[0]), "+f"(c[1]), "+f"(c[2]), "+f"(c[3])
        : "r"(a[0]), "r"(a[1]), "r"(a[2]), "r"(a[3]), "r"(b0), "r"(b1));
}
#define CP16(dst, src) \
    asm volatile("cp.async.cg.shared.global [%0], [%1], 16;" :: "r"(dst), "l"(src) : "memory")
#define CP_COMMIT() asm volatile("cp.async.commit_group;" ::: "memory")
#define CP_WAIT1()  asm volatile("cp.async.wait_group 1;" ::: "memory")
#define CP_WAIT0()  asm volatile("cp.async.wait_group 0;" ::: "memory")

__device__ __forceinline__ uint32_t sw128(uint32_t off) {
    return off ^ ((off >> 3) & 0x70);
}
__device__ __forceinline__ uint32_t sw64(uint32_t off) {
    return off ^ ((off >> 3) & 0x30);
}
__device__ __forceinline__ uint32_t pack_h2(float v0, float v1) {
    __half2 hp = __floats2half2_rn(v0, v1);
    return *(uint32_t*)&hp;
}
// fp16 hi/lo split of a pair (hi = rn(v), lo = rn(v - hi))
__device__ __forceinline__ void split2h(float v0, float v1, uint32_t& hi, uint32_t& lo) {
    __half2 hp = __floats2half2_rn(v0, v1);
    hi = *(uint32_t*)&hp;
    float h0 = __half2float(__low2half(hp));
    float h1 = __half2float(__high2half(hp));
    lo = pack_h2(v0 - h0, v1 - h1);
}
__device__ __forceinline__ float fexp(float x) {
    x = fmaxf(x, -87.0f);
    float y = fmaf(x, 1.4426950408889634f, 12582912.0f);
    int   n = __float_as_int(y) - 0x4B400000;
    float nf = y - 12582912.0f;
    float f = fmaf(x, 1.4426950408889634f, -nf);
    float p = fmaf(1.54035304e-4f, f, 1.33335581e-3f);
    p = fmaf(p, f, 9.61812911e-3f);
    p = fmaf(p, f, 5.55041087e-2f);
    p = fmaf(p, f, 2.40226507e-1f);
    p = fmaf(p, f, 6.93147181e-1f);
    p = fmaf(p, f, 1.0f);
    return __int_as_float((n + 127) << 23) * p;
}

// ---------------------------------------------------------------------------
// fp16 2-term HMMA GEMM: D = A_fp16 * (B_hi + B_lo).
// CTA 128x128, 8 warps (4x2), warp tile 32x64, K-chunk 32 (SW64, 64B rows).
// smem/stage: A 8K | B_hi 8K | B_lo 8K = 24K;  2 stages = 48K.
// mode 0: A=xh, B=WqkvT -> q/k/v fp16 hi/lo [b,h,t,d] (q scaled by 0.125)
// mode 1: A=attnh, B=WoutT -> out fp32 (+bias)
// ---------------------------------------------------------------------------
#define GS_A    0
#define GS_B_HI 8192
#define GS_B_LO 16384
#define GS_STAGE 24576
#define GEMM_SMEM 49152
#define NCHUNK 32

__device__ __forceinline__ void gemm_load_stage(
    uint32_t dst, int ch, int bm, int bn, int tid,
    const __half* Ah, const __half* Bhi, const __half* Blo) {
    const int k0 = ch * 32;
#pragma unroll
    for (int i = tid; i < 512; i += 256) {
        int r = i >> 2, g = i & 3;
        uint32_t sw = sw64((uint32_t)(r * 64 + g * 16));
        size_t ga = (size_t)(bm + r) * C_ + k0 + g * 8;
        CP16(dst + GS_A + sw, Ah + ga);
        size_t gb = (size_t)(bn + r) * C_ + k0 + g * 8;
        CP16(dst + GS_B_HI + sw, Bhi + gb);
        CP16(dst + GS_B_LO + sw, Blo + gb);
    }
}

__global__ __launch_bounds__(256, 2) void hmma_gemm(int mode, float* __restrict__ out,
                                                    const float* __restrict__ bias, int N) {
    extern __shared__ char smem[];
    const uint32_t sbase = smem_u32_of(smem);
    const int tid = threadIdx.x, wid = tid >> 5, lane = tid & 31;
    const int bm = blockIdx.y * 128, bn = blockIdx.x * 128;
    const int wm = wid & 3, wn = wid >> 2;

    const __half* Ah  = (mode == 0) ? g_xh : g_attnh;
    const __half* Bhi = (mode == 0) ? g_wqkvThi : g_woutThi;
    const __half* Blo = (mode == 0) ? g_wqkvTlo : g_woutTlo;

    float acc[2][8][4];
#pragma unroll
    for (int i = 0; i < 2; i++)
#pragma unroll
        for (int j = 0; j < 8; j++)
#pragma unroll
            for (int k = 0; k < 4; k++) acc[i][j][k] = 0.0f;

    const int lrow = lane & 15;
    const int lkb  = (lane >> 4) << 4;

    gemm_load_stage(sbase, 0, bm, bn, tid, Ah, Bhi, Blo);
    CP_COMMIT();
    gemm_load_stage(sbase + GS_STAGE, 1, bm, bn, tid, Ah, Bhi, Blo);
    CP_COMMIT();

    for (int ch = 0; ch < NCHUNK; ch++) {
        if (ch < NCHUNK - 1) { CP_WAIT1(); } else { CP_WAIT0(); }
        __syncthreads();
        const uint32_t buf = sbase + (uint32_t)(ch & 1) * GS_STAGE;

#pragma unroll
        for (int ks = 0; ks < 2; ks++) {
            uint32_t ah[2][4];
#pragma unroll
            for (int mf = 0; mf < 2; mf++) {
                uint32_t sw = sw64((uint32_t)((wm * 32 + mf * 16 + lrow) * 64 + ks * 32 + lkb));
                ldsm4(ah[mf], buf + GS_A + sw);
            }
#pragma unroll
            for (int np = 0; np < 4; np++) {
                uint32_t sw = sw64((uint32_t)((wn * 64 + np * 16 + lrow) * 64 + ks * 32 + lkb));
                uint32_t bh[4], bl[4];
                ldsm4(bh, buf + GS_B_HI + sw);
                ldsm4(bl, buf + GS_B_LO + sw);
#pragma unroll
                for (int mf = 0; mf < 2; mf++) {
                    mma16816(acc[mf][np * 2],     ah[mf], bh[0], bh[2]);
                    mma16816(acc[mf][np * 2 + 1], ah[mf], bh[1], bh[3]);
                    mma16816(acc[mf][np * 2],     ah[mf], bl[0], bl[2]);
                    mma16816(acc[mf][np * 2 + 1], ah[mf], bl[1], bl[3]);
                }
            }
        }
        __syncthreads();
        if (ch + 2 < NCHUNK) {
            gemm_load_stage(sbase + (uint32_t)(ch & 1) * GS_STAGE, ch + 2,
                            bm, bn, tid, Ah, Bhi, Blo);
            CP_COMMIT();
        }
    }

    const int r0 = bm + wm * 32 + (lane >> 2);
    const int c0 = bn + wn * 64 + (lane & 3) * 2;
    if (mode == 0) {
#pragma unroll
        for (int nf = 0; nf < 8; nf++) {
            int col = c0 + nf * 8;
            int which = col >> 10;
            int hh = (col >> 6) & 15;
            int d = col & 63;
            float sc = (which == 0) ? 0.125f : 1.0f;
            __half* dhi = (which == 0) ? g_qhi : (which == 1) ? g_khi : g_vhi;
            __half* dlo = (which == 0) ? g_qlo : (which == 1) ? g_klo : g_vlo;
#pragma unroll
            for (int mf = 0; mf < 2; mf++) {
                int row = r0 + mf * 16;
                int t = row & (T_ - 1), b = row >> 11;
                size_t i1 = ((size_t)((b << 4) + hh) * T_ + t) * 64 + d;
                uint32_t h0, l0, h1, l1;
                split2h(acc[mf][nf][0] * sc, acc[mf][nf][1] * sc, h0, l0);
                split2h(acc[mf][nf][2] * sc, acc[mf][nf][3] * sc, h1, l1);
                *(uint32_t*)&dhi[i1] = h0;
                *(uint32_t*)&dlo[i1] = l0;
                *(uint32_t*)&dhi[i1 + 8 * 64] = h1;
                *(uint32_t*)&dlo[i1 + 8 * 64] = l1;
            }
        }
    } else {
#pragma unroll
        for (int mf = 0; mf < 2; mf++) {
#pragma unroll
            for (int nf = 0; nf < 8; nf++) {
                int row = r0 + mf * 16;
                int col = c0 + nf * 8;
                float b0 = bias[col], b1 = bias[col + 1];
                *(float2*)&out[(size_t)row * N + col] =
                    make_float2(acc[mf][nf][0] + b0, acc[mf][nf][1] + b1);
                *(float2*)&out[(size_t)(row + 8) * N + col] =
                    make_float2(acc[mf][nf][2] + b0, acc[mf][nf][3] + b1);
            }
        }
    }
}

// ---------------------------------------------------------------------------
__global__ void conv_x(const float* __restrict__ src) {
    int i = blockIdx.x * 256 + threadIdx.x;
    if (i < M_ * C_) g_xh[i] = __float2half(src[i]);
}
__global__ void conv_split_t(const float* __restrict__ src, int mode, int K, int N) {
    __shared__ float s[32][33];
    __half* hi = (mode == 0) ? g_wqkvThi : g_woutThi;
    __half* lo = (mode == 0) ? g_wqkvTlo : g_woutTlo;
    int n0 = blockIdx.x * 32, k0 = blockIdx.y * 32;
    int tx = threadIdx.x, ty = threadIdx.y;
#pragma unroll
    for (int yy = 0; yy < 32; yy += 8)
        s[ty + yy][tx] = src[(size_t)(k0 + ty + yy) * N + n0 + tx];
    __syncthreads();
#pragma unroll
    for (int yy = 0; yy < 32; yy += 8) {
        float v = s[tx][ty + yy];
        __half h = __float2half(v);
        size_t o = (size_t)(n0 + ty + yy) * K + k0 + tx;
        hi[o] = h;
        lo[o] = __float2half(v - __half2float(h));
    }
}

// ---------------------------------------------------------------------------
// fp16 flash attention: S 3-term (q pair x k pair), PV 2-term (P single x V pair)
// Block 256 thr (8 warps), q-tile 128 rows, k-tiles of 64, double-buffered.
// ---------------------------------------------------------------------------
#define FL_SMEM 65536

__device__ __forceinline__ void fl_load_tile(uint32_t dst, size_t gbase, int kt, int tid) {
    const __half* kh = g_khi + gbase + (size_t)kt * 64 * 64;
    const __half* kl = g_klo + gbase + (size_t)kt * 64 * 64;
    const __half* vh = g_vhi + gbase + (size_t)kt * 64 * 64;
    const __half* vl = g_vlo + gbase + (size_t)kt * 64 * 64;
#pragma unroll
    for (int i = tid; i < 512; i += 256) {
        int r = i >> 3, g = i & 7;
        uint32_t sw = sw128((uint32_t)(r * 128 + g * 16));
        size_t go = (size_t)r * 64 + g * 8;
        CP16(dst + 0     + sw, kh + go);
        CP16(dst + 8192  + sw, kl + go);
        CP16(dst + 16384 + sw, vh + go);
        CP16(dst + 24576 + sw, vl + go);
    }
}

__global__ __launch_bounds__(256) void hmma_flash() {
    extern __shared__ char smem[];
    const uint32_t sbase = smem_u32_of(smem);
    const int tid = threadIdx.x, w = tid >> 5, lane = tid & 31;
    const int qt = blockIdx.x, bh = blockIdx.y;
    const int nkt = 2 * (qt + 1);
    const size_t gbase = (size_t)bh * T_ * 64;
    const int lrow = lane & 15, lkb = (lane >> 4) << 4;

    {
        const __half* qh = g_qhi + gbase + (size_t)qt * 128 * 64;
        const __half* ql = g_qlo + gbase + (size_t)qt * 128 * 64;
#pragma unroll
        for (int i = tid; i < 1024; i += 256) {
            int r = i >> 3, g = i & 7;
            uint32_t sw = sw128((uint32_t)(r * 128 + g * 16));
            size_t go = (size_t)r * 64 + g * 8;
            CP16(sbase + 32768 + sw, qh + go);
            CP16(sbase + 49152 + sw, ql + go);
        }
        CP_COMMIT();
    }
    fl_load_tile(sbase, gbase, 0, tid);
    CP_COMMIT();
    CP_WAIT1();
    __syncthreads();

    uint32_t qfh[4][4], qfl[4][4];
#pragma unroll
    for (int ks = 0; ks < 4; ks++) {
        uint32_t sw = sw128((uint32_t)((w * 16 + lrow) * 128 + ks * 32 + lkb));
        ldsm4(qfh[ks], sbase + 32768 + sw);
        ldsm4(qfl[ks], sbase + 49152 + sw);
    }
    __syncthreads();

    float o[8][4];
#pragma unroll
    for (int j = 0; j < 8; j++)
#pragma unroll
        for (int k = 0; k < 4; k++) o[j][k] = 0.0f;
    float m1 = -1e30f, m2 = -1e30f, l1 = 0.0f, l2 = 0.0f;

    for (int kt = 0; kt < nkt; kt++) {
        const uint32_t buf = sbase + (uint32_t)(kt & 1) * 32768;
        if (kt + 1 < nkt) {
            fl_load_tile(sbase + (uint32_t)((kt + 1) & 1) * 32768, gbase, kt + 1, tid);
            CP_COMMIT();
            CP_WAIT1();
        } else {
            CP_WAIT0();
        }
        __syncthreads();

        // ---- S = (Q/8) K^T : 3-term fp16 (residual ~2^-22)
        float s[8][4];
#pragma unroll
        for (int j = 0; j < 8; j++)
#pragma unroll
            for (int k = 0; k < 4; k++) s[j][k] = 0.0f;
#pragma unroll
        for (int kn = 0; kn < 4; kn++) {
#pragma unroll
            for (int ks = 0; ks < 4; ks++) {
                uint32_t sw = sw128((uint32_t)((kn * 16 + lrow) * 128 + ks * 32 + lkb));
                uint32_t kh4[4], kl4[4];
                ldsm4(kh4, buf + 0 + sw);
                ldsm4(kl4, buf + 8192 + sw);
                mma16816(s[kn * 2],     qfh[ks], kh4[0], kh4[2]);
                mma16816(s[kn * 2 + 1], qfh[ks], kh4[1], kh4[3]);
                mma16816(s[kn * 2],     qfh[ks], kl4[0], kl4[2]);
                mma16816(s[kn * 2 + 1], qfh[ks], kl4[1], kl4[3]);
                mma16816(s[kn * 2],     qfl[ks], kh4[0], kh4[2]);
                mma16816(s[kn * 2 + 1], qfl[ks], kh4[1], kh4[3]);
            }
        }

        const int gr1 = qt * 128 + w * 16 + (lane >> 2);
        if (kt * 64 + 63 > qt * 128 + w * 16) {
#pragma unroll
            for (int j = 0; j < 8; j++) {
                int c = kt * 64 + j * 8 + (lane & 3) * 2;
                if (c     > gr1)     s[j][0] = -1e30f;
                if (c + 1 > gr1)     s[j][1] = -1e30f;
                if (c     > gr1 + 8) s[j][2] = -1e30f;
                if (c + 1 > gr1 + 8) s[j][3] = -1e30f;
            }
        }

        float mx1 = -1e30f, mx2 = -1e30f;
#pragma unroll
        for (int j = 0; j < 8; j++) {
            mx1 = fmaxf(mx1, fmaxf(s[j][0], s[j][1]));
            mx2 = fmaxf(mx2, fmaxf(s[j][2], s[j][3]));
        }
        mx1 = fmaxf(mx1, __shfl_xor_sync(0xffffffffu, mx1, 1));
        mx1 = fmaxf(mx1, __shfl_xor_sync(0xffffffffu, mx1, 2));
        mx2 = fmaxf(mx2, __shfl_xor_sync(0xffffffffu, mx2, 1));
        mx2 = fmaxf(mx2, __shfl_xor_sync(0xffffffffu, mx2, 2));
        float nm1 = fmaxf(m1, mx1), nm2 = fmaxf(m2, mx2);
        float a1 = fexp(m1 - nm1), a2 = fexp(m2 - nm2);
        m1 = nm1; m2 = nm2;
        float rs1 = 0.0f, rs2 = 0.0f;
#pragma unroll
        for (int j = 0; j < 8; j++) {
            s[j][0] = fexp(s[j][0] - nm1);
            s[j][1] = fexp(s[j][1] - nm1);
            s[j][2] = fexp(s[j][2] - nm2);
            s[j][3] = fexp(s[j][3] - nm2);
            rs1 += s[j][0] + s[j][1];
            rs2 += s[j][2] + s[j][3];
        }
        rs1 += __shfl_xor_sync(0xffffffffu, rs1, 1);
        rs1 += __shfl_xor_sync(0xffffffffu, rs1, 2);
        rs2 += __shfl_xor_sync(0xffffffffu, rs2, 1);
        rs2 += __shfl_xor_sync(0xffffffffu, rs2, 2);
        l1 = l1 * a1 + rs1;
        l2 = l2 * a2 + rs2;
#pragma unroll
        for (int j = 0; j < 8; j++) {
            o[j][0] *= a1; o[j][1] *= a1;
            o[j][2] *= a2; o[j][3] *= a2;
        }

        // ---- O += P V : P single fp16, V hi/lo (2-term)
        const int lg = lane >> 3, lr8 = lane & 7;
#pragma unroll
        for (int kn = 0; kn < 4; kn++) {
            uint32_t ph[4];
            ph[0] = pack_h2(s[2 * kn][0],     s[2 * kn][1]);
            ph[1] = pack_h2(s[2 * kn][2],     s[2 * kn][3]);
            ph[2] = pack_h2(s[2 * kn + 1][0], s[2 * kn + 1][1]);
            ph[3] = pack_h2(s[2 * kn + 1][2], s[2 * kn + 1][3]);
#pragma unroll
            for (int nd = 0; nd < 4; nd++) {
                int key = kn * 16 + lr8 + (lg >> 1) * 8;
                int dim = nd * 16 + (lg & 1) * 8;
                uint32_t sw = sw128((uint32_t)(key * 128 + dim * 2));
                uint32_t vh4[4], vl4[4];
                ldsm4t(vh4, buf + 16384 + sw);
                ldsm4t(vl4, buf + 24576 + sw);
                mma16816(o[nd * 2],     ph, vh4[0], vh4[2]);
                mma16816(o[nd * 2 + 1], ph, vh4[1], vh4[3]);
                mma16816(o[nd * 2],     ph, vl4[0], vl4[2]);
                mma16816(o[nd * 2 + 1], ph, vl4[1], vl4[3]);
            }
        }
        __syncthreads();
    }

    // ---- epilogue: attn out as single fp16 [m][C]
    const int b = bh >> 4, hh = bh & 15;
    const int t1 = qt * 128 + w * 16 + (lane >> 2);
    const float inv1 = 1.0f / l1, inv2 = 1.0f / l2;
#pragma unroll
    for (int j = 0; j < 8; j++) {
        int d = j * 8 + (lane & 3) * 2;
        size_t i1 = ((size_t)(b * T_ + t1)) * C_ + hh * 64 + d;
        size_t i2 = i1 + (size_t)8 * C_;
        *(uint32_t*)&g_attnh[i1] = pack_h2(o[j][0] * inv1, o[j][1] * inv1);
        *(uint32_t*)&g_attnh[i2] = pack_h2(o[j][2] * inv2, o[j][3] * inv2);
    }
}

// ---------------------------------------------------------------------------
extern "C" void kernel_launch(void* const* d_in, const int* in_sizes, int n_in,
                              void* d_out, int out_size) {
    const float* x    = (const float*)d_in[0];
    const float* Wqkv = (const float*)d_in[1];
    const float* Wout = (const float*)d_in[2];
    const float* bout = (const float*)d_in[3];
    float* out = (float*)d_out;

    conv_x<<<(M_ * C_ + 255) / 256, 256>>>(x);
    conv_split_t<<<dim3(NQKV_ / 32, C_ / 32), dim3(32, 8)>>>(Wqkv, 0, C_, NQKV_);
    conv_split_t<<<dim3(C_ / 32, C_ / 32), dim3(32, 8)>>>(Wout, 1, C_, C_);

    cudaFuncSetAttribute(hmma_gemm, cudaFuncAttributeMaxDynamicSharedMemorySize, GEMM_SMEM);
    hmma_gemm<<<dim3(NQKV_ / 128, M_ / 128), 256, GEMM_SMEM>>>(0, nullptr, nullptr, NQKV_);

    cudaFuncSetAttribute(hmma_flash, cudaFuncAttributeMaxDynamicSharedMemorySize, FL_SMEM);
    hmma_flash<<<dim3(T_ / 128, B_ * H_), 256, FL_SMEM>>>();

    hmma_gemm<<<dim3(C_ / 128, M_ / 128), 256, GEMM_SMEM>>>(1, out, bout, C_);
}

// round 7
// speedup vs baseline: 4.5467x; 1.1835x over previous
#include <cuda_runtime.h>
#include <cuda_fp16.h>
#include <cstdint>

#define B_  2
#define T_  2048
#define C_  1024
#define H_  16
#define M_  (B_*T_)      // 4096
#define NQKV_ (3*C_)     // 3072

// ---------------- device scratch (no allocation allowed) -------------------
__device__ __half g_xh[M_*C_];                       // x as single fp16
__device__ __half g_wqkvThi[NQKV_*C_], g_wqkvTlo[NQKV_*C_];
__device__ __half g_woutThi[C_*C_],    g_woutTlo[C_*C_];
__device__ __half g_attnh[M_*C_];                    // attn out single fp16
// q/k in [b,h,t,d] fp16 hi/lo (q pre-scaled by 1/8); v single fp16
__device__ __half g_qhi[M_*C_], g_qlo[M_*C_];
__device__ __half g_khi[M_*C_], g_klo[M_*C_];
__device__ __half g_vh[M_*C_];

// ---------------- helpers ----------------------------------------------------
__device__ __forceinline__ uint32_t smem_u32_of(const void* p) {
    uint32_t a;
    asm("{ .reg .u64 t; cvta.to.shared.u64 t, %1; cvt.u32.u64 %0, t; }" : "=r"(a) : "l"(p));
    return a;
}
__device__ __forceinline__ void ldsm4(uint32_t* r, uint32_t addr) {
    asm volatile("ldmatrix.sync.aligned.m8n8.x4.shared.b16 {%0,%1,%2,%3}, [%4];"
                 : "=r"(r[0]), "=r"(r[1]), "=r"(r[2]), "=r"(r[3]) : "r"(addr));
}
__device__ __forceinline__ void ldsm4t(uint32_t* r, uint32_t addr) {
    asm volatile("ldmatrix.sync.aligned.m8n8.x4.trans.shared.b16 {%0,%1,%2,%3}, [%4];"
                 : "=r"(r[0]), "=r"(r[1]), "=r"(r[2]), "=r"(r[3]) : "r"(addr));
}
__device__ __forceinline__ void mma16816(float* c, const uint32_t* a,
                                         uint32_t b0, uint32_t b1) {
    asm volatile(
        "mma.sync.aligned.m16n8k16.row.col.f32.f16.f16.f32 "
        "{%0,%1,%2,%3}, {%4,%5,%6,%7}, {%8,%9}, {%0,%1,%2,%3};"
        : "+f"(c[0]), "+f"(c[1]), "+f"(c[2]), "+f"(c[3])
        : "r"(a[0]), "r"(a[1]), "r"(a[2]), "r"(a[3]), "r"(b0), "r"(b1));
}
#define CP16(dst, src) \
    asm volatile("cp.async.cg.shared.global [%0], [%1], 16;" :: "r"(dst), "l"(src) : "memory")
#define CP_COMMIT() asm volatile("cp.async.commit_group;" ::: "memory")
#define CP_WAIT1()  asm volatile("cp.async.wait_group 1;" ::: "memory")
#define CP_WAIT0()  asm volatile("cp.async.wait_group 0;" ::: "memory")

__device__ __forceinline__ uint32_t sw128(uint32_t off) {
    return off ^ ((off >> 3) & 0x70);
}
__device__ __forceinline__ uint32_t sw64(uint32_t off) {
    return off ^ ((off >> 3) & 0x30);
}
__device__ __forceinline__ uint32_t pack_h2(float v0, float v1) {
    __half2 hp = __floats2half2_rn(v0, v1);
    return *(uint32_t*)&hp;
}
__device__ __forceinline__ void split2h(float v0, float v1, uint32_t& hi, uint32_t& lo) {
    __half2 hp = __floats2half2_rn(v0, v1);
    hi = *(uint32_t*)&hp;
    float h0 = __half2float(__low2half(hp));
    float h1 = __half2float(__high2half(hp));
    lo = pack_h2(v0 - h0, v1 - h1);
}
__device__ __forceinline__ float fexp(float x) {
    x = fmaxf(x, -87.0f);
    float y = fmaf(x, 1.4426950408889634f, 12582912.0f);
    int   n = __float_as_int(y) - 0x4B400000;
    float nf = y - 12582912.0f;
    float f = fmaf(x, 1.4426950408889634f, -nf);
    float p = fmaf(1.54035304e-4f, f, 1.33335581e-3f);
    p = fmaf(p, f, 9.61812911e-3f);
    p = fmaf(p, f, 5.55041087e-2f);
    p = fmaf(p, f, 2.40226507e-1f);
    p = fmaf(p, f, 6.93147181e-1f);
    p = fmaf(p, f, 1.0f);
    return __int_as_float((n + 127) << 23) * p;
}

// ---------------------------------------------------------------------------
// fp16 2-term HMMA GEMM: D = A_fp16 * (B_hi + B_lo).
// Pure-V output CTAs (mode 0, bn>=2C) run 1-term: D = A * B_hi.
// CTA 128x128, 8 warps (4x2), warp tile 32x64, K-chunk 32 (SW64).
// ---------------------------------------------------------------------------
#define GS_A    0
#define GS_B_HI 8192
#define GS_B_LO 16384
#define GS_STAGE 24576
#define GEMM_SMEM 49152
#define NCHUNK 32

__device__ __forceinline__ void gemm_load_stage(
    uint32_t dst, int ch, int bm, int bn, int tid, bool loadBlo,
    const __half* Ah, const __half* Bhi, const __half* Blo) {
    const int k0 = ch * 32;
#pragma unroll
    for (int i = tid; i < 512; i += 256) {
        int r = i >> 2, g = i & 3;
        uint32_t sw = sw64((uint32_t)(r * 64 + g * 16));
        size_t ga = (size_t)(bm + r) * C_ + k0 + g * 8;
        CP16(dst + GS_A + sw, Ah + ga);
        size_t gb = (size_t)(bn + r) * C_ + k0 + g * 8;
        CP16(dst + GS_B_HI + sw, Bhi + gb);
        if (loadBlo) CP16(dst + GS_B_LO + sw, Blo + gb);
    }
}

__global__ __launch_bounds__(256, 2) void hmma_gemm(int mode, float* __restrict__ out,
                                                    const float* __restrict__ bias, int N) {
    extern __shared__ char smem[];
    const uint32_t sbase = smem_u32_of(smem);
    const int tid = threadIdx.x, wid = tid >> 5, lane = tid & 31;
    const int bm = blockIdx.y * 128, bn = blockIdx.x * 128;
    const int wm = wid & 3, wn = wid >> 2;

    const __half* Ah  = (mode == 0) ? g_xh : g_attnh;
    const __half* Bhi = (mode == 0) ? g_wqkvThi : g_woutThi;
    const __half* Blo = (mode == 0) ? g_wqkvTlo : g_woutTlo;
    const bool twoterm = !(mode == 0 && bn >= 2 * C_);   // V-only CTAs: 1-term

    float acc[2][8][4];
#pragma unroll
    for (int i = 0; i < 2; i++)
#pragma unroll
        for (int j = 0; j < 8; j++)
#pragma unroll
            for (int k = 0; k < 4; k++) acc[i][j][k] = 0.0f;

    const int lrow = lane & 15;
    const int lkb  = (lane >> 4) << 4;

    gemm_load_stage(sbase, 0, bm, bn, tid, twoterm, Ah, Bhi, Blo);
    CP_COMMIT();
    gemm_load_stage(sbase + GS_STAGE, 1, bm, bn, tid, twoterm, Ah, Bhi, Blo);
    CP_COMMIT();

    for (int ch = 0; ch < NCHUNK; ch++) {
        if (ch < NCHUNK - 1) { CP_WAIT1(); } else { CP_WAIT0(); }
        __syncthreads();
        const uint32_t buf = sbase + (uint32_t)(ch & 1) * GS_STAGE;

#pragma unroll
        for (int ks = 0; ks < 2; ks++) {
            uint32_t ah[2][4];
#pragma unroll
            for (int mf = 0; mf < 2; mf++) {
                uint32_t sw = sw64((uint32_t)((wm * 32 + mf * 16 + lrow) * 64 + ks * 32 + lkb));
                ldsm4(ah[mf], buf + GS_A + sw);
            }
#pragma unroll
            for (int np = 0; np < 4; np++) {
                uint32_t sw = sw64((uint32_t)((wn * 64 + np * 16 + lrow) * 64 + ks * 32 + lkb));
                uint32_t bh[4];
                ldsm4(bh, buf + GS_B_HI + sw);
#pragma unroll
                for (int mf = 0; mf < 2; mf++) {
                    mma16816(acc[mf][np * 2],     ah[mf], bh[0], bh[2]);
                    mma16816(acc[mf][np * 2 + 1], ah[mf], bh[1], bh[3]);
                }
                if (twoterm) {
                    uint32_t bl[4];
                    ldsm4(bl, buf + GS_B_LO + sw);
#pragma unroll
                    for (int mf = 0; mf < 2; mf++) {
                        mma16816(acc[mf][np * 2],     ah[mf], bl[0], bl[2]);
                        mma16816(acc[mf][np * 2 + 1], ah[mf], bl[1], bl[3]);
                    }
                }
            }
        }
        __syncthreads();
        if (ch + 2 < NCHUNK) {
            gemm_load_stage(sbase + (uint32_t)(ch & 1) * GS_STAGE, ch + 2,
                            bm, bn, tid, twoterm, Ah, Bhi, Blo);
            CP_COMMIT();
        }
    }

    const int r0 = bm + wm * 32 + (lane >> 2);
    const int c0 = bn + wn * 64 + (lane & 3) * 2;
    if (mode == 0) {
#pragma unroll
        for (int nf = 0; nf < 8; nf++) {
            int col = c0 + nf * 8;
            int which = col >> 10;
            int hh = (col >> 6) & 15;
            int d = col & 63;
            float sc = (which == 0) ? 0.125f : 1.0f;
#pragma unroll
            for (int mf = 0; mf < 2; mf++) {
                int row = r0 + mf * 16;
                int t = row & (T_ - 1), b = row >> 11;
                size_t i1 = ((size_t)((b << 4) + hh) * T_ + t) * 64 + d;
                if (which == 2) {
                    // V: single fp16
                    *(uint32_t*)&g_vh[i1] = pack_h2(acc[mf][nf][0], acc[mf][nf][1]);
                    *(uint32_t*)&g_vh[i1 + 8 * 64] = pack_h2(acc[mf][nf][2], acc[mf][nf][3]);
                } else {
                    __half* dhi = (which == 0) ? g_qhi : g_khi;
                    __half* dlo = (which == 0) ? g_qlo : g_klo;
                    uint32_t h0, l0, h1, l1;
                    split2h(acc[mf][nf][0] * sc, acc[mf][nf][1] * sc, h0, l0);
                    split2h(acc[mf][nf][2] * sc, acc[mf][nf][3] * sc, h1, l1);
                    *(uint32_t*)&dhi[i1] = h0;
                    *(uint32_t*)&dlo[i1] = l0;
                    *(uint32_t*)&dhi[i1 + 8 * 64] = h1;
                    *(uint32_t*)&dlo[i1 + 8 * 64] = l1;
                }
            }
        }
    } else {
#pragma unroll
        for (int mf = 0; mf < 2; mf++) {
#pragma unroll
            for (int nf = 0; nf < 8; nf++) {
                int row = r0 + mf * 16;
                int col = c0 + nf * 8;
                float b0 = bias[col], b1 = bias[col + 1];
                *(float2*)&out[(size_t)row * N + col] =
                    make_float2(acc[mf][nf][0] + b0, acc[mf][nf][1] + b1);
                *(float2*)&out[(size_t)(row + 8) * N + col] =
                    make_float2(acc[mf][nf][2] + b0, acc[mf][nf][3] + b1);
            }
        }
    }
}

// ---------------------------------------------------------------------------
__global__ void conv_x(const float* __restrict__ src) {
    int i = blockIdx.x * 256 + threadIdx.x;
    if (i < M_ * C_) g_xh[i] = __float2half(src[i]);
}
__global__ void conv_split_t(const float* __restrict__ src, int mode, int K, int N) {
    __shared__ float s[32][33];
    __half* hi = (mode == 0) ? g_wqkvThi : g_woutThi;
    __half* lo = (mode == 0) ? g_wqkvTlo : g_woutTlo;
    int n0 = blockIdx.x * 32, k0 = blockIdx.y * 32;
    int tx = threadIdx.x, ty = threadIdx.y;
#pragma unroll
    for (int yy = 0; yy < 32; yy += 8)
        s[ty + yy][tx] = src[(size_t)(k0 + ty + yy) * N + n0 + tx];
    __syncthreads();
#pragma unroll
    for (int yy = 0; yy < 32; yy += 8) {
        float v = s[tx][ty + yy];
        __half h = __float2half(v);
        size_t o = (size_t)(n0 + ty + yy) * K + k0 + tx;
        hi[o] = h;
        lo[o] = __float2half(v - __half2float(h));
    }
}

// ---------------------------------------------------------------------------
// fp16 flash attention: S 3-term (q pair x k pair), PV 1-term (fp16 P x fp16 V)
// Block 256 thr (8 warps), q-tile 128 rows, k-tiles of 64, double-buffered.
// smem: stage0 @0 (24K: kh|kl|vh), stage1 @24K, Q hi @48K, Q lo @64K -> 80K.
// Heavy q-tiles scheduled first (qt reversed vs blockIdx).
// ---------------------------------------------------------------------------
#define FLS_KH 0
#define FLS_KL 8192
#define FLS_VH 16384
#define FLS_STAGE 24576
#define FLS_QH 49152
#define FLS_QL 65536
#define FL_SMEM 81920

__device__ __forceinline__ void fl_load_tile(uint32_t dst, size_t gbase, int kt, int tid) {
    const __half* kh = g_khi + gbase + (size_t)kt * 64 * 64;
    const __half* kl = g_klo + gbase + (size_t)kt * 64 * 64;
    const __half* vh = g_vh  + gbase + (size_t)kt * 64 * 64;
#pragma unroll
    for (int i = tid; i < 512; i += 256) {
        int r = i >> 3, g = i & 7;
        uint32_t sw = sw128((uint32_t)(r * 128 + g * 16));
        size_t go = (size_t)r * 64 + g * 8;
        CP16(dst + FLS_KH + sw, kh + go);
        CP16(dst + FLS_KL + sw, kl + go);
        CP16(dst + FLS_VH + sw, vh + go);
    }
}

__global__ __launch_bounds__(256, 2) void hmma_flash() {
    extern __shared__ char smem[];
    const uint32_t sbase = smem_u32_of(smem);
    const int tid = threadIdx.x, w = tid >> 5, lane = tid & 31;
    const int qt = gridDim.x - 1 - blockIdx.x;   // heavy tiles first
    const int bh = blockIdx.y;
    const int nkt = 2 * (qt + 1);
    const size_t gbase = (size_t)bh * T_ * 64;
    const int lrow = lane & 15, lkb = (lane >> 4) << 4;

    {
        const __half* qh = g_qhi + gbase + (size_t)qt * 128 * 64;
        const __half* ql = g_qlo + gbase + (size_t)qt * 128 * 64;
#pragma unroll
        for (int i = tid; i < 1024; i += 256) {
            int r = i >> 3, g = i & 7;
            uint32_t sw = sw128((uint32_t)(r * 128 + g * 16));
            size_t go = (size_t)r * 64 + g * 8;
            CP16(sbase + FLS_QH + sw, qh + go);
            CP16(sbase + FLS_QL + sw, ql + go);
        }
        CP_COMMIT();
    }
    fl_load_tile(sbase, gbase, 0, tid);
    CP_COMMIT();
    CP_WAIT1();
    __syncthreads();

    uint32_t qfh[4][4], qfl[4][4];
#pragma unroll
    for (int ks = 0; ks < 4; ks++) {
        uint32_t sw = sw128((uint32_t)((w * 16 + lrow) * 128 + ks * 32 + lkb));
        ldsm4(qfh[ks], sbase + FLS_QH + sw);
        ldsm4(qfl[ks], sbase + FLS_QL + sw);
    }

    float o[8][4];
#pragma unroll
    for (int j = 0; j < 8; j++)
#pragma unroll
        for (int k = 0; k < 4; k++) o[j][k] = 0.0f;
    float m1 = -1e30f, m2 = -1e30f, l1 = 0.0f, l2 = 0.0f;

    for (int kt = 0; kt < nkt; kt++) {
        const uint32_t buf = sbase + (uint32_t)(kt & 1) * FLS_STAGE;
        if (kt + 1 < nkt) {
            fl_load_tile(sbase + (uint32_t)((kt + 1) & 1) * FLS_STAGE, gbase, kt + 1, tid);
            CP_COMMIT();
            CP_WAIT1();
        } else {
            CP_WAIT0();
        }
        __syncthreads();

        // ---- S = (Q/8) K^T : 3-term fp16
        float s[8][4];
#pragma unroll
        for (int j = 0; j < 8; j++)
#pragma unroll
            for (int k = 0; k < 4; k++) s[j][k] = 0.0f;
#pragma unroll
        for (int kn = 0; kn < 4; kn++) {
#pragma unroll
            for (int ks = 0; ks < 4; ks++) {
                uint32_t sw = sw128((uint32_t)((kn * 16 + lrow) * 128 + ks * 32 + lkb));
                uint32_t kh4[4], kl4[4];
                ldsm4(kh4, buf + FLS_KH + sw);
                ldsm4(kl4, buf + FLS_KL + sw);
                mma16816(s[kn * 2],     qfh[ks], kh4[0], kh4[2]);
                mma16816(s[kn * 2 + 1], qfh[ks], kh4[1], kh4[3]);
                mma16816(s[kn * 2],     qfh[ks], kl4[0], kl4[2]);
                mma16816(s[kn * 2 + 1], qfh[ks], kl4[1], kl4[3]);
                mma16816(s[kn * 2],     qfl[ks], kh4[0], kh4[2]);
                mma16816(s[kn * 2 + 1], qfl[ks], kh4[1], kh4[3]);
            }
        }

        const int gr1 = qt * 128 + w * 16 + (lane >> 2);
        if (kt * 64 + 63 > qt * 128 + w * 16) {
#pragma unroll
            for (int j = 0; j < 8; j++) {
                int c = kt * 64 + j * 8 + (lane & 3) * 2;
                if (c     > gr1)     s[j][0] = -1e30f;
                if (c + 1 > gr1)     s[j][1] = -1e30f;
                if (c     > gr1 + 8) s[j][2] = -1e30f;
                if (c + 1 > gr1 + 8) s[j][3] = -1e30f;
            }
        }

        float mx1 = -1e30f, mx2 = -1e30f;
#pragma unroll
        for (int j = 0; j < 8; j++) {
            mx1 = fmaxf(mx1, fmaxf(s[j][0], s[j][1]));
            mx2 = fmaxf(mx2, fmaxf(s[j][2], s[j][3]));
        }
        mx1 = fmaxf(mx1, __shfl_xor_sync(0xffffffffu, mx1, 1));
        mx1 = fmaxf(mx1, __shfl_xor_sync(0xffffffffu, mx1, 2));
        mx2 = fmaxf(mx2, __shfl_xor_sync(0xffffffffu, mx2, 1));
        mx2 = fmaxf(mx2, __shfl_xor_sync(0xffffffffu, mx2, 2));
        float nm1 = fmaxf(m1, mx1), nm2 = fmaxf(m2, mx2);
        float a1 = fexp(m1 - nm1), a2 = fexp(m2 - nm2);
        m1 = nm1; m2 = nm2;
        float rs1 = 0.0f, rs2 = 0.0f;
#pragma unroll
        for (int j = 0; j < 8; j++) {
            s[j][0] = fexp(s[j][0] - nm1);
            s[j][1] = fexp(s[j][1] - nm1);
            s[j][2] = fexp(s[j][2] - nm2);
            s[j][3] = fexp(s[j][3] - nm2);
            rs1 += s[j][0] + s[j][1];
            rs2 += s[j][2] + s[j][3];
        }
        rs1 += __shfl_xor_sync(0xffffffffu, rs1, 1);
        rs1 += __shfl_xor_sync(0xffffffffu, rs1, 2);
        rs2 += __shfl_xor_sync(0xffffffffu, rs2, 1);
        rs2 += __shfl_xor_sync(0xffffffffu, rs2, 2);
        l1 = l1 * a1 + rs1;
        l2 = l2 * a2 + rs2;
#pragma unroll
        for (int j = 0; j < 8; j++) {
            o[j][0] *= a1; o[j][1] *= a1;
            o[j][2] *= a2; o[j][3] *= a2;
        }

        // ---- O += P V : single-term fp16
        const int lg = lane >> 3, lr8 = lane & 7;
#pragma unroll
        for (int kn = 0; kn < 4; kn++) {
            uint32_t ph[4];
            ph[0] = pack_h2(s[2 * kn][0],     s[2 * kn][1]);
            ph[1] = pack_h2(s[2 * kn][2],     s[2 * kn][3]);
            ph[2] = pack_h2(s[2 * kn + 1][0], s[2 * kn + 1][1]);
            ph[3] = pack_h2(s[2 * kn + 1][2], s[2 * kn + 1][3]);
#pragma unroll
            for (int nd = 0; nd < 4; nd++) {
                int key = kn * 16 + lr8 + (lg >> 1) * 8;
                int dim = nd * 16 + (lg & 1) * 8;
                uint32_t sw = sw128((uint32_t)(key * 128 + dim * 2));
                uint32_t vh4[4];
                ldsm4t(vh4, buf + FLS_VH + sw);
                mma16816(o[nd * 2],     ph, vh4[0], vh4[2]);
                mma16816(o[nd * 2 + 1], ph, vh4[1], vh4[3]);
            }
        }
        __syncthreads();
    }

    const int b = bh >> 4, hh = bh & 15;
    const int t1 = qt * 128 + w * 16 + (lane >> 2);
    const float inv1 = 1.0f / l1, inv2 = 1.0f / l2;
#pragma unroll
    for (int j = 0; j < 8; j++) {
        int d = j * 8 + (lane & 3) * 2;
        size_t i1 = ((size_t)(b * T_ + t1)) * C_ + hh * 64 + d;
        size_t i2 = i1 + (size_t)8 * C_;
        *(uint32_t*)&g_attnh[i1] = pack_h2(o[j][0] * inv1, o[j][1] * inv1);
        *(uint32_t*)&g_attnh[i2] = pack_h2(o[j][2] * inv2, o[j][3] * inv2);
    }
}

// ---------------------------------------------------------------------------
extern "C" void kernel_launch(void* const* d_in, const int* in_sizes, int n_in,
                              void* d_out, int out_size) {
    const float* x    = (const float*)d_in[0];
    const float* Wqkv = (const float*)d_in[1];
    const float* Wout = (const float*)d_in[2];
    const float* bout = (const float*)d_in[3];
    float* out = (float*)d_out;

    conv_x<<<(M_ * C_ + 255) / 256, 256>>>(x);
    conv_split_t<<<dim3(NQKV_ / 32, C_ / 32), dim3(32, 8)>>>(Wqkv, 0, C_, NQKV_);
    conv_split_t<<<dim3(C_ / 32, C_ / 32), dim3(32, 8)>>>(Wout, 1, C_, C_);

    cudaFuncSetAttribute(hmma_gemm, cudaFuncAttributeMaxDynamicSharedMemorySize, GEMM_SMEM);
    hmma_gemm<<<dim3(NQKV_ / 128, M_ / 128), 256, GEMM_SMEM>>>(0, nullptr, nullptr, NQKV_);

    cudaFuncSetAttribute(hmma_flash, cudaFuncAttributeMaxDynamicSharedMemorySize, FL_SMEM);
    hmma_flash<<<dim3(T_ / 128, B_ * H_), 256, FL_SMEM>>>();

    hmma_gemm<<<dim3(C_ / 128, M_ / 128), 256, GEMM_SMEM>>>(1, out, bout, C_);
}

// round 8
// speedup vs baseline: 4.8867x; 1.0748x over previous
#include <cuda_runtime.h>
#include <cuda_fp16.h>
#include <cstdint>

#define B_  2
#define T_  2048
#define C_  1024
#define H_  16
#define M_  (B_*T_)      // 4096
#define NQKV_ (3*C_)     // 3072

// ---------------- device scratch (no allocation allowed) -------------------
__device__ __half g_xh[M_*C_];                       // x as single fp16
__device__ __half g_wqkvThi[NQKV_*C_], g_wqkvTlo[NQKV_*C_];
__device__ __half g_woutThi[C_*C_],    g_woutTlo[C_*C_];
__device__ __half g_attnh[M_*C_];                    // attn out single fp16
// [b,h,t,d]: q single fp16 (pre-scaled 1/8), k fp16 hi/lo, v single fp16
__device__ __half g_qh[M_*C_];
__device__ __half g_khi[M_*C_], g_klo[M_*C_];
__device__ __half g_vh[M_*C_];

// ---------------- helpers ----------------------------------------------------
__device__ __forceinline__ uint32_t smem_u32_of(const void* p) {
    uint32_t a;
    asm("{ .reg .u64 t; cvta.to.shared.u64 t, %1; cvt.u32.u64 %0, t; }" : "=r"(a) : "l"(p));
    return a;
}
__device__ __forceinline__ void ldsm4(uint32_t* r, uint32_t addr) {
    asm volatile("ldmatrix.sync.aligned.m8n8.x4.shared.b16 {%0,%1,%2,%3}, [%4];"
                 : "=r"(r[0]), "=r"(r[1]), "=r"(r[2]), "=r"(r[3]) : "r"(addr));
}
__device__ __forceinline__ void ldsm4t(uint32_t* r, uint32_t addr) {
    asm volatile("ldmatrix.sync.aligned.m8n8.x4.trans.shared.b16 {%0,%1,%2,%3}, [%4];"
                 : "=r"(r[0]), "=r"(r[1]), "=r"(r[2]), "=r"(r[3]) : "r"(addr));
}
__device__ __forceinline__ void mma16816(float* c, const uint32_t* a,
                                         uint32_t b0, uint32_t b1) {
    asm volatile(
        "mma.sync.aligned.m16n8k16.row.col.f32.f16.f16.f32 "
        "{%0,%1,%2,%3}, {%4,%5,%6,%7}, {%8,%9}, {%0,%1,%2,%3};"
        : "+f"(c[0]), "+f"(c[1]), "+f"(c[2]), "+f"(c[3])
        : "r"(a[0]), "r"(a[1]), "r"(a[2]), "r"(a[3]), "r"(b0), "r"(b1));
}
#define CP16(dst, src) \
    asm volatile("cp.async.cg.shared.global [%0], [%1], 16;" :: "r"(dst), "l"(src) : "memory")
#define CP_COMMIT() asm volatile("cp.async.commit_group;" ::: "memory")
#define CP_WAIT1()  asm volatile("cp.async.wait_group 1;" ::: "memory")
#define CP_WAIT0()  asm volatile("cp.async.wait_group 0;" ::: "memory")

__device__ __forceinline__ uint32_t sw128(uint32_t off) {
    return off ^ ((off >> 3) & 0x70);
}
__device__ __forceinline__ uint32_t sw64(uint32_t off) {
    return off ^ ((off >> 3) & 0x30);
}
__device__ __forceinline__ uint32_t pack_h2(float v0, float v1) {
    __half2 hp = __floats2half2_rn(v0, v1);
    return *(uint32_t*)&hp;
}
__device__ __forceinline__ void split2h(float v0, float v1, uint32_t& hi, uint32_t& lo) {
    __half2 hp = __floats2half2_rn(v0, v1);
    hi = *(uint32_t*)&hp;
    float h0 = __half2float(__low2half(hp));
    float h1 = __half2float(__high2half(hp));
    lo = pack_h2(v0 - h0, v1 - h1);
}
__device__ __forceinline__ float fexp(float x) {
    x = fmaxf(x, -87.0f);
    float y = fmaf(x, 1.4426950408889634f, 12582912.0f);
    int   n = __float_as_int(y) - 0x4B400000;
    float nf = y - 12582912.0f;
    float f = fmaf(x, 1.4426950408889634f, -nf);
    float p = fmaf(1.54035304e-4f, f, 1.33335581e-3f);
    p = fmaf(p, f, 9.61812911e-3f);
    p = fmaf(p, f, 5.55041087e-2f);
    p = fmaf(p, f, 2.40226507e-1f);
    p = fmaf(p, f, 6.93147181e-1f);
    p = fmaf(p, f, 1.0f);
    return __int_as_float((n + 127) << 23) * p;
}

// ---------------------------------------------------------------------------
// fp16 HMMA GEMM: D = A_fp16 * (B_hi [+ B_lo]).
// mode 0: K-output CTAs (C<=bn<2C) 2-term; Q/V-output CTAs 1-term.
// mode 1: always 2-term.
// CTA 128x128, 8 warps (4x2), warp tile 32x64, K-chunk 32 (SW64).
// ---------------------------------------------------------------------------
#define GS_A    0
#define GS_B_HI 8192
#define GS_B_LO 16384
#define GS_STAGE 24576
#define GEMM_SMEM 49152
#define NCHUNK 32

__device__ __forceinline__ void gemm_load_stage(
    uint32_t dst, int ch, int bm, int bn, int tid, bool loadBlo,
    const __half* Ah, const __half* Bhi, const __half* Blo) {
    const int k0 = ch * 32;
#pragma unroll
    for (int i = tid; i < 512; i += 256) {
        int r = i >> 2, g = i & 3;
        uint32_t sw = sw64((uint32_t)(r * 64 + g * 16));
        size_t ga = (size_t)(bm + r) * C_ + k0 + g * 8;
        CP16(dst + GS_A + sw, Ah + ga);
        size_t gb = (size_t)(bn + r) * C_ + k0 + g * 8;
        CP16(dst + GS_B_HI + sw, Bhi + gb);
        if (loadBlo) CP16(dst + GS_B_LO + sw, Blo + gb);
    }
}

__global__ __launch_bounds__(256, 2) void hmma_gemm(int mode, float* __restrict__ out,
                                                    const float* __restrict__ bias, int N) {
    extern __shared__ char smem[];
    const uint32_t sbase = smem_u32_of(smem);
    const int tid = threadIdx.x, wid = tid >> 5, lane = tid & 31;
    const int bm = blockIdx.y * 128, bn = blockIdx.x * 128;
    const int wm = wid & 3, wn = wid >> 2;

    const __half* Ah  = (mode == 0) ? g_xh : g_attnh;
    const __half* Bhi = (mode == 0) ? g_wqkvThi : g_woutThi;
    const __half* Blo = (mode == 0) ? g_wqkvTlo : g_woutTlo;
    // mode 0: only K columns (C..2C) need the lo compensation term
    const bool twoterm = (mode == 1) || (bn >= C_ && bn < 2 * C_);

    float acc[2][8][4];
#pragma unroll
    for (int i = 0; i < 2; i++)
#pragma unroll
        for (int j = 0; j < 8; j++)
#pragma unroll
            for (int k = 0; k < 4; k++) acc[i][j][k] = 0.0f;

    const int lrow = lane & 15;
    const int lkb  = (lane >> 4) << 4;

    gemm_load_stage(sbase, 0, bm, bn, tid, twoterm, Ah, Bhi, Blo);
    CP_COMMIT();
    gemm_load_stage(sbase + GS_STAGE, 1, bm, bn, tid, twoterm, Ah, Bhi, Blo);
    CP_COMMIT();

    for (int ch = 0; ch < NCHUNK; ch++) {
        if (ch < NCHUNK - 1) { CP_WAIT1(); } else { CP_WAIT0(); }
        __syncthreads();
        const uint32_t buf = sbase + (uint32_t)(ch & 1) * GS_STAGE;

#pragma unroll
        for (int ks = 0; ks < 2; ks++) {
            uint32_t ah[2][4];
#pragma unroll
            for (int mf = 0; mf < 2; mf++) {
                uint32_t sw = sw64((uint32_t)((wm * 32 + mf * 16 + lrow) * 64 + ks * 32 + lkb));
                ldsm4(ah[mf], buf + GS_A + sw);
            }
#pragma unroll
            for (int np = 0; np < 4; np++) {
                uint32_t sw = sw64((uint32_t)((wn * 64 + np * 16 + lrow) * 64 + ks * 32 + lkb));
                uint32_t bh[4];
                ldsm4(bh, buf + GS_B_HI + sw);
#pragma unroll
                for (int mf = 0; mf < 2; mf++) {
                    mma16816(acc[mf][np * 2],     ah[mf], bh[0], bh[2]);
                    mma16816(acc[mf][np * 2 + 1], ah[mf], bh[1], bh[3]);
                }
                if (twoterm) {
                    uint32_t bl[4];
                    ldsm4(bl, buf + GS_B_LO + sw);
#pragma unroll
                    for (int mf = 0; mf < 2; mf++) {
                        mma16816(acc[mf][np * 2],     ah[mf], bl[0], bl[2]);
                        mma16816(acc[mf][np * 2 + 1], ah[mf], bl[1], bl[3]);
                    }
                }
            }
        }
        __syncthreads();
        if (ch + 2 < NCHUNK) {
            gemm_load_stage(sbase + (uint32_t)(ch & 1) * GS_STAGE, ch + 2,
                            bm, bn, tid, twoterm, Ah, Bhi, Blo);
            CP_COMMIT();
        }
    }

    const int r0 = bm + wm * 32 + (lane >> 2);
    const int c0 = bn + wn * 64 + (lane & 3) * 2;
    if (mode == 0) {
#pragma unroll
        for (int nf = 0; nf < 8; nf++) {
            int col = c0 + nf * 8;
            int which = col >> 10;
            int hh = (col >> 6) & 15;
            int d = col & 63;
#pragma unroll
            for (int mf = 0; mf < 2; mf++) {
                int row = r0 + mf * 16;
                int t = row & (T_ - 1), b = row >> 11;
                size_t i1 = ((size_t)((b << 4) + hh) * T_ + t) * 64 + d;
                if (which == 1) {
                    // K: fp16 hi/lo pair
                    uint32_t h0, l0, h1, l1;
                    split2h(acc[mf][nf][0], acc[mf][nf][1], h0, l0);
                    split2h(acc[mf][nf][2], acc[mf][nf][3], h1, l1);
                    *(uint32_t*)&g_khi[i1] = h0;
                    *(uint32_t*)&g_klo[i1] = l0;
                    *(uint32_t*)&g_khi[i1 + 8 * 64] = h1;
                    *(uint32_t*)&g_klo[i1 + 8 * 64] = l1;
                } else {
                    // Q (scaled 1/8) or V: single fp16
                    float sc = (which == 0) ? 0.125f : 1.0f;
                    __half* dst = (which == 0) ? g_qh : g_vh;
                    *(uint32_t*)&dst[i1] = pack_h2(acc[mf][nf][0] * sc, acc[mf][nf][1] * sc);
                    *(uint32_t*)&dst[i1 + 8 * 64] = pack_h2(acc[mf][nf][2] * sc, acc[mf][nf][3] * sc);
                }
            }
        }
    } else {
#pragma unroll
        for (int mf = 0; mf < 2; mf++) {
#pragma unroll
            for (int nf = 0; nf < 8; nf++) {
                int row = r0 + mf * 16;
                int col = c0 + nf * 8;
                float b0 = bias[col], b1 = bias[col + 1];
                *(float2*)&out[(size_t)row * N + col] =
                    make_float2(acc[mf][nf][0] + b0, acc[mf][nf][1] + b1);
                *(float2*)&out[(size_t)(row + 8) * N + col] =
                    make_float2(acc[mf][nf][2] + b0, acc[mf][nf][3] + b1);
            }
        }
    }
}

// ---------------------------------------------------------------------------
__global__ void conv_x(const float* __restrict__ src) {
    int i = blockIdx.x * 256 + threadIdx.x;
    if (i < M_ * C_) g_xh[i] = __float2half(src[i]);
}
__global__ void conv_split_t(const float* __restrict__ src, int mode, int K, int N) {
    __shared__ float s[32][33];
    __half* hi = (mode == 0) ? g_wqkvThi : g_woutThi;
    __half* lo = (mode == 0) ? g_wqkvTlo : g_woutTlo;
    int n0 = blockIdx.x * 32, k0 = blockIdx.y * 32;
    int tx = threadIdx.x, ty = threadIdx.y;
#pragma unroll
    for (int yy = 0; yy < 32; yy += 8)
        s[ty + yy][tx] = src[(size_t)(k0 + ty + yy) * N + n0 + tx];
    __syncthreads();
#pragma unroll
    for (int yy = 0; yy < 32; yy += 8) {
        float v = s[tx][ty + yy];
        __half h = __float2half(v);
        size_t o = (size_t)(n0 + ty + yy) * K + k0 + tx;
        hi[o] = h;
        lo[o] = __float2half(v - __half2float(h));
    }
}

// ---------------------------------------------------------------------------
// fp16 flash attention: S 2-term (q single x k pair), PV 1-term.
// Block 256 thr (8 warps), q-tile 128 rows, k-tiles of 64, double-buffered.
// smem: stage0 @0 (24K: kh|kl|vh), stage1 @24K, Q @48K (16K) -> 64K.
// Heavy q-tiles scheduled first (qt reversed vs blockIdx).
// ---------------------------------------------------------------------------
#define FLS_KH 0
#define FLS_KL 8192
#define FLS_VH 16384
#define FLS_STAGE 24576
#define FLS_QH 49152
#define FL_SMEM 65536

__device__ __forceinline__ void fl_load_tile(uint32_t dst, size_t gbase, int kt, int tid) {
    const __half* kh = g_khi + gbase + (size_t)kt * 64 * 64;
    const __half* kl = g_klo + gbase + (size_t)kt * 64 * 64;
    const __half* vh = g_vh  + gbase + (size_t)kt * 64 * 64;
#pragma unroll
    for (int i = tid; i < 512; i += 256) {
        int r = i >> 3, g = i & 7;
        uint32_t sw = sw128((uint32_t)(r * 128 + g * 16));
        size_t go = (size_t)r * 64 + g * 8;
        CP16(dst + FLS_KH + sw, kh + go);
        CP16(dst + FLS_KL + sw, kl + go);
        CP16(dst + FLS_VH + sw, vh + go);
    }
}

__global__ __launch_bounds__(256, 2) void hmma_flash() {
    extern __shared__ char smem[];
    const uint32_t sbase = smem_u32_of(smem);
    const int tid = threadIdx.x, w = tid >> 5, lane = tid & 31;
    const int qt = gridDim.x - 1 - blockIdx.x;   // heavy tiles first
    const int bh = blockIdx.y;
    const int nkt = 2 * (qt + 1);
    const size_t gbase = (size_t)bh * T_ * 64;
    const int lrow = lane & 15, lkb = (lane >> 4) << 4;

    {
        const __half* qh = g_qh + gbase + (size_t)qt * 128 * 64;
#pragma unroll
        for (int i = tid; i < 1024; i += 256) {
            int r = i >> 3, g = i & 7;
            uint32_t sw = sw128((uint32_t)(r * 128 + g * 16));
            size_t go = (size_t)r * 64 + g * 8;
            CP16(sbase + FLS_QH + sw, qh + go);
        }
        CP_COMMIT();
    }
    fl_load_tile(sbase, gbase, 0, tid);
    CP_COMMIT();
    CP_WAIT1();
    __syncthreads();

    uint32_t qf[4][4];
#pragma unroll
    for (int ks = 0; ks < 4; ks++) {
        uint32_t sw = sw128((uint32_t)((w * 16 + lrow) * 128 + ks * 32 + lkb));
        ldsm4(qf[ks], sbase + FLS_QH + sw);
    }

    float o[8][4];
#pragma unroll
    for (int j = 0; j < 8; j++)
#pragma unroll
        for (int k = 0; k < 4; k++) o[j][k] = 0.0f;
    float m1 = -1e30f, m2 = -1e30f, l1 = 0.0f, l2 = 0.0f;

    for (int kt = 0; kt < nkt; kt++) {
        const uint32_t buf = sbase + (uint32_t)(kt & 1) * FLS_STAGE;
        if (kt + 1 < nkt) {
            fl_load_tile(sbase + (uint32_t)((kt + 1) & 1) * FLS_STAGE, gbase, kt + 1, tid);
            CP_COMMIT();
            CP_WAIT1();
        } else {
            CP_WAIT0();
        }
        __syncthreads();

        // ---- S = (Q/8) K^T : 2-term (q single, k hi/lo)
        float s[8][4];
#pragma unroll
        for (int j = 0; j < 8; j++)
#pragma unroll
            for (int k = 0; k < 4; k++) s[j][k] = 0.0f;
#pragma unroll
        for (int kn = 0; kn < 4; kn++) {
#pragma unroll
            for (int ks = 0; ks < 4; ks++) {
                uint32_t sw = sw128((uint32_t)((kn * 16 + lrow) * 128 + ks * 32 + lkb));
                uint32_t kh4[4], kl4[4];
                ldsm4(kh4, buf + FLS_KH + sw);
                ldsm4(kl4, buf + FLS_KL + sw);
                mma16816(s[kn * 2],     qf[ks], kh4[0], kh4[2]);
                mma16816(s[kn * 2 + 1], qf[ks], kh4[1], kh4[3]);
                mma16816(s[kn * 2],     qf[ks], kl4[0], kl4[2]);
                mma16816(s[kn * 2 + 1], qf[ks], kl4[1], kl4[3]);
            }
        }

        const int gr1 = qt * 128 + w * 16 + (lane >> 2);
        if (kt * 64 + 63 > qt * 128 + w * 16) {
#pragma unroll
            for (int j = 0; j < 8; j++) {
                int c = kt * 64 + j * 8 + (lane & 3) * 2;
                if (c     > gr1)     s[j][0] = -1e30f;
                if (c + 1 > gr1)     s[j][1] = -1e30f;
                if (c     > gr1 + 8) s[j][2] = -1e30f;
                if (c + 1 > gr1 + 8) s[j][3] = -1e30f;
            }
        }

        float mx1 = -1e30f, mx2 = -1e30f;
#pragma unroll
        for (int j = 0; j < 8; j++) {
            mx1 = fmaxf(mx1, fmaxf(s[j][0], s[j][1]));
            mx2 = fmaxf(mx2, fmaxf(s[j][2], s[j][3]));
        }
        mx1 = fmaxf(mx1, __shfl_xor_sync(0xffffffffu, mx1, 1));
        mx1 = fmaxf(mx1, __shfl_xor_sync(0xffffffffu, mx1, 2));
        mx2 = fmaxf(mx2, __shfl_xor_sync(0xffffffffu, mx2, 1));
        mx2 = fmaxf(mx2, __shfl_xor_sync(0xffffffffu, mx2, 2));
        float nm1 = fmaxf(m1, mx1), nm2 = fmaxf(m2, mx2);
        float a1 = fexp(m1 - nm1), a2 = fexp(m2 - nm2);
        m1 = nm1; m2 = nm2;
        float rs1 = 0.0f, rs2 = 0.0f;
#pragma unroll
        for (int j = 0; j < 8; j++) {
            s[j][0] = fexp(s[j][0] - nm1);
            s[j][1] = fexp(s[j][1] - nm1);
            s[j][2] = fexp(s[j][2] - nm2);
            s[j][3] = fexp(s[j][3] - nm2);
            rs1 += s[j][0] + s[j][1];
            rs2 += s[j][2] + s[j][3];
        }
        rs1 += __shfl_xor_sync(0xffffffffu, rs1, 1);
        rs1 += __shfl_xor_sync(0xffffffffu, rs1, 2);
        rs2 += __shfl_xor_sync(0xffffffffu, rs2, 1);
        rs2 += __shfl_xor_sync(0xffffffffu, rs2, 2);
        l1 = l1 * a1 + rs1;
        l2 = l2 * a2 + rs2;
#pragma unroll
        for (int j = 0; j < 8; j++) {
            o[j][0] *= a1; o[j][1] *= a1;
            o[j][2] *= a2; o[j][3] *= a2;
        }

        // ---- O += P V : single-term fp16
        const int lg = lane >> 3, lr8 = lane & 7;
#pragma unroll
        for (int kn = 0; kn < 4; kn++) {
            uint32_t ph[4];
            ph[0] = pack_h2(s[2 * kn][0],     s[2 * kn][1]);
            ph[1] = pack_h2(s[2 * kn][2],     s[2 * kn][3]);
            ph[2] = pack_h2(s[2 * kn + 1][0], s[2 * kn + 1][1]);
            ph[3] = pack_h2(s[2 * kn + 1][2], s[2 * kn + 1][3]);
#pragma unroll
            for (int nd = 0; nd < 4; nd++) {
                int key = kn * 16 + lr8 + (lg >> 1) * 8;
                int dim = nd * 16 + (lg & 1) * 8;
                uint32_t sw = sw128((uint32_t)(key * 128 + dim * 2));
                uint32_t vh4[4];
                ldsm4t(vh4, buf + FLS_VH + sw);
                mma16816(o[nd * 2],     ph, vh4[0], vh4[2]);
                mma16816(o[nd * 2 + 1], ph, vh4[1], vh4[3]);
            }
        }
        __syncthreads();
    }

    const int b = bh >> 4, hh = bh & 15;
    const int t1 = qt * 128 + w * 16 + (lane >> 2);
    const float inv1 = 1.0f / l1, inv2 = 1.0f / l2;
#pragma unroll
    for (int j = 0; j < 8; j++) {
        int d = j * 8 + (lane & 3) * 2;
        size_t i1 = ((size_t)(b * T_ + t1)) * C_ + hh * 64 + d;
        size_t i2 = i1 + (size_t)8 * C_;
        *(uint32_t*)&g_attnh[i1] = pack_h2(o[j][0] * inv1, o[j][1] * inv1);
        *(uint32_t*)&g_attnh[i2] = pack_h2(o[j][2] * inv2, o[j][3] * inv2);
    }
}

// ---------------------------------------------------------------------------
extern "C" void kernel_launch(void* const* d_in, const int* in_sizes, int n_in,
                              void* d_out, int out_size) {
    const float* x    = (const float*)d_in[0];
    const float* Wqkv = (const float*)d_in[1];
    const float* Wout = (const float*)d_in[2];
    const float* bout = (const float*)d_in[3];
    float* out = (float*)d_out;

    conv_x<<<(M_ * C_ + 255) / 256, 256>>>(x);
    conv_split_t<<<dim3(NQKV_ / 32, C_ / 32), dim3(32, 8)>>>(Wqkv, 0, C_, NQKV_);
    conv_split_t<<<dim3(C_ / 32, C_ / 32), dim3(32, 8)>>>(Wout, 1, C_, C_);

    cudaFuncSetAttribute(hmma_gemm, cudaFuncAttributeMaxDynamicSharedMemorySize, GEMM_SMEM);
    hmma_gemm<<<dim3(NQKV_ / 128, M_ / 128), 256, GEMM_SMEM>>>(0, nullptr, nullptr, NQKV_);

    cudaFuncSetAttribute(hmma_flash, cudaFuncAttributeMaxDynamicSharedMemorySize, FL_SMEM);
    hmma_flash<<<dim3(T_ / 128, B_ * H_), 256, FL_SMEM>>>();

    hmma_gemm<<<dim3(C_ / 128, M_ / 128), 256, GEMM_SMEM>>>(1, out, bout, C_);
}

// round 9
// speedup vs baseline: 5.8486x; 1.1968x over previous
#include <cuda_runtime.h>
#include <cuda_fp16.h>
#include <cstdint>

#define B_  2
#define T_  2048
#define C_  1024
#define H_  16
#define M_  (B_*T_)      // 4096
#define NQKV_ (3*C_)     // 3072

// ---------------- device scratch (no allocation allowed) -------------------
__device__ __half g_xh[M_*C_];                       // x as single fp16
__device__ __half g_wqkvTh[NQKV_*C_];                // Wqkv^T single fp16
__device__ __half g_woutThi[C_*C_], g_woutTlo[C_*C_];
__device__ __half g_attnh[M_*C_];                    // attn out single fp16
// [b,h,t,d]: q (pre-scaled 1/8), k, v — all single fp16
__device__ __half g_qh[M_*C_], g_kh[M_*C_], g_vh[M_*C_];

// ---------------- helpers ----------------------------------------------------
__device__ __forceinline__ uint32_t smem_u32_of(const void* p) {
    uint32_t a;
    asm("{ .reg .u64 t; cvta.to.shared.u64 t, %1; cvt.u32.u64 %0, t; }" : "=r"(a) : "l"(p));
    return a;
}
__device__ __forceinline__ void ldsm4(uint32_t* r, uint32_t addr) {
    asm volatile("ldmatrix.sync.aligned.m8n8.x4.shared.b16 {%0,%1,%2,%3}, [%4];"
                 : "=r"(r[0]), "=r"(r[1]), "=r"(r[2]), "=r"(r[3]) : "r"(addr));
}
__device__ __forceinline__ void ldsm4t(uint32_t* r, uint32_t addr) {
    asm volatile("ldmatrix.sync.aligned.m8n8.x4.trans.shared.b16 {%0,%1,%2,%3}, [%4];"
                 : "=r"(r[0]), "=r"(r[1]), "=r"(r[2]), "=r"(r[3]) : "r"(addr));
}
__device__ __forceinline__ void mma16816(float* c, const uint32_t* a,
                                         uint32_t b0, uint32_t b1) {
    asm volatile(
        "mma.sync.aligned.m16n8k16.row.col.f32.f16.f16.f32 "
        "{%0,%1,%2,%3}, {%4,%5,%6,%7}, {%8,%9}, {%0,%1,%2,%3};"
        : "+f"(c[0]), "+f"(c[1]), "+f"(c[2]), "+f"(c[3])
        : "r"(a[0]), "r"(a[1]), "r"(a[2]), "r"(a[3]), "r"(b0), "r"(b1));
}
#define CP16(dst, src) \
    asm volatile("cp.async.cg.shared.global [%0], [%1], 16;" :: "r"(dst), "l"(src) : "memory")
#define CP_COMMIT() asm volatile("cp.async.commit_group;" ::: "memory")
#define CP_WAIT1()  asm volatile("cp.async.wait_group 1;" ::: "memory")
#define CP_WAIT0()  asm volatile("cp.async.wait_group 0;" ::: "memory")

__device__ __forceinline__ uint32_t sw128(uint32_t off) {
    return off ^ ((off >> 3) & 0x70);
}
__device__ __forceinline__ uint32_t sw64(uint32_t off) {
    return off ^ ((off >> 3) & 0x30);
}
__device__ __forceinline__ uint32_t pack_h2(float v0, float v1) {
    __half2 hp = __floats2half2_rn(v0, v1);
    return *(uint32_t*)&hp;
}
__device__ __forceinline__ void split2h(float v0, float v1, uint32_t& hi, uint32_t& lo) {
    __half2 hp = __floats2half2_rn(v0, v1);
    hi = *(uint32_t*)&hp;
    float h0 = __half2float(__low2half(hp));
    float h1 = __half2float(__high2half(hp));
    lo = pack_h2(v0 - h0, v1 - h1);
}

// ---------------------------------------------------------------------------
// fp16 HMMA GEMM: D = A_fp16 * (B_hi [+ B_lo]).
// mode 0 (qkv): 1-term everywhere.  mode 1 (proj): 2-term.
// CTA 128x128, 8 warps (4x2), warp tile 32x64, K-chunk 32 (SW64).
// ---------------------------------------------------------------------------
#define GS_A    0
#define GS_B_HI 8192
#define GS_B_LO 16384
#define GS_STAGE 24576
#define GEMM_SMEM 49152
#define NCHUNK 32

__device__ __forceinline__ void gemm_load_stage(
    uint32_t dst, int ch, int bm, int bn, int tid, bool loadBlo,
    const __half* Ah, const __half* Bhi, const __half* Blo) {
    const int k0 = ch * 32;
#pragma unroll
    for (int i = tid; i < 512; i += 256) {
        int r = i >> 2, g = i & 3;
        uint32_t sw = sw64((uint32_t)(r * 64 + g * 16));
        size_t ga = (size_t)(bm + r) * C_ + k0 + g * 8;
        CP16(dst + GS_A + sw, Ah + ga);
        size_t gb = (size_t)(bn + r) * C_ + k0 + g * 8;
        CP16(dst + GS_B_HI + sw, Bhi + gb);
        if (loadBlo) CP16(dst + GS_B_LO + sw, Blo + gb);
    }
}

__global__ __launch_bounds__(256, 2) void hmma_gemm(int mode, float* __restrict__ out,
                                                    const float* __restrict__ bias, int N) {
    extern __shared__ char smem[];
    const uint32_t sbase = smem_u32_of(smem);
    const int tid = threadIdx.x, wid = tid >> 5, lane = tid & 31;
    const int bm = blockIdx.y * 128, bn = blockIdx.x * 128;
    const int wm = wid & 3, wn = wid >> 2;

    const __half* Ah  = (mode == 0) ? g_xh : g_attnh;
    const __half* Bhi = (mode == 0) ? g_wqkvTh : g_woutThi;
    const __half* Blo = (mode == 0) ? g_wqkvTh : g_woutTlo;  // unused in mode 0
    const bool twoterm = (mode == 1);

    float acc[2][8][4];
#pragma unroll
    for (int i = 0; i < 2; i++)
#pragma unroll
        for (int j = 0; j < 8; j++)
#pragma unroll
            for (int k = 0; k < 4; k++) acc[i][j][k] = 0.0f;

    const int lrow = lane & 15;
    const int lkb  = (lane >> 4) << 4;

    gemm_load_stage(sbase, 0, bm, bn, tid, twoterm, Ah, Bhi, Blo);
    CP_COMMIT();
    gemm_load_stage(sbase + GS_STAGE, 1, bm, bn, tid, twoterm, Ah, Bhi, Blo);
    CP_COMMIT();

    for (int ch = 0; ch < NCHUNK; ch++) {
        if (ch < NCHUNK - 1) { CP_WAIT1(); } else { CP_WAIT0(); }
        __syncthreads();
        const uint32_t buf = sbase + (uint32_t)(ch & 1) * GS_STAGE;

#pragma unroll
        for (int ks = 0; ks < 2; ks++) {
            uint32_t ah[2][4];
#pragma unroll
            for (int mf = 0; mf < 2; mf++) {
                uint32_t sw = sw64((uint32_t)((wm * 32 + mf * 16 + lrow) * 64 + ks * 32 + lkb));
                ldsm4(ah[mf], buf + GS_A + sw);
            }
#pragma unroll
            for (int np = 0; np < 4; np++) {
                uint32_t sw = sw64((uint32_t)((wn * 64 + np * 16 + lrow) * 64 + ks * 32 + lkb));
                uint32_t bh[4];
                ldsm4(bh, buf + GS_B_HI + sw);
#pragma unroll
                for (int mf = 0; mf < 2; mf++) {
                    mma16816(acc[mf][np * 2],     ah[mf], bh[0], bh[2]);
                    mma16816(acc[mf][np * 2 + 1], ah[mf], bh[1], bh[3]);
                }
                if (twoterm) {
                    uint32_t bl[4];
                    ldsm4(bl, buf + GS_B_LO + sw);
#pragma unroll
                    for (int mf = 0; mf < 2; mf++) {
                        mma16816(acc[mf][np * 2],     ah[mf], bl[0], bl[2]);
                        mma16816(acc[mf][np * 2 + 1], ah[mf], bl[1], bl[3]);
                    }
                }
            }
        }
        __syncthreads();
        if (ch + 2 < NCHUNK) {
            gemm_load_stage(sbase + (uint32_t)(ch & 1) * GS_STAGE, ch + 2,
                            bm, bn, tid, twoterm, Ah, Bhi, Blo);
            CP_COMMIT();
        }
    }

    const int r0 = bm + wm * 32 + (lane >> 2);
    const int c0 = bn + wn * 64 + (lane & 3) * 2;
    if (mode == 0) {
#pragma unroll
        for (int nf = 0; nf < 8; nf++) {
            int col = c0 + nf * 8;
            int which = col >> 10;
            int hh = (col >> 6) & 15;
            int d = col & 63;
            float sc = (which == 0) ? 0.125f : 1.0f;
            __half* dst = (which == 0) ? g_qh : (which == 1) ? g_kh : g_vh;
#pragma unroll
            for (int mf = 0; mf < 2; mf++) {
                int row = r0 + mf * 16;
                int t = row & (T_ - 1), b = row >> 11;
                size_t i1 = ((size_t)((b << 4) + hh) * T_ + t) * 64 + d;
                *(uint32_t*)&dst[i1] = pack_h2(acc[mf][nf][0] * sc, acc[mf][nf][1] * sc);
                *(uint32_t*)&dst[i1 + 8 * 64] = pack_h2(acc[mf][nf][2] * sc, acc[mf][nf][3] * sc);
            }
        }
    } else {
#pragma unroll
        for (int mf = 0; mf < 2; mf++) {
#pragma unroll
            for (int nf = 0; nf < 8; nf++) {
                int row = r0 + mf * 16;
                int col = c0 + nf * 8;
                float b0 = bias[col], b1 = bias[col + 1];
                *(float2*)&out[(size_t)row * N + col] =
                    make_float2(acc[mf][nf][0] + b0, acc[mf][nf][1] + b1);
                *(float2*)&out[(size_t)(row + 8) * N + col] =
                    make_float2(acc[mf][nf][2] + b0, acc[mf][nf][3] + b1);
            }
        }
    }
}

// ---------------------------------------------------------------------------
__global__ void conv_x(const float* __restrict__ src) {
    int i = blockIdx.x * 256 + threadIdx.x;
    if (i < M_ * C_) g_xh[i] = __float2half(src[i]);
}
// transpose: src [K][N] fp32 -> dst [N][K] fp16 (hi only, or hi+lo)
__global__ void conv_split_t(const float* __restrict__ src, int mode, int K, int N) {
    __shared__ float s[32][33];
    __half* hi = (mode == 0) ? g_wqkvTh : g_woutThi;
    __half* lo = (mode == 0) ? nullptr : g_woutTlo;
    int n0 = blockIdx.x * 32, k0 = blockIdx.y * 32;
    int tx = threadIdx.x, ty = threadIdx.y;
#pragma unroll
    for (int yy = 0; yy < 32; yy += 8)
        s[ty + yy][tx] = src[(size_t)(k0 + ty + yy) * N + n0 + tx];
    __syncthreads();
#pragma unroll
    for (int yy = 0; yy < 32; yy += 8) {
        float v = s[tx][ty + yy];
        __half h = __float2half(v);
        size_t o = (size_t)(n0 + ty + yy) * K + k0 + tx;
        hi[o] = h;
        if (lo) lo[o] = __float2half(v - __half2float(h));
    }
}

// ---------------------------------------------------------------------------
// fp16 flash attention: S 1-term, PV 1-term, MUFU exp.
// Block 256 thr (8 warps), q-tile 128 rows, k-tiles of 64, double-buffered.
// smem: stage0 @0 (16K: kh|vh), stage1 @16K, Q @32K (16K) -> 48K.
// Heavy q-tiles scheduled first.
// ---------------------------------------------------------------------------
#define FLS_KH 0
#define FLS_VH 8192
#define FLS_STAGE 16384
#define FLS_QH 32768
#define FL_SMEM 49152

__device__ __forceinline__ void fl_load_tile(uint32_t dst, size_t gbase, int kt, int tid) {
    const __half* kh = g_kh + gbase + (size_t)kt * 64 * 64;
    const __half* vh = g_vh + gbase + (size_t)kt * 64 * 64;
#pragma unroll
    for (int i = tid; i < 512; i += 256) {
        int r = i >> 3, g = i & 7;
        uint32_t sw = sw128((uint32_t)(r * 128 + g * 16));
        size_t go = (size_t)r * 64 + g * 8;
        CP16(dst + FLS_KH + sw, kh + go);
        CP16(dst + FLS_VH + sw, vh + go);
    }
}

__global__ __launch_bounds__(256, 2) void hmma_flash() {
    extern __shared__ char smem[];
    const uint32_t sbase = smem_u32_of(smem);
    const int tid = threadIdx.x, w = tid >> 5, lane = tid & 31;
    const int qt = gridDim.x - 1 - blockIdx.x;   // heavy tiles first
    const int bh = blockIdx.y;
    const int nkt = 2 * (qt + 1);
    const size_t gbase = (size_t)bh * T_ * 64;
    const int lrow = lane & 15, lkb = (lane >> 4) << 4;

    {
        const __half* qh = g_qh + gbase + (size_t)qt * 128 * 64;
#pragma unroll
        for (int i = tid; i < 1024; i += 256) {
            int r = i >> 3, g = i & 7;
            uint32_t sw = sw128((uint32_t)(r * 128 + g * 16));
            size_t go = (size_t)r * 64 + g * 8;
            CP16(sbase + FLS_QH + sw, qh + go);
        }
        CP_COMMIT();
    }
    fl_load_tile(sbase, gbase, 0, tid);
    CP_COMMIT();
    CP_WAIT1();
    __syncthreads();

    uint32_t qf[4][4];
#pragma unroll
    for (int ks = 0; ks < 4; ks++) {
        uint32_t sw = sw128((uint32_t)((w * 16 + lrow) * 128 + ks * 32 + lkb));
        ldsm4(qf[ks], sbase + FLS_QH + sw);
    }

    float o[8][4];
#pragma unroll
    for (int j = 0; j < 8; j++)
#pragma unroll
        for (int k = 0; k < 4; k++) o[j][k] = 0.0f;
    float m1 = -1e30f, m2 = -1e30f, l1 = 0.0f, l2 = 0.0f;

    for (int kt = 0; kt < nkt; kt++) {
        const uint32_t buf = sbase + (uint32_t)(kt & 1) * FLS_STAGE;
        if (kt + 1 < nkt) {
            fl_load_tile(sbase + (uint32_t)((kt + 1) & 1) * FLS_STAGE, gbase, kt + 1, tid);
            CP_COMMIT();
            CP_WAIT1();
        } else {
            CP_WAIT0();
        }
        __syncthreads();

        // ---- S = (Q/8) K^T : 1-term fp16
        float s[8][4];
#pragma unroll
        for (int j = 0; j < 8; j++)
#pragma unroll
            for (int k = 0; k < 4; k++) s[j][k] = 0.0f;
#pragma unroll
        for (int kn = 0; kn < 4; kn++) {
#pragma unroll
            for (int ks = 0; ks < 4; ks++) {
                uint32_t sw = sw128((uint32_t)((kn * 16 + lrow) * 128 + ks * 32 + lkb));
                uint32_t kh4[4];
                ldsm4(kh4, buf + FLS_KH + sw);
                mma16816(s[kn * 2],     qf[ks], kh4[0], kh4[2]);
                mma16816(s[kn * 2 + 1], qf[ks], kh4[1], kh4[3]);
            }
        }

        const int gr1 = qt * 128 + w * 16 + (lane >> 2);
        if (kt * 64 + 63 > qt * 128 + w * 16) {
#pragma unroll
            for (int j = 0; j < 8; j++) {
                int c = kt * 64 + j * 8 + (lane & 3) * 2;
                if (c     > gr1)     s[j][0] = -1e30f;
                if (c + 1 > gr1)     s[j][1] = -1e30f;
                if (c     > gr1 + 8) s[j][2] = -1e30f;
                if (c + 1 > gr1 + 8) s[j][3] = -1e30f;
            }
        }

        float mx1 = -1e30f, mx2 = -1e30f;
#pragma unroll
        for (int j = 0; j < 8; j++) {
            mx1 = fmaxf(mx1, fmaxf(s[j][0], s[j][1]));
            mx2 = fmaxf(mx2, fmaxf(s[j][2], s[j][3]));
        }
        mx1 = fmaxf(mx1, __shfl_xor_sync(0xffffffffu, mx1, 1));
        mx1 = fmaxf(mx1, __shfl_xor_sync(0xffffffffu, mx1, 2));
        mx2 = fmaxf(mx2, __shfl_xor_sync(0xffffffffu, mx2, 1));
        mx2 = fmaxf(mx2, __shfl_xor_sync(0xffffffffu, mx2, 2));
        float nm1 = fmaxf(m1, mx1), nm2 = fmaxf(m2, mx2);
        float a1 = __expf(m1 - nm1), a2 = __expf(m2 - nm2);
        m1 = nm1; m2 = nm2;
        float rs1 = 0.0f, rs2 = 0.0f;
#pragma unroll
        for (int j = 0; j < 8; j++) {
            s[j][0] = __expf(s[j][0] - nm1);
            s[j][1] = __expf(s[j][1] - nm1);
            s[j][2] = __expf(s[j][2] - nm2);
            s[j][3] = __expf(s[j][3] - nm2);
            rs1 += s[j][0] + s[j][1];
            rs2 += s[j][2] + s[j][3];
        }
        rs1 += __shfl_xor_sync(0xffffffffu, rs1, 1);
        rs1 += __shfl_xor_sync(0xffffffffu, rs1, 2);
        rs2 += __shfl_xor_sync(0xffffffffu, rs2, 1);
        rs2 += __shfl_xor_sync(0xffffffffu, rs2, 2);
        l1 = l1 * a1 + rs1;
        l2 = l2 * a2 + rs2;
#pragma unroll
        for (int j = 0; j < 8; j++) {
            o[j][0] *= a1; o[j][1] *= a1;
            o[j][2] *= a2; o[j][3] *= a2;
        }

        // ---- O += P V : single-term fp16
        const int lg = lane >> 3, lr8 = lane & 7;
#pragma unroll
        for (int kn = 0; kn < 4; kn++) {
            uint32_t ph[4];
            ph[0] = pack_h2(s[2 * kn][0],     s[2 * kn][1]);
            ph[1] = pack_h2(s[2 * kn][2],     s[2 * kn][3]);
            ph[2] = pack_h2(s[2 * kn + 1][0], s[2 * kn + 1][1]);
            ph[3] = pack_h2(s[2 * kn + 1][2], s[2 * kn + 1][3]);
#pragma unroll
            for (int nd = 0; nd < 4; nd++) {
                int key = kn * 16 + lr8 + (lg >> 1) * 8;
                int dim = nd * 16 + (lg & 1) * 8;
                uint32_t sw = sw128((uint32_t)(key * 128 + dim * 2));
                uint32_t vh4[4];
                ldsm4t(vh4, buf + FLS_VH + sw);
                mma16816(o[nd * 2],     ph, vh4[0], vh4[2]);
                mma16816(o[nd * 2 + 1], ph, vh4[1], vh4[3]);
            }
        }
        __syncthreads();
    }

    const int b = bh >> 4, hh = bh & 15;
    const int t1 = qt * 128 + w * 16 + (lane >> 2);
    const float inv1 = 1.0f / l1, inv2 = 1.0f / l2;
#pragma unroll
    for (int j = 0; j < 8; j++) {
        int d = j * 8 + (lane & 3) * 2;
        size_t i1 = ((size_t)(b * T_ + t1)) * C_ + hh * 64 + d;
        size_t i2 = i1 + (size_t)8 * C_;
        *(uint32_t*)&g_attnh[i1] = pack_h2(o[j][0] * inv1, o[j][1] * inv1);
        *(uint32_t*)&g_attnh[i2] = pack_h2(o[j][2] * inv2, o[j][3] * inv2);
    }
}

// ---------------------------------------------------------------------------
extern "C" void kernel_launch(void* const* d_in, const int* in_sizes, int n_in,
                              void* d_out, int out_size) {
    const float* x    = (const float*)d_in[0];
    const float* Wqkv = (const float*)d_in[1];
    const float* Wout = (const float*)d_in[2];
    const float* bout = (const float*)d_in[3];
    float* out = (float*)d_out;

    conv_x<<<(M_ * C_ + 255) / 256, 256>>>(x);
    conv_split_t<<<dim3(NQKV_ / 32, C_ / 32), dim3(32, 8)>>>(Wqkv, 0, C_, NQKV_);
    conv_split_t<<<dim3(C_ / 32, C_ / 32), dim3(32, 8)>>>(Wout, 1, C_, C_);

    cudaFuncSetAttribute(hmma_gemm, cudaFuncAttributeMaxDynamicSharedMemorySize, GEMM_SMEM);
    hmma_gemm<<<dim3(NQKV_ / 128, M_ / 128), 256, GEMM_SMEM>>>(0, nullptr, nullptr, NQKV_);

    cudaFuncSetAttribute(hmma_flash, cudaFuncAttributeMaxDynamicSharedMemorySize, FL_SMEM);
    hmma_flash<<<dim3(T_ / 128, B_ * H_), 256, FL_SMEM>>>();

    hmma_gemm<<<dim3(C_ / 128, M_ / 128), 256, GEMM_SMEM>>>(1, out, bout, C_);
}

// round 10
// speedup vs baseline: 6.0547x; 1.0352x over previous
#include <cuda_runtime.h>
#include <cuda_fp16.h>
#include <cstdint>

#define B_  2
#define T_  2048
#define C_  1024
#define H_  16
#define M_  (B_*T_)      // 4096
#define NQKV_ (3*C_)     // 3072

// ---------------- device scratch (no allocation allowed) -------------------
__device__ __half g_xh[M_*C_];                       // x as single fp16
__device__ __half g_wqkvTh[NQKV_*C_];                // Wqkv^T single fp16
__device__ __half g_woutThi[C_*C_], g_woutTlo[C_*C_];
__device__ __half g_attnh[M_*C_];                    // attn out single fp16
// [b,h,t,d]: q (pre-scaled 1/8), k, v — all single fp16
__device__ __half g_qh[M_*C_], g_kh[M_*C_], g_vh[M_*C_];

// ---------------- helpers ----------------------------------------------------
__device__ __forceinline__ uint32_t smem_u32_of(const void* p) {
    uint32_t a;
    asm("{ .reg .u64 t; cvta.to.shared.u64 t, %1; cvt.u32.u64 %0, t; }" : "=r"(a) : "l"(p));
    return a;
}
__device__ __forceinline__ void ldsm4(uint32_t* r, uint32_t addr) {
    asm volatile("ldmatrix.sync.aligned.m8n8.x4.shared.b16 {%0,%1,%2,%3}, [%4];"
                 : "=r"(r[0]), "=r"(r[1]), "=r"(r[2]), "=r"(r[3]) : "r"(addr));
}
__device__ __forceinline__ void ldsm4t(uint32_t* r, uint32_t addr) {
    asm volatile("ldmatrix.sync.aligned.m8n8.x4.trans.shared.b16 {%0,%1,%2,%3}, [%4];"
                 : "=r"(r[0]), "=r"(r[1]), "=r"(r[2]), "=r"(r[3]) : "r"(addr));
}
__device__ __forceinline__ void mma16816(float* c, const uint32_t* a,
                                         uint32_t b0, uint32_t b1) {
    asm volatile(
        "mma.sync.aligned.m16n8k16.row.col.f32.f16.f16.f32 "
        "{%0,%1,%2,%3}, {%4,%5,%6,%7}, {%8,%9}, {%0,%1,%2,%3};"
        : "+f"(c[0]), "+f"(c[1]), "+f"(c[2]), "+f"(c[3])
        : "r"(a[0]), "r"(a[1]), "r"(a[2]), "r"(a[3]), "r"(b0), "r"(b1));
}
#define CP16(dst, src) \
    asm volatile("cp.async.cg.shared.global [%0], [%1], 16;" :: "r"(dst), "l"(src) : "memory")
#define CP_COMMIT() asm volatile("cp.async.commit_group;" ::: "memory")
#define CP_WAIT1()  asm volatile("cp.async.wait_group 1;" ::: "memory")
#define CP_WAIT0()  asm volatile("cp.async.wait_group 0;" ::: "memory")

__device__ __forceinline__ uint32_t sw128(uint32_t off) {
    return off ^ ((off >> 3) & 0x70);
}
__device__ __forceinline__ uint32_t pack_h2(float v0, float v1) {
    __half2 hp = __floats2half2_rn(v0, v1);
    return *(uint32_t*)&hp;
}

// ---------------------------------------------------------------------------
// fp16 HMMA GEMM: D = A_fp16 * (B_hi [+ B_lo]).
// mode 0 (qkv): 1-term.  mode 1 (proj): 2-term.
// CTA 128x128, 8 warps (4x2), warp tile 32x64, K-chunk 64 (SW128, 128B rows).
// smem/stage: A 16K | B_hi 16K | B_lo 16K = 48K; 2 stages = 96K; 2 CTA/SM.
// ---------------------------------------------------------------------------
#define GS_A    0
#define GS_B_HI 16384
#define GS_B_LO 32768
#define GS_STAGE 49152
#define GEMM_SMEM 98304
#define NCHUNK 16

__device__ __forceinline__ void gemm_load_stage(
    uint32_t dst, int ch, int bm, int bn, int tid, bool loadBlo,
    const __half* Ah, const __half* Bhi, const __half* Blo) {
    const int k0 = ch * 64;
#pragma unroll
    for (int i = tid; i < 1024; i += 256) {
        int r = i >> 3, g = i & 7;
        uint32_t sw = sw128((uint32_t)(r * 128 + g * 16));
        size_t ga = (size_t)(bm + r) * C_ + k0 + g * 8;
        CP16(dst + GS_A + sw, Ah + ga);
        size_t gb = (size_t)(bn + r) * C_ + k0 + g * 8;
        CP16(dst + GS_B_HI + sw, Bhi + gb);
        if (loadBlo) CP16(dst + GS_B_LO + sw, Blo + gb);
    }
}

__global__ __launch_bounds__(256, 2) void hmma_gemm(int mode, float* __restrict__ out,
                                                    const float* __restrict__ bias, int N) {
    extern __shared__ char smem[];
    const uint32_t sbase = smem_u32_of(smem);
    const int tid = threadIdx.x, wid = tid >> 5, lane = tid & 31;
    const int bm = blockIdx.y * 128, bn = blockIdx.x * 128;
    const int wm = wid & 3, wn = wid >> 2;

    const __half* Ah  = (mode == 0) ? g_xh : g_attnh;
    const __half* Bhi = (mode == 0) ? g_wqkvTh : g_woutThi;
    const __half* Blo = (mode == 0) ? g_wqkvTh : g_woutTlo;  // unused in mode 0
    const bool twoterm = (mode == 1);

    float acc[2][8][4];
#pragma unroll
    for (int i = 0; i < 2; i++)
#pragma unroll
        for (int j = 0; j < 8; j++)
#pragma unroll
            for (int k = 0; k < 4; k++) acc[i][j][k] = 0.0f;

    const int lrow = lane & 15;
    const int lkb  = (lane >> 4) << 4;

    gemm_load_stage(sbase, 0, bm, bn, tid, twoterm, Ah, Bhi, Blo);
    CP_COMMIT();
    gemm_load_stage(sbase + GS_STAGE, 1, bm, bn, tid, twoterm, Ah, Bhi, Blo);
    CP_COMMIT();

    for (int ch = 0; ch < NCHUNK; ch++) {
        if (ch < NCHUNK - 1) { CP_WAIT1(); } else { CP_WAIT0(); }
        __syncthreads();
        const uint32_t buf = sbase + (uint32_t)(ch & 1) * GS_STAGE;

#pragma unroll
        for (int ks = 0; ks < 4; ks++) {
            uint32_t ah[2][4];
#pragma unroll
            for (int mf = 0; mf < 2; mf++) {
                uint32_t sw = sw128((uint32_t)((wm * 32 + mf * 16 + lrow) * 128 + ks * 32 + lkb));
                ldsm4(ah[mf], buf + GS_A + sw);
            }
#pragma unroll
            for (int np = 0; np < 4; np++) {
                uint32_t sw = sw128((uint32_t)((wn * 64 + np * 16 + lrow) * 128 + ks * 32 + lkb));
                uint32_t bh[4];
                ldsm4(bh, buf + GS_B_HI + sw);
#pragma unroll
                for (int mf = 0; mf < 2; mf++) {
                    mma16816(acc[mf][np * 2],     ah[mf], bh[0], bh[2]);
                    mma16816(acc[mf][np * 2 + 1], ah[mf], bh[1], bh[3]);
                }
                if (twoterm) {
                    uint32_t bl[4];
                    ldsm4(bl, buf + GS_B_LO + sw);
#pragma unroll
                    for (int mf = 0; mf < 2; mf++) {
                        mma16816(acc[mf][np * 2],     ah[mf], bl[0], bl[2]);
                        mma16816(acc[mf][np * 2 + 1], ah[mf], bl[1], bl[3]);
                    }
                }
            }
        }
        __syncthreads();
        if (ch + 2 < NCHUNK) {
            gemm_load_stage(sbase + (uint32_t)(ch & 1) * GS_STAGE, ch + 2,
                            bm, bn, tid, twoterm, Ah, Bhi, Blo);
            CP_COMMIT();
        }
    }

    const int r0 = bm + wm * 32 + (lane >> 2);
    const int c0 = bn + wn * 64 + (lane & 3) * 2;
    if (mode == 0) {
#pragma unroll
        for (int nf = 0; nf < 8; nf++) {
            int col = c0 + nf * 8;
            int which = col >> 10;
            int hh = (col >> 6) & 15;
            int d = col & 63;
            float sc = (which == 0) ? 0.125f : 1.0f;
            __half* dst = (which == 0) ? g_qh : (which == 1) ? g_kh : g_vh;
#pragma unroll
            for (int mf = 0; mf < 2; mf++) {
                int row = r0 + mf * 16;
                int t = row & (T_ - 1), b = row >> 11;
                size_t i1 = ((size_t)((b << 4) + hh) * T_ + t) * 64 + d;
                *(uint32_t*)&dst[i1] = pack_h2(acc[mf][nf][0] * sc, acc[mf][nf][1] * sc);
                *(uint32_t*)&dst[i1 + 8 * 64] = pack_h2(acc[mf][nf][2] * sc, acc[mf][nf][3] * sc);
            }
        }
    } else {
#pragma unroll
        for (int mf = 0; mf < 2; mf++) {
#pragma unroll
            for (int nf = 0; nf < 8; nf++) {
                int row = r0 + mf * 16;
                int col = c0 + nf * 8;
                float b0 = bias[col], b1 = bias[col + 1];
                *(float2*)&out[(size_t)row * N + col] =
                    make_float2(acc[mf][nf][0] + b0, acc[mf][nf][1] + b1);
                *(float2*)&out[(size_t)(row + 8) * N + col] =
                    make_float2(acc[mf][nf][2] + b0, acc[mf][nf][3] + b1);
            }
        }
    }
}

// ---------------------------------------------------------------------------
__global__ void conv_x(const float* __restrict__ src) {
    int i = blockIdx.x * 256 + threadIdx.x;
    if (i < M_ * C_) g_xh[i] = __float2half(src[i]);
}
// transpose: src [K][N] fp32 -> dst [N][K] fp16 (hi only, or hi+lo)
__global__ void conv_split_t(const float* __restrict__ src, int mode, int K, int N) {
    __shared__ float s[32][33];
    __half* hi = (mode == 0) ? g_wqkvTh : g_woutThi;
    __half* lo = (mode == 0) ? nullptr : g_woutTlo;
    int n0 = blockIdx.x * 32, k0 = blockIdx.y * 32;
    int tx = threadIdx.x, ty = threadIdx.y;
#pragma unroll
    for (int yy = 0; yy < 32; yy += 8)
        s[ty + yy][tx] = src[(size_t)(k0 + ty + yy) * N + n0 + tx];
    __syncthreads();
#pragma unroll
    for (int yy = 0; yy < 32; yy += 8) {
        float v = s[tx][ty + yy];
        __half h = __float2half(v);
        size_t o = (size_t)(n0 + ty + yy) * K + k0 + tx;
        hi[o] = h;
        if (lo) lo[o] = __float2half(v - __half2float(h));
    }
}

// ---------------------------------------------------------------------------
// fp16 flash attention: S 1-term, PV 1-term, MUFU exp.  (unchanged)
// ---------------------------------------------------------------------------
#define FLS_KH 0
#define FLS_VH 8192
#define FLS_STAGE 16384
#define FLS_QH 32768
#define FL_SMEM 49152

__device__ __forceinline__ void fl_load_tile(uint32_t dst, size_t gbase, int kt, int tid) {
    const __half* kh = g_kh + gbase + (size_t)kt * 64 * 64;
    const __half* vh = g_vh + gbase + (size_t)kt * 64 * 64;
#pragma unroll
    for (int i = tid; i < 512; i += 256) {
        int r = i >> 3, g = i & 7;
        uint32_t sw = sw128((uint32_t)(r * 128 + g * 16));
        size_t go = (size_t)r * 64 + g * 8;
        CP16(dst + FLS_KH + sw, kh + go);
        CP16(dst + FLS_VH + sw, vh + go);
    }
}

__global__ __launch_bounds__(256, 2) void hmma_flash() {
    extern __shared__ char smem[];
    const uint32_t sbase = smem_u32_of(smem);
    const int tid = threadIdx.x, w = tid >> 5, lane = tid & 31;
    const int qt = gridDim.x - 1 - blockIdx.x;   // heavy tiles first
    const int bh = blockIdx.y;
    const int nkt = 2 * (qt + 1);
    const size_t gbase = (size_t)bh * T_ * 64;
    const int lrow = lane & 15, lkb = (lane >> 4) << 4;

    {
        const __half* qh = g_qh + gbase + (size_t)qt * 128 * 64;
#pragma unroll
        for (int i = tid; i < 1024; i += 256) {
            int r = i >> 3, g = i & 7;
            uint32_t sw = sw128((uint32_t)(r * 128 + g * 16));
            size_t go = (size_t)r * 64 + g * 8;
            CP16(sbase + FLS_QH + sw, qh + go);
        }
        CP_COMMIT();
    }
    fl_load_tile(sbase, gbase, 0, tid);
    CP_COMMIT();
    CP_WAIT1();
    __syncthreads();

    uint32_t qf[4][4];
#pragma unroll
    for (int ks = 0; ks < 4; ks++) {
        uint32_t sw = sw128((uint32_t)((w * 16 + lrow) * 128 + ks * 32 + lkb));
        ldsm4(qf[ks], sbase + FLS_QH + sw);
    }

    float o[8][4];
#pragma unroll
    for (int j = 0; j < 8; j++)
#pragma unroll
        for (int k = 0; k < 4; k++) o[j][k] = 0.0f;
    float m1 = -1e30f, m2 = -1e30f, l1 = 0.0f, l2 = 0.0f;

    for (int kt = 0; kt < nkt; kt++) {
        const uint32_t buf = sbase + (uint32_t)(kt & 1) * FLS_STAGE;
        if (kt + 1 < nkt) {
            fl_load_tile(sbase + (uint32_t)((kt + 1) & 1) * FLS_STAGE, gbase, kt + 1, tid);
            CP_COMMIT();
            CP_WAIT1();
        } else {
            CP_WAIT0();
        }
        __syncthreads();

        float s[8][4];
#pragma unroll
        for (int j = 0; j < 8; j++)
#pragma unroll
            for (int k = 0; k < 4; k++) s[j][k] = 0.0f;
#pragma unroll
        for (int kn = 0; kn < 4; kn++) {
#pragma unroll
            for (int ks = 0; ks < 4; ks++) {
                uint32_t sw = sw128((uint32_t)((kn * 16 + lrow) * 128 + ks * 32 + lkb));
                uint32_t kh4[4];
                ldsm4(kh4, buf + FLS_KH + sw);
                mma16816(s[kn * 2],     qf[ks], kh4[0], kh4[2]);
                mma16816(s[kn * 2 + 1], qf[ks], kh4[1], kh4[3]);
            }
        }

        const int gr1 = qt * 128 + w * 16 + (lane >> 2);
        if (kt * 64 + 63 > qt * 128 + w * 16) {
#pragma unroll
            for (int j = 0; j < 8; j++) {
                int c = kt * 64 + j * 8 + (lane & 3) * 2;
                if (c     > gr1)     s[j][0] = -1e30f;
                if (c + 1 > gr1)     s[j][1] = -1e30f;
                if (c     > gr1 + 8) s[j][2] = -1e30f;
                if (c + 1 > gr1 + 8) s[j][3] = -1e30f;
            }
        }

        float mx1 = -1e30f, mx2 = -1e30f;
#pragma unroll
        for (int j = 0; j < 8; j++) {
            mx1 = fmaxf(mx1, fmaxf(s[j][0], s[j][1]));
            mx2 = fmaxf(mx2, fmaxf(s[j][2], s[j][3]));
        }
        mx1 = fmaxf(mx1, __shfl_xor_sync(0xffffffffu, mx1, 1));
        mx1 = fmaxf(mx1, __shfl_xor_sync(0xffffffffu, mx1, 2));
        mx2 = fmaxf(mx2, __shfl_xor_sync(0xffffffffu, mx2, 1));
        mx2 = fmaxf(mx2, __shfl_xor_sync(0xffffffffu, mx2, 2));
        float nm1 = fmaxf(m1, mx1), nm2 = fmaxf(m2, mx2);
        float a1 = __expf(m1 - nm1), a2 = __expf(m2 - nm2);
        m1 = nm1; m2 = nm2;
        float rs1 = 0.0f, rs2 = 0.0f;
#pragma unroll
        for (int j = 0; j < 8; j++) {
            s[j][0] = __expf(s[j][0] - nm1);
            s[j][1] = __expf(s[j][1] - nm1);
            s[j][2] = __expf(s[j][2] - nm2);
            s[j][3] = __expf(s[j][3] - nm2);
            rs1 += s[j][0] + s[j][1];
            rs2 += s[j][2] + s[j][3];
        }
        rs1 += __shfl_xor_sync(0xffffffffu, rs1, 1);
        rs1 += __shfl_xor_sync(0xffffffffu, rs1, 2);
        rs2 += __shfl_xor_sync(0xffffffffu, rs2, 1);
        rs2 += __shfl_xor_sync(0xffffffffu, rs2, 2);
        l1 = l1 * a1 + rs1;
        l2 = l2 * a2 + rs2;
#pragma unroll
        for (int j = 0; j < 8; j++) {
            o[j][0] *= a1; o[j][1] *= a1;
            o[j][2] *= a2; o[j][3] *= a2;
        }

        const int lg = lane >> 3, lr8 = lane & 7;
#pragma unroll
        for (int kn = 0; kn < 4; kn++) {
            uint32_t ph[4];
            ph[0] = pack_h2(s[2 * kn][0],     s[2 * kn][1]);
            ph[1] = pack_h2(s[2 * kn][2],     s[2 * kn][3]);
            ph[2] = pack_h2(s[2 * kn + 1][0], s[2 * kn + 1][1]);
            ph[3] = pack_h2(s[2 * kn + 1][2], s[2 * kn + 1][3]);
#pragma unroll
            for (int nd = 0; nd < 4; nd++) {
                int key = kn * 16 + lr8 + (lg >> 1) * 8;
                int dim = nd * 16 + (lg & 1) * 8;
                uint32_t sw = sw128((uint32_t)(key * 128 + dim * 2));
                uint32_t vh4[4];
                ldsm4t(vh4, buf + FLS_VH + sw);
                mma16816(o[nd * 2],     ph, vh4[0], vh4[2]);
                mma16816(o[nd * 2 + 1], ph, vh4[1], vh4[3]);
            }
        }
        __syncthreads();
    }

    const int b = bh >> 4, hh = bh & 15;
    const int t1 = qt * 128 + w * 16 + (lane >> 2);
    const float inv1 = 1.0f / l1, inv2 = 1.0f / l2;
#pragma unroll
    for (int j = 0; j < 8; j++) {
        int d = j * 8 + (lane & 3) * 2;
        size_t i1 = ((size_t)(b * T_ + t1)) * C_ + hh * 64 + d;
        size_t i2 = i1 + (size_t)8 * C_;
        *(uint32_t*)&g_attnh[i1] = pack_h2(o[j][0] * inv1, o[j][1] * inv1);
        *(uint32_t*)&g_attnh[i2] = pack_h2(o[j][2] * inv2, o[j][3] * inv2);
    }
}

// ---------------------------------------------------------------------------
extern "C" void kernel_launch(void* const* d_in, const int* in_sizes, int n_in,
                              void* d_out, int out_size) {
    const float* x    = (const float*)d_in[0];
    const float* Wqkv = (const float*)d_in[1];
    const float* Wout = (const float*)d_in[2];
    const float* bout = (const float*)d_in[3];
    float* out = (float*)d_out;

    conv_x<<<(M_ * C_ + 255) / 256, 256>>>(x);
    conv_split_t<<<dim3(NQKV_ / 32, C_ / 32), dim3(32, 8)>>>(Wqkv, 0, C_, NQKV_);
    conv_split_t<<<dim3(C_ / 32, C_ / 32), dim3(32, 8)>>>(Wout, 1, C_, C_);

    cudaFuncSetAttribute(hmma_gemm, cudaFuncAttributeMaxDynamicSharedMemorySize, GEMM_SMEM);
    hmma_gemm<<<dim3(NQKV_ / 128, M_ / 128), 256, GEMM_SMEM>>>(0, nullptr, nullptr, NQKV_);

    cudaFuncSetAttribute(hmma_flash, cudaFuncAttributeMaxDynamicSharedMemorySize, FL_SMEM);
    hmma_flash<<<dim3(T_ / 128, B_ * H_), 256, FL_SMEM>>>();

    hmma_gemm<<<dim3(C_ / 128, M_ / 128), 256, GEMM_SMEM>>>(1, out, bout, C_);
}

// round 11
// speedup vs baseline: 7.8440x; 1.2955x over previous
#include <cuda_runtime.h>
#include <cuda_fp16.h>
#include <cstdint>

#define B_  2
#define T_  2048
#define C_  1024
#define H_  16
#define M_  (B_*T_)      // 4096
#define NQKV_ (3*C_)     // 3072

// ---------------- device scratch (no allocation allowed) -------------------
__device__ __half g_xh[M_*C_];                       // x fp16
__device__ __half g_wqkvTh[NQKV_*C_];                // Wqkv^T fp16
__device__ __half g_woutTh[C_*C_];                   // Wout^T fp16
__device__ __half g_attnh[M_*C_];                    // attn out fp16
__device__ __half g_qh[M_*C_], g_kh[M_*C_], g_vh[M_*C_];  // [b,h,t,d], q pre-scaled 1/8

// ---------------- helpers ----------------------------------------------------
__device__ __forceinline__ uint32_t smem_u32_of(const void* p) {
    uint32_t a;
    asm("{ .reg .u64 t; cvta.to.shared.u64 t, %1; cvt.u32.u64 %0, t; }" : "=r"(a) : "l"(p));
    return a;
}
__device__ __forceinline__ void ldsm4(uint32_t* r, uint32_t addr) {
    asm volatile("ldmatrix.sync.aligned.m8n8.x4.shared.b16 {%0,%1,%2,%3}, [%4];"
                 : "=r"(r[0]), "=r"(r[1]), "=r"(r[2]), "=r"(r[3]) : "r"(addr));
}
__device__ __forceinline__ void ldsm4t(uint32_t* r, uint32_t addr) {
    asm volatile("ldmatrix.sync.aligned.m8n8.x4.trans.shared.b16 {%0,%1,%2,%3}, [%4];"
                 : "=r"(r[0]), "=r"(r[1]), "=r"(r[2]), "=r"(r[3]) : "r"(addr));
}
__device__ __forceinline__ void mma16816(float* c, const uint32_t* a,
                                         uint32_t b0, uint32_t b1) {
    asm volatile(
        "mma.sync.aligned.m16n8k16.row.col.f32.f16.f16.f32 "
        "{%0,%1,%2,%3}, {%4,%5,%6,%7}, {%8,%9}, {%0,%1,%2,%3};"
        : "+f"(c[0]), "+f"(c[1]), "+f"(c[2]), "+f"(c[3])
        : "r"(a[0]), "r"(a[1]), "r"(a[2]), "r"(a[3]), "r"(b0), "r"(b1));
}
#define CP16(dst, src) \
    asm volatile("cp.async.cg.shared.global [%0], [%1], 16;" :: "r"(dst), "l"(src) : "memory")
#define CP_COMMIT() asm volatile("cp.async.commit_group;" ::: "memory")
#define CP_WAIT2()  asm volatile("cp.async.wait_group 2;" ::: "memory")
#define CP_WAIT1()  asm volatile("cp.async.wait_group 1;" ::: "memory")
#define CP_WAIT0()  asm volatile("cp.async.wait_group 0;" ::: "memory")

__device__ __forceinline__ uint32_t sw128(uint32_t off) {
    return off ^ ((off >> 3) & 0x70);
}
__device__ __forceinline__ uint32_t pack_h2(float v0, float v1) {
    __half2 hp = __floats2half2_rn(v0, v1);
    return *(uint32_t*)&hp;
}

// ---------------------------------------------------------------------------
// fp16 1-term HMMA GEMM: D = A_fp16 * B_fp16.
// CTA 128x128, 8 warps (4x2), warp tile 32x64, K-chunk 64 (SW128).
// smem/stage: A 16K | B 16K = 32K; 3 stages = 96K; 2 CTA/SM.
// mode 0: A=xh, B=WqkvT -> q/k/v fp16 [b,h,t,d] (q scaled 0.125)
// mode 1: A=attnh, B=WoutT -> out fp32 (+bias)
// ---------------------------------------------------------------------------
#define GS_A    0
#define GS_B    16384
#define GS_STAGE 32768
#define GEMM_SMEM 98304
#define NCHUNK 16

__device__ __forceinline__ void gemm_load_stage(
    uint32_t dst, int ch, int bm, int bn, int tid,
    const __half* Ah, const __half* Bh) {
    const int k0 = ch * 64;
#pragma unroll
    for (int i = tid; i < 1024; i += 256) {
        int r = i >> 3, g = i & 7;
        uint32_t sw = sw128((uint32_t)(r * 128 + g * 16));
        CP16(dst + GS_A + sw, Ah + (size_t)(bm + r) * C_ + k0 + g * 8);
        CP16(dst + GS_B + sw, Bh + (size_t)(bn + r) * C_ + k0 + g * 8);
    }
}

__global__ __launch_bounds__(256, 2) void hmma_gemm(int mode, float* __restrict__ out,
                                                    const float* __restrict__ bias, int N) {
    extern __shared__ char smem[];
    const uint32_t sbase = smem_u32_of(smem);
    const int tid = threadIdx.x, wid = tid >> 5, lane = tid & 31;
    const int bm = blockIdx.y * 128, bn = blockIdx.x * 128;
    const int wm = wid & 3, wn = wid >> 2;

    const __half* Ah = (mode == 0) ? g_xh : g_attnh;
    const __half* Bh = (mode == 0) ? g_wqkvTh : g_woutTh;

    float acc[2][8][4];
#pragma unroll
    for (int i = 0; i < 2; i++)
#pragma unroll
        for (int j = 0; j < 8; j++)
#pragma unroll
            for (int k = 0; k < 4; k++) acc[i][j][k] = 0.0f;

    const int lrow = lane & 15;
    const int lkb  = (lane >> 4) << 4;

    gemm_load_stage(sbase, 0, bm, bn, tid, Ah, Bh);
    CP_COMMIT();
    gemm_load_stage(sbase + GS_STAGE, 1, bm, bn, tid, Ah, Bh);
    CP_COMMIT();
    gemm_load_stage(sbase + 2 * GS_STAGE, 2, bm, bn, tid, Ah, Bh);
    CP_COMMIT();

    for (int ch = 0; ch < NCHUNK; ch++) {
        if (ch <= NCHUNK - 3)      { CP_WAIT2(); }
        else if (ch == NCHUNK - 2) { CP_WAIT1(); }
        else                       { CP_WAIT0(); }
        __syncthreads();
        const uint32_t buf = sbase + (uint32_t)(ch % 3) * GS_STAGE;

#pragma unroll
        for (int ks = 0; ks < 4; ks++) {
            uint32_t ah[2][4];
#pragma unroll
            for (int mf = 0; mf < 2; mf++) {
                uint32_t sw = sw128((uint32_t)((wm * 32 + mf * 16 + lrow) * 128 + ks * 32 + lkb));
                ldsm4(ah[mf], buf + GS_A + sw);
            }
#pragma unroll
            for (int np = 0; np < 4; np++) {
                uint32_t sw = sw128((uint32_t)((wn * 64 + np * 16 + lrow) * 128 + ks * 32 + lkb));
                uint32_t bh[4];
                ldsm4(bh, buf + GS_B + sw);
#pragma unroll
                for (int mf = 0; mf < 2; mf++) {
                    mma16816(acc[mf][np * 2],     ah[mf], bh[0], bh[2]);
                    mma16816(acc[mf][np * 2 + 1], ah[mf], bh[1], bh[3]);
                }
            }
        }
        __syncthreads();
        if (ch + 3 < NCHUNK) {
            gemm_load_stage(sbase + (uint32_t)(ch % 3) * GS_STAGE, ch + 3, bm, bn, tid, Ah, Bh);
            CP_COMMIT();
        }
    }

    const int r0 = bm + wm * 32 + (lane >> 2);
    const int c0 = bn + wn * 64 + (lane & 3) * 2;
    if (mode == 0) {
#pragma unroll
        for (int nf = 0; nf < 8; nf++) {
            int col = c0 + nf * 8;
            int which = col >> 10;
            int hh = (col >> 6) & 15;
            int d = col & 63;
            float sc = (which == 0) ? 0.125f : 1.0f;
            __half* dst = (which == 0) ? g_qh : (which == 1) ? g_kh : g_vh;
#pragma unroll
            for (int mf = 0; mf < 2; mf++) {
                int row = r0 + mf * 16;
                int t = row & (T_ - 1), b = row >> 11;
                size_t i1 = ((size_t)((b << 4) + hh) * T_ + t) * 64 + d;
                *(uint32_t*)&dst[i1] = pack_h2(acc[mf][nf][0] * sc, acc[mf][nf][1] * sc);
                *(uint32_t*)&dst[i1 + 8 * 64] = pack_h2(acc[mf][nf][2] * sc, acc[mf][nf][3] * sc);
            }
        }
    } else {
#pragma unroll
        for (int mf = 0; mf < 2; mf++) {
#pragma unroll
            for (int nf = 0; nf < 8; nf++) {
                int row = r0 + mf * 16;
                int col = c0 + nf * 8;
                float b0 = bias[col], b1 = bias[col + 1];
                *(float2*)&out[(size_t)row * N + col] =
                    make_float2(acc[mf][nf][0] + b0, acc[mf][nf][1] + b1);
                *(float2*)&out[(size_t)(row + 8) * N + col] =
                    make_float2(acc[mf][nf][2] + b0, acc[mf][nf][3] + b1);
            }
        }
    }
}

// ---------------------------------------------------------------------------
__global__ void conv_x(const float* __restrict__ src) {
    int i = blockIdx.x * 256 + threadIdx.x;
    if (i < M_ * C_) g_xh[i] = __float2half(src[i]);
}
// merged transpose: z=0 -> Wqkv [C,3C]->[3C,C]; z=1 -> Wout [C,C]->[C,C]
__global__ void conv_t2(const float* __restrict__ wqkv, const float* __restrict__ wout) {
    __shared__ float s[32][33];
    const int z = blockIdx.z;
    const int N = z ? C_ : NQKV_;
    if (blockIdx.x * 32 >= N) return;
    const float* src = z ? wout : wqkv;
    __half* dst = z ? g_woutTh : g_wqkvTh;
    int n0 = blockIdx.x * 32, k0 = blockIdx.y * 32;
    int tx = threadIdx.x, ty = threadIdx.y;
#pragma unroll
    for (int yy = 0; yy < 32; yy += 8)
        s[ty + yy][tx] = src[(size_t)(k0 + ty + yy) * N + n0 + tx];
    __syncthreads();
#pragma unroll
    for (int yy = 0; yy < 32; yy += 8)
        dst[(size_t)(n0 + ty + yy) * C_ + k0 + tx] = __float2half(s[tx][ty + yy]);
}

// ---------------------------------------------------------------------------
// fp16 flash attention: S 1-term, PV 1-term, MUFU exp. (unchanged)
// ---------------------------------------------------------------------------
#define FLS_KH 0
#define FLS_VH 8192
#define FLS_STAGE 16384
#define FLS_QH 32768
#define FL_SMEM 49152

__device__ __forceinline__ void fl_load_tile(uint32_t dst, size_t gbase, int kt, int tid) {
    const __half* kh = g_kh + gbase + (size_t)kt * 64 * 64;
    const __half* vh = g_vh + gbase + (size_t)kt * 64 * 64;
#pragma unroll
    for (int i = tid; i < 512; i += 256) {
        int r = i >> 3, g = i & 7;
        uint32_t sw = sw128((uint32_t)(r * 128 + g * 16));
        size_t go = (size_t)r * 64 + g * 8;
        CP16(dst + FLS_KH + sw, kh + go);
        CP16(dst + FLS_VH + sw, vh + go);
    }
}

__global__ __launch_bounds__(256, 2) void hmma_flash() {
    extern __shared__ char smem[];
    const uint32_t sbase = smem_u32_of(smem);
    const int tid = threadIdx.x, w = tid >> 5, lane = tid & 31;
    const int qt = gridDim.x - 1 - blockIdx.x;   // heavy tiles first
    const int bh = blockIdx.y;
    const int nkt = 2 * (qt + 1);
    const size_t gbase = (size_t)bh * T_ * 64;
    const int lrow = lane & 15, lkb = (lane >> 4) << 4;

    {
        const __half* qh = g_qh + gbase + (size_t)qt * 128 * 64;
#pragma unroll
        for (int i = tid; i < 1024; i += 256) {
            int r = i >> 3, g = i & 7;
            uint32_t sw = sw128((uint32_t)(r * 128 + g * 16));
            CP16(sbase + FLS_QH + sw, qh + (size_t)r * 64 + g * 8);
        }
        CP_COMMIT();
    }
    fl_load_tile(sbase, gbase, 0, tid);
    CP_COMMIT();
    CP_WAIT1();
    __syncthreads();

    uint32_t qf[4][4];
#pragma unroll
    for (int ks = 0; ks < 4; ks++) {
        uint32_t sw = sw128((uint32_t)((w * 16 + lrow) * 128 + ks * 32 + lkb));
        ldsm4(qf[ks], sbase + FLS_QH + sw);
    }

    float o[8][4];
#pragma unroll
    for (int j = 0; j < 8; j++)
#pragma unroll
        for (int k = 0; k < 4; k++) o[j][k] = 0.0f;
    float m1 = -1e30f, m2 = -1e30f, l1 = 0.0f, l2 = 0.0f;

    for (int kt = 0; kt < nkt; kt++) {
        const uint32_t buf = sbase + (uint32_t)(kt & 1) * FLS_STAGE;
        if (kt + 1 < nkt) {
            fl_load_tile(sbase + (uint32_t)((kt + 1) & 1) * FLS_STAGE, gbase, kt + 1, tid);
            CP_COMMIT();
            CP_WAIT1();
        } else {
            CP_WAIT0();
        }
        __syncthreads();

        float s[8][4];
#pragma unroll
        for (int j = 0; j < 8; j++)
#pragma unroll
            for (int k = 0; k < 4; k++) s[j][k] = 0.0f;
#pragma unroll
        for (int kn = 0; kn < 4; kn++) {
#pragma unroll
            for (int ks = 0; ks < 4; ks++) {
                uint32_t sw = sw128((uint32_t)((kn * 16 + lrow) * 128 + ks * 32 + lkb));
                uint32_t kh4[4];
                ldsm4(kh4, buf + FLS_KH + sw);
                mma16816(s[kn * 2],     qf[ks], kh4[0], kh4[2]);
                mma16816(s[kn * 2 + 1], qf[ks], kh4[1], kh4[3]);
            }
        }

        const int gr1 = qt * 128 + w * 16 + (lane >> 2);
        if (kt * 64 + 63 > qt * 128 + w * 16) {
#pragma unroll
            for (int j = 0; j < 8; j++) {
                int c = kt * 64 + j * 8 + (lane & 3) * 2;
                if (c     > gr1)     s[j][0] = -1e30f;
                if (c + 1 > gr1)     s[j][1] = -1e30f;
                if (c     > gr1 + 8) s[j][2] = -1e30f;
                if (c + 1 > gr1 + 8) s[j][3] = -1e30f;
            }
        }

        float mx1 = -1e30f, mx2 = -1e30f;
#pragma unroll
        for (int j = 0; j < 8; j++) {
            mx1 = fmaxf(mx1, fmaxf(s[j][0], s[j][1]));
            mx2 = fmaxf(mx2, fmaxf(s[j][2], s[j][3]));
        }
        mx1 = fmaxf(mx1, __shfl_xor_sync(0xffffffffu, mx1, 1));
        mx1 = fmaxf(mx1, __shfl_xor_sync(0xffffffffu, mx1, 2));
        mx2 = fmaxf(mx2, __shfl_xor_sync(0xffffffffu, mx2, 1));
        mx2 = fmaxf(mx2, __shfl_xor_sync(0xffffffffu, mx2, 2));
        float nm1 = fmaxf(m1, mx1), nm2 = fmaxf(m2, mx2);
        float a1 = __expf(m1 - nm1), a2 = __expf(m2 - nm2);
        m1 = nm1; m2 = nm2;
        float rs1 = 0.0f, rs2 = 0.0f;
#pragma unroll
        for (int j = 0; j < 8; j++) {
            s[j][0] = __expf(s[j][0] - nm1);
            s[j][1] = __expf(s[j][1] - nm1);
            s[j][2] = __expf(s[j][2] - nm2);
            s[j][3] = __expf(s[j][3] - nm2);
            rs1 += s[j][0] + s[j][1];
            rs2 += s[j][2] + s[j][3];
        }
        rs1 += __shfl_xor_sync(0xffffffffu, rs1, 1);
        rs1 += __shfl_xor_sync(0xffffffffu, rs1, 2);
        rs2 += __shfl_xor_sync(0xffffffffu, rs2, 1);
        rs2 += __shfl_xor_sync(0xffffffffu, rs2, 2);
        l1 = l1 * a1 + rs1;
        l2 = l2 * a2 + rs2;
#pragma unroll
        for (int j = 0; j < 8; j++) {
            o[j][0] *= a1; o[j][1] *= a1;
            o[j][2] *= a2; o[j][3] *= a2;
        }

        const int lg = lane >> 3, lr8 = lane & 7;
#pragma unroll
        for (int kn = 0; kn < 4; kn++) {
            uint32_t ph[4];
            ph[0] = pack_h2(s[2 * kn][0],     s[2 * kn][1]);
            ph[1] = pack_h2(s[2 * kn][2],     s[2 * kn][3]);
            ph[2] = pack_h2(s[2 * kn + 1][0], s[2 * kn + 1][1]);
            ph[3] = pack_h2(s[2 * kn + 1][2], s[2 * kn + 1][3]);
#pragma unroll
            for (int nd = 0; nd < 4; nd++) {
                int key = kn * 16 + lr8 + (lg >> 1) * 8;
                int dim = nd * 16 + (lg & 1) * 8;
                uint32_t sw = sw128((uint32_t)(key * 128 + dim * 2));
                uint32_t vh4[4];
                ldsm4t(vh4, buf + FLS_VH + sw);
                mma16816(o[nd * 2],     ph, vh4[0], vh4[2]);
                mma16816(o[nd * 2 + 1], ph, vh4[1], vh4[3]);
            }
        }
        __syncthreads();
    }

    const int b = bh >> 4, hh = bh & 15;
    const int t1 = qt * 128 + w * 16 + (lane >> 2);
    const float inv1 = 1.0f / l1, inv2 = 1.0f / l2;
#pragma unroll
    for (int j = 0; j < 8; j++) {
        int d = j * 8 + (lane & 3) * 2;
        size_t i1 = ((size_t)(b * T_ + t1)) * C_ + hh * 64 + d;
        size_t i2 = i1 + (size_t)8 * C_;
        *(uint32_t*)&g_attnh[i1] = pack_h2(o[j][0] * inv1, o[j][1] * inv1);
        *(uint32_t*)&g_attnh[i2] = pack_h2(o[j][2] * inv2, o[j][3] * inv2);
    }
}

// ---------------------------------------------------------------------------
extern "C" void kernel_launch(void* const* d_in, const int* in_sizes, int n_in,
                              void* d_out, int out_size) {
    const float* x    = (const float*)d_in[0];
    const float* Wqkv = (const float*)d_in[1];
    const float* Wout = (const float*)d_in[2];
    const float* bout = (const float*)d_in[3];
    float* out = (float*)d_out;

    conv_x<<<(M_ * C_ + 255) / 256, 256>>>(x);
    conv_t2<<<dim3(NQKV_ / 32, C_ / 32, 2), dim3(32, 8)>>>(Wqkv, Wout);

    cudaFuncSetAttribute(hmma_gemm, cudaFuncAttributeMaxDynamicSharedMemorySize, GEMM_SMEM);
    hmma_gemm<<<dim3(NQKV_ / 128, M_ / 128), 256, GEMM_SMEM>>>(0, nullptr, nullptr, NQKV_);

    cudaFuncSetAttribute(hmma_flash, cudaFuncAttributeMaxDynamicSharedMemorySize, FL_SMEM);
    hmma_flash<<<dim3(T_ / 128, B_ * H_), 256, FL_SMEM>>>();

    hmma_gemm<<<dim3(C_ / 128, M_ / 128), 256, GEMM_SMEM>>>(1, out, bout, C_);
}

// round 12
// speedup vs baseline: 8.4758x; 1.0805x over previous
#include <cuda_runtime.h>
#include <cuda_fp16.h>
#include <cstdint>

#define B_  2
#define T_  2048
#define C_  1024
#define H_  16
#define M_  (B_*T_)      // 4096
#define NQKV_ (3*C_)     // 3072

// ---------------- device scratch (no allocation allowed) -------------------
__device__ __half g_xh[M_*C_];                       // x fp16
__device__ __half g_wqkvTh[NQKV_*C_];                // Wqkv^T fp16
__device__ __half g_woutTh[C_*C_];                   // Wout^T fp16
__device__ __half g_attnh[M_*C_];                    // attn out fp16
__device__ __half g_qh[M_*C_], g_kh[M_*C_], g_vh[M_*C_];  // [b,h,t,d], q pre-scaled 1/8

// ---------------- helpers ----------------------------------------------------
__device__ __forceinline__ uint32_t smem_u32_of(const void* p) {
    uint32_t a;
    asm("{ .reg .u64 t; cvta.to.shared.u64 t, %1; cvt.u32.u64 %0, t; }" : "=r"(a) : "l"(p));
    return a;
}
__device__ __forceinline__ void ldsm4(uint32_t* r, uint32_t addr) {
    asm volatile("ldmatrix.sync.aligned.m8n8.x4.shared.b16 {%0,%1,%2,%3}, [%4];"
                 : "=r"(r[0]), "=r"(r[1]), "=r"(r[2]), "=r"(r[3]) : "r"(addr));
}
__device__ __forceinline__ void ldsm4t(uint32_t* r, uint32_t addr) {
    asm volatile("ldmatrix.sync.aligned.m8n8.x4.trans.shared.b16 {%0,%1,%2,%3}, [%4];"
                 : "=r"(r[0]), "=r"(r[1]), "=r"(r[2]), "=r"(r[3]) : "r"(addr));
}
__device__ __forceinline__ void mma16816(float* c, const uint32_t* a,
                                         uint32_t b0, uint32_t b1) {
    asm volatile(
        "mma.sync.aligned.m16n8k16.row.col.f32.f16.f16.f32 "
        "{%0,%1,%2,%3}, {%4,%5,%6,%7}, {%8,%9}, {%0,%1,%2,%3};"
        : "+f"(c[0]), "+f"(c[1]), "+f"(c[2]), "+f"(c[3])
        : "r"(a[0]), "r"(a[1]), "r"(a[2]), "r"(a[3]), "r"(b0), "r"(b1));
}
#define CP16(dst, src) \
    asm volatile("cp.async.cg.shared.global [%0], [%1], 16;" :: "r"(dst), "l"(src) : "memory")
#define CP_COMMIT() asm volatile("cp.async.commit_group;" ::: "memory")
#define CP_WAIT0()  asm volatile("cp.async.wait_group 0;" ::: "memory")

__device__ __forceinline__ uint32_t sw128(uint32_t off) {
    return off ^ ((off >> 3) & 0x70);
}
__device__ __forceinline__ uint32_t pack_h2(float v0, float v1) {
    __half2 hp = __floats2half2_rn(v0, v1);
    return *(uint32_t*)&hp;
}
__device__ __forceinline__ uint32_t ex2_h2(uint32_t x) {
    uint32_t r;
    asm("ex2.approx.f16x2 %0, %1;" : "=r"(r) : "r"(x));
    return r;
}

// ---------------------------------------------------------------------------
// fp16 1-term HMMA GEMM: D = A_fp16 * B_fp16.
// CTA 128x128, 8 warps (4x2), warp tile 32x64, K-chunk 64 (SW128), 2 stages,
// ONE __syncthreads per chunk (loads issued pre-compute, wait+sync at end).
// ---------------------------------------------------------------------------
#define GS_A    0
#define GS_B    16384
#define GS_STAGE 32768
#define GEMM_SMEM 65536
#define NCHUNK 16

__device__ __forceinline__ void gemm_load_stage(
    uint32_t dst, int ch, int bm, int bn, int tid,
    const __half* Ah, const __half* Bh) {
    const int k0 = ch * 64;
#pragma unroll
    for (int i = tid; i < 1024; i += 256) {
        int r = i >> 3, g = i & 7;
        uint32_t sw = sw128((uint32_t)(r * 128 + g * 16));
        CP16(dst + GS_A + sw, Ah + (size_t)(bm + r) * C_ + k0 + g * 8);
        CP16(dst + GS_B + sw, Bh + (size_t)(bn + r) * C_ + k0 + g * 8);
    }
}

__global__ __launch_bounds__(256, 2) void hmma_gemm(int mode, float* __restrict__ out,
                                                    const float* __restrict__ bias, int N) {
    extern __shared__ char smem[];
    const uint32_t sbase = smem_u32_of(smem);
    const int tid = threadIdx.x, wid = tid >> 5, lane = tid & 31;
    const int bm = blockIdx.y * 128, bn = blockIdx.x * 128;
    const int wm = wid & 3, wn = wid >> 2;

    const __half* Ah = (mode == 0) ? g_xh : g_attnh;
    const __half* Bh = (mode == 0) ? g_wqkvTh : g_woutTh;

    float acc[2][8][4];
#pragma unroll
    for (int i = 0; i < 2; i++)
#pragma unroll
        for (int j = 0; j < 8; j++)
#pragma unroll
            for (int k = 0; k < 4; k++) acc[i][j][k] = 0.0f;

    const int lrow = lane & 15;
    const int lkb  = (lane >> 4) << 4;

    gemm_load_stage(sbase, 0, bm, bn, tid, Ah, Bh);
    CP_COMMIT();
    CP_WAIT0();
    __syncthreads();

    for (int ch = 0; ch < NCHUNK; ch++) {
        // issue next chunk (its buffer drained as of last iteration's sync)
        if (ch + 1 < NCHUNK) {
            gemm_load_stage(sbase + (uint32_t)((ch + 1) & 1) * GS_STAGE, ch + 1,
                            bm, bn, tid, Ah, Bh);
            CP_COMMIT();
        }
        const uint32_t buf = sbase + (uint32_t)(ch & 1) * GS_STAGE;

#pragma unroll
        for (int ks = 0; ks < 4; ks++) {
            uint32_t ah[2][4];
#pragma unroll
            for (int mf = 0; mf < 2; mf++) {
                uint32_t sw = sw128((uint32_t)((wm * 32 + mf * 16 + lrow) * 128 + ks * 32 + lkb));
                ldsm4(ah[mf], buf + GS_A + sw);
            }
#pragma unroll
            for (int np = 0; np < 4; np++) {
                uint32_t sw = sw128((uint32_t)((wn * 64 + np * 16 + lrow) * 128 + ks * 32 + lkb));
                uint32_t bh[4];
                ldsm4(bh, buf + GS_B + sw);
#pragma unroll
                for (int mf = 0; mf < 2; mf++) {
                    mma16816(acc[mf][np * 2],     ah[mf], bh[0], bh[2]);
                    mma16816(acc[mf][np * 2 + 1], ah[mf], bh[1], bh[3]);
                }
            }
        }
        CP_WAIT0();
        __syncthreads();
    }

    const int r0 = bm + wm * 32 + (lane >> 2);
    const int c0 = bn + wn * 64 + (lane & 3) * 2;
    if (mode == 0) {
#pragma unroll
        for (int nf = 0; nf < 8; nf++) {
            int col = c0 + nf * 8;
            int which = col >> 10;
            int hh = (col >> 6) & 15;
            int d = col & 63;
            float sc = (which == 0) ? 0.125f : 1.0f;
            __half* dst = (which == 0) ? g_qh : (which == 1) ? g_kh : g_vh;
#pragma unroll
            for (int mf = 0; mf < 2; mf++) {
                int row = r0 + mf * 16;
                int t = row & (T_ - 1), b = row >> 11;
                size_t i1 = ((size_t)((b << 4) + hh) * T_ + t) * 64 + d;
                *(uint32_t*)&dst[i1] = pack_h2(acc[mf][nf][0] * sc, acc[mf][nf][1] * sc);
                *(uint32_t*)&dst[i1 + 8 * 64] = pack_h2(acc[mf][nf][2] * sc, acc[mf][nf][3] * sc);
            }
        }
    } else {
#pragma unroll
        for (int mf = 0; mf < 2; mf++) {
#pragma unroll
            for (int nf = 0; nf < 8; nf++) {
                int row = r0 + mf * 16;
                int col = c0 + nf * 8;
                float b0 = bias[col], b1 = bias[col + 1];
                *(float2*)&out[(size_t)row * N + col] =
                    make_float2(acc[mf][nf][0] + b0, acc[mf][nf][1] + b1);
                *(float2*)&out[(size_t)(row + 8) * N + col] =
                    make_float2(acc[mf][nf][2] + b0, acc[mf][nf][3] + b1);
            }
        }
    }
}

// ---------------------------------------------------------------------------
__global__ void conv_x(const float* __restrict__ src) {
    int i = blockIdx.x * 256 + threadIdx.x;
    if (i < M_ * C_) g_xh[i] = __float2half(src[i]);
}
__global__ void conv_t2(const float* __restrict__ wqkv, const float* __restrict__ wout) {
    __shared__ float s[32][33];
    const int z = blockIdx.z;
    const int N = z ? C_ : NQKV_;
    if (blockIdx.x * 32 >= N) return;
    const float* src = z ? wout : wqkv;
    __half* dst = z ? g_woutTh : g_wqkvTh;
    int n0 = blockIdx.x * 32, k0 = blockIdx.y * 32;
    int tx = threadIdx.x, ty = threadIdx.y;
#pragma unroll
    for (int yy = 0; yy < 32; yy += 8)
        s[ty + yy][tx] = src[(size_t)(k0 + ty + yy) * N + n0 + tx];
    __syncthreads();
#pragma unroll
    for (int yy = 0; yy < 32; yy += 8)
        dst[(size_t)(n0 + ty + yy) * C_ + k0 + tx] = __float2half(s[tx][ty + yy]);
}

// ---------------------------------------------------------------------------
// fp16 flash attention: S 1-term, PV 1-term, f16x2 ex2 softmax, MMA row-sums,
// one __syncthreads per key-tile.
// ---------------------------------------------------------------------------
#define FLS_KH 0
#define FLS_VH 8192
#define FLS_STAGE 16384
#define FLS_QH 32768
#define FL_SMEM 49152
#define L2E 1.4426950408889634f

__device__ __forceinline__ void fl_load_tile(uint32_t dst, size_t gbase, int kt, int tid) {
    const __half* kh = g_kh + gbase + (size_t)kt * 64 * 64;
    const __half* vh = g_vh + gbase + (size_t)kt * 64 * 64;
#pragma unroll
    for (int i = tid; i < 512; i += 256) {
        int r = i >> 3, g = i & 7;
        uint32_t sw = sw128((uint32_t)(r * 128 + g * 16));
        size_t go = (size_t)r * 64 + g * 8;
        CP16(dst + FLS_KH + sw, kh + go);
        CP16(dst + FLS_VH + sw, vh + go);
    }
}

__global__ __launch_bounds__(256, 2) void hmma_flash() {
    extern __shared__ char smem[];
    const uint32_t sbase = smem_u32_of(smem);
    const int tid = threadIdx.x, w = tid >> 5, lane = tid & 31;
    const int qt = gridDim.x - 1 - blockIdx.x;   // heavy tiles first
    const int bh = blockIdx.y;
    const int nkt = 2 * (qt + 1);
    const size_t gbase = (size_t)bh * T_ * 64;
    const int lrow = lane & 15, lkb = (lane >> 4) << 4;
    // ones-fragment for row-sum MMA: B col 0 = 1 (owned by lanes 0-3)
    const uint32_t ones = (lane < 4) ? 0x3C003C00u : 0u;

    {
        const __half* qh = g_qh + gbase + (size_t)qt * 128 * 64;
#pragma unroll
        for (int i = tid; i < 1024; i += 256) {
            int r = i >> 3, g = i & 7;
            uint32_t sw = sw128((uint32_t)(r * 128 + g * 16));
            CP16(sbase + FLS_QH + sw, qh + (size_t)r * 64 + g * 8);
        }
    }
    fl_load_tile(sbase, gbase, 0, tid);
    CP_COMMIT();
    CP_WAIT0();
    __syncthreads();

    uint32_t qf[4][4];
#pragma unroll
    for (int ks = 0; ks < 4; ks++) {
        uint32_t sw = sw128((uint32_t)((w * 16 + lrow) * 128 + ks * 32 + lkb));
        ldsm4(qf[ks], sbase + FLS_QH + sw);
    }

    float o[8][4];
#pragma unroll
    for (int j = 0; j < 8; j++)
#pragma unroll
        for (int k = 0; k < 4; k++) o[j][k] = 0.0f;
    float m1 = -1e30f, m2 = -1e30f, l1 = 0.0f, l2 = 0.0f;

    for (int kt = 0; kt < nkt; kt++) {
        // issue next tile (its buffer drained as of last iteration's sync)
        if (kt + 1 < nkt) {
            fl_load_tile(sbase + (uint32_t)((kt + 1) & 1) * FLS_STAGE, gbase, kt + 1, tid);
            CP_COMMIT();
        }
        const uint32_t buf = sbase + (uint32_t)(kt & 1) * FLS_STAGE;

        // ---- S = (Q/8) K^T : 1-term fp16
        float s[8][4];
#pragma unroll
        for (int j = 0; j < 8; j++)
#pragma unroll
            for (int k = 0; k < 4; k++) s[j][k] = 0.0f;
#pragma unroll
        for (int kn = 0; kn < 4; kn++) {
#pragma unroll
            for (int ks = 0; ks < 4; ks++) {
                uint32_t sw = sw128((uint32_t)((kn * 16 + lrow) * 128 + ks * 32 + lkb));
                uint32_t kh4[4];
                ldsm4(kh4, buf + FLS_KH + sw);
                mma16816(s[kn * 2],     qf[ks], kh4[0], kh4[2]);
                mma16816(s[kn * 2 + 1], qf[ks], kh4[1], kh4[3]);
            }
        }

        // ---- causal mask (diagonal region only)
        const int gr1 = qt * 128 + w * 16 + (lane >> 2);
        if (kt * 64 + 63 > qt * 128 + w * 16) {
#pragma unroll
            for (int j = 0; j < 8; j++) {
                int c = kt * 64 + j * 8 + (lane & 3) * 2;
                if (c     > gr1)     s[j][0] = -1e30f;
                if (c + 1 > gr1)     s[j][1] = -1e30f;
                if (c     > gr1 + 8) s[j][2] = -1e30f;
                if (c + 1 > gr1 + 8) s[j][3] = -1e30f;
            }
        }

        // ---- online max update
        float mx1 = -1e30f, mx2 = -1e30f;
#pragma unroll
        for (int j = 0; j < 8; j++) {
            mx1 = fmaxf(mx1, fmaxf(s[j][0], s[j][1]));
            mx2 = fmaxf(mx2, fmaxf(s[j][2], s[j][3]));
        }
        mx1 = fmaxf(mx1, __shfl_xor_sync(0xffffffffu, mx1, 1));
        mx1 = fmaxf(mx1, __shfl_xor_sync(0xffffffffu, mx1, 2));
        mx2 = fmaxf(mx2, __shfl_xor_sync(0xffffffffu, mx2, 1));
        mx2 = fmaxf(mx2, __shfl_xor_sync(0xffffffffu, mx2, 2));
        float nm1 = fmaxf(m1, mx1), nm2 = fmaxf(m2, mx2);
        float a1 = __expf(m1 - nm1), a2 = __expf(m2 - nm2);
        m1 = nm1; m2 = nm2;
        const float mlg1 = nm1 * L2E, mlg2 = nm2 * L2E;
#pragma unroll
        for (int j = 0; j < 8; j++) {
            o[j][0] *= a1; o[j][1] *= a1;
            o[j][2] *= a2; o[j][3] *= a2;
        }

        // ---- p = ex2.f16x2((s-m)*log2e); O += P V; row-sum via ones-MMA
        float osum[4] = {0.0f, 0.0f, 0.0f, 0.0f};
        const int lg = lane >> 3, lr8 = lane & 7;
#pragma unroll
        for (int kn = 0; kn < 4; kn++) {
            uint32_t ph[4];
            ph[0] = ex2_h2(pack_h2(fmaf(s[2 * kn][0], L2E, -mlg1),
                                   fmaf(s[2 * kn][1], L2E, -mlg1)));
            ph[1] = ex2_h2(pack_h2(fmaf(s[2 * kn][2], L2E, -mlg2),
                                   fmaf(s[2 * kn][3], L2E, -mlg2)));
            ph[2] = ex2_h2(pack_h2(fmaf(s[2 * kn + 1][0], L2E, -mlg1),
                                   fmaf(s[2 * kn + 1][1], L2E, -mlg1)));
            ph[3] = ex2_h2(pack_h2(fmaf(s[2 * kn + 1][2], L2E, -mlg2),
                                   fmaf(s[2 * kn + 1][3], L2E, -mlg2)));
            mma16816(osum, ph, ones, ones);   // row sums into col 0
#pragma unroll
            for (int nd = 0; nd < 4; nd++) {
                int key = kn * 16 + lr8 + (lg >> 1) * 8;
                int dim = nd * 16 + (lg & 1) * 8;
                uint32_t sw = sw128((uint32_t)(key * 128 + dim * 2));
                uint32_t vh4[4];
                ldsm4t(vh4, buf + FLS_VH + sw);
                mma16816(o[nd * 2],     ph, vh4[0], vh4[2]);
                mma16816(o[nd * 2 + 1], ph, vh4[1], vh4[3]);
            }
        }
        // valid on lanes with lane%4==0 (col 0 owners); broadcast at epilogue
        l1 = l1 * a1 + osum[0];
        l2 = l2 * a2 + osum[2];

        CP_WAIT0();
        __syncthreads();
    }

    // broadcast row sums from col-0 owner lane of each row group
    l1 = __shfl_sync(0xffffffffu, l1, lane & 28);
    l2 = __shfl_sync(0xffffffffu, l2, lane & 28);

    const int b = bh >> 4, hh = bh & 15;
    const int t1 = qt * 128 + w * 16 + (lane >> 2);
    const float inv1 = 1.0f / l1, inv2 = 1.0f / l2;
#pragma unroll
    for (int j = 0; j < 8; j++) {
        int d = j * 8 + (lane & 3) * 2;
        size_t i1 = ((size_t)(b * T_ + t1)) * C_ + hh * 64 + d;
        size_t i2 = i1 + (size_t)8 * C_;
        *(uint32_t*)&g_attnh[i1] = pack_h2(o[j][0] * inv1, o[j][1] * inv1);
        *(uint32_t*)&g_attnh[i2] = pack_h2(o[j][2] * inv2, o[j][3] * inv2);
    }
}

// ---------------------------------------------------------------------------
extern "C" void kernel_launch(void* const* d_in, const int* in_sizes, int n_in,
                              void* d_out, int out_size) {
    const float* x    = (const float*)d_in[0];
    const float* Wqkv = (const float*)d_in[1];
    const float* Wout = (const float*)d_in[2];
    const float* bout = (const float*)d_in[3];
    float* out = (float*)d_out;

    conv_x<<<(M_ * C_ + 255) / 256, 256>>>(x);
    conv_t2<<<dim3(NQKV_ / 32, C_ / 32, 2), dim3(32, 8)>>>(Wqkv, Wout);

    cudaFuncSetAttribute(hmma_gemm, cudaFuncAttributeMaxDynamicSharedMemorySize, GEMM_SMEM);
    hmma_gemm<<<dim3(NQKV_ / 128, M_ / 128), 256, GEMM_SMEM>>>(0, nullptr, nullptr, NQKV_);

    cudaFuncSetAttribute(hmma_flash, cudaFuncAttributeMaxDynamicSharedMemorySize, FL_SMEM);
    hmma_flash<<<dim3(T_ / 128, B_ * H_), 256, FL_SMEM>>>();

    hmma_gemm<<<dim3(C_ / 128, M_ / 128), 256, GEMM_SMEM>>>(1, out, bout, C_);
}